// round 13
// baseline (speedup 1.0000x reference)
#include <cuda_runtime.h>
#include <cuda_bf16.h>
#include <math.h>
#include <cstdint>

// Problem constants
#define SEQ   8192
#define HID   2048
#define NH    16
#define NKV   4
#define DH    128
#define TK    2048
#define SK    640
#define NQF   (TK + SK)        // 2688
#define NQT   (NQF / 128)      // 21 q tiles
#define NKT   (NQF / 64)       // 42 key tiles
#define KSPL  21               // key tiles per split (2 splits)
#define ATT_SCALE 0.08838834764831843f   // 1/sqrt(128)

// ---------------- scratch (device globals; no allocation) ----------------
__device__ float g_T[8 * SEQ * 64];
__device__ float g_logits[SEQ];
__device__ float g_weights[SEQ];
__device__ float g_q[SEQ * NH * DH];       // normalized q
__device__ float g_k[SEQ * 512];           // normalized k (4 heads x 128)
__device__ int   g_topk[TK];
__device__ int   g_istop[SEQ];
__device__ float g_Pq[NH * 32 * 32 * DH];  // q-sketch stage-A scratch
__device__ float g_Pk[NKV * 32 * 32 * DH]; // k-sketch stage-A scratch
__device__ float g_Ph[16 * 32 * 32 * DH];  // hs-sketch stage-A scratch
__device__ float g_HSr[SK * HID];          // rest-weighted hs sketch rows
__device__ float g_Qfr[NH * NQT * 16 * 8 * 32 * 4];
__device__ float g_Kfr[NKV * NKT * 16 * 8 * 32 * 2];
__device__ float g_Vfr[NKV * NKT * 8 * 16 * 32 * 2];
__device__ float g_AO[NQF * NH * DH];      // split-0 partial, then combined AO
__device__ float g_AO2[NQF * NH * DH];     // split-1 partial
__device__ float g_ML[2 * NQF * NH * 2];
__device__ float g_E1[32 * 32 * HID];
__device__ float g_Z[SK * HID];
__device__ float g_Afr[SEQ * HID];         // A fragments (hs, later AO)
__device__ float g_Afr2[NQF * HID];        // A fragments for V GEMM (topk hs | HSr)
__device__ float g_Bfr[40 * 128 * 2048];   // wq[0:16) | wk[16:20) | wv[20:24) | wo[24:40)

// ======================= tf32 mma.sync helpers =======================
__device__ __forceinline__ float tf32f(float x) {
    uint32_t r; asm("cvt.rna.tf32.f32 %0, %1;" : "=r"(r) : "f"(x));
    return __uint_as_float(r);
}

__device__ __forceinline__ void mma_tf32(float* c, const uint32_t* a, const uint32_t* b) {
    asm volatile("mma.sync.aligned.m16n8k8.row.col.f32.tf32.tf32.f32 "
        "{%0,%1,%2,%3}, {%4,%5,%6,%7}, {%8,%9}, {%0,%1,%2,%3};"
        : "+f"(c[0]), "+f"(c[1]), "+f"(c[2]), "+f"(c[3])
        : "r"(a[0]), "r"(a[1]), "r"(a[2]), "r"(a[3]), "r"(b[0]), "r"(b[1]));
}

#define CP_ASYNC16(dst_u32, src_ptr) \
    asm volatile("cp.async.cg.shared.global [%0], [%1], 16;" :: "r"(dst_u32), "l"(src_ptr))
#define CP_COMMIT() asm volatile("cp.async.commit_group;")

__device__ __forceinline__ void store_qfrag(float* Qg, int h, int tok, int d, float v) {
    int qt = tok >> 7, m = tok & 127;
    int k8 = d >> 3, mf = m >> 4;
    int lane = ((m & 7) << 2) | (d & 3);
    int reg = 2 * ((d & 7) >= 4) + ((m & 15) >= 8);
    size_t idx = ((((size_t)(h * NQT + qt) * 16 + k8) * 8 + mf) * 32 + lane) * 4 + reg;
    Qg[idx] = tf32f(v);
}
__device__ __forceinline__ void store_kfrag(float* Kg, int kvh, int tok, int d, float v) {
    int kt = tok >> 6, key = tok & 63;
    int k8 = d >> 3, nf = key >> 3;
    int lane = ((key & 7) << 2) | (d & 3);
    int reg = ((d & 7) >= 4);
    size_t idx = ((((size_t)(kvh * NKT + kt) * 16 + k8) * 8 + nf) * 32 + lane) * 2 + reg;
    Kg[idx] = tf32f(v);
}
__device__ __forceinline__ void store_vfrag(float* Vg, int kvh, int tok, int d, float v) {
    int kt = tok >> 6, key = tok & 63;
    int k8 = key >> 3, nf = d >> 3;
    int lane = ((d & 7) << 2) | (key & 3);
    int reg = ((key & 7) >= 4);
    size_t idx = ((((size_t)(kvh * NKT + kt) * 8 + k8) * 16 + nf) * 32 + lane) * 2 + reg;
    Vg[idx] = tf32f(v);
}

// ======================= fragment conversion pre-passes =======================
__global__ void __launch_bounds__(256) convA_kernel(const float* __restrict__ A,
                                                    const int* __restrict__ remap,
                                                    float* __restrict__ Afr, int K) {
    __shared__ float sm[2048];
    const int rt = blockIdx.y, c = blockIdx.x;
    const int tid = threadIdx.x;
#pragma unroll
    for (int i = 0; i < 2; i++) {
        int f = tid + i * 256;
        int r = f >> 2, c4 = f & 3;
        int act = remap ? __ldg(&remap[rt * 128 + r]) : (rt * 128 + r);
        float4 v = *reinterpret_cast<const float4*>(A + (size_t)act * K + c * 16 + c4 * 4);
        int mf = r >> 4, gid = r & 7, mhi = (r >> 3) & 1;
        float vv[4] = {v.x, v.y, v.z, v.w};
#pragma unroll
        for (int j = 0; j < 4; j++) {
            int k = c4 * 4 + j;
            int slot = ((k >> 3) * 8 + mf) * 128 + ((gid << 2) | (k & 3)) * 4
                     + 2 * ((k & 7) >= 4) + mhi;
            sm[slot] = tf32f(vv[j]);
        }
    }
    __syncthreads();
    float4* out = reinterpret_cast<float4*>(Afr + ((size_t)(rt * (K >> 4) + c)) * 2048);
    const float4* s4 = reinterpret_cast<const float4*>(sm);
#pragma unroll
    for (int i = 0; i < 2; i++) out[tid + i * 256] = s4[tid + i * 256];
}

__global__ void __launch_bounds__(256) convB_kernel(const float* __restrict__ B,
                                                    float* __restrict__ Bfr, int K, int N,
                                                    int ctbase) {
    __shared__ float sm[2048];
    const int ct = blockIdx.y + ctbase, c = blockIdx.x;
    const int tid = threadIdx.x;
    const float* Bb = B + ((size_t)(c * 16)) * N + blockIdx.y * 128;
#pragma unroll
    for (int i = 0; i < 2; i++) {
        int f = tid + i * 256;
        int kk = f >> 5, n4 = f & 31;
        float4 v = *reinterpret_cast<const float4*>(Bb + (size_t)kk * N + n4 * 4);
        int k8in = kk >> 3, reg = ((kk & 7) >= 4);
        float vv[4] = {v.x, v.y, v.z, v.w};
#pragma unroll
        for (int j = 0; j < 4; j++) {
            int n = n4 * 4 + j;
            int slot = (k8in * 16 + (n >> 3)) * 64 + (((n & 7) << 2) | (kk & 3)) * 2 + reg;
            sm[slot] = tf32f(vv[j]);
        }
    }
    __syncthreads();
    float4* out = reinterpret_cast<float4*>(Bfr + ((size_t)(ct * (K >> 4) + c)) * 2048);
    const float4* s4 = reinterpret_cast<const float4*>(sm);
#pragma unroll
    for (int i = 0; i < 2; i++) out[tid + i * 256] = s4[tid + i * 256];
}

// ======= tf32 GEMM: 128x128, cp.async 3-stage, 2 CTA/SM; optional rmsnorm / remap /
//         vfrag-epilogue ===
__global__ void __launch_bounds__(256, 2) mma_gemm_kernel(
    const float* __restrict__ Afr, const float* __restrict__ Bfr,
    float* __restrict__ C, const int* __restrict__ remap,
    const float* __restrict__ normw, int normct, float* __restrict__ vfr,
    int N, int K)
{
    __shared__ float sA[3][2048];
    __shared__ float sB[3][2048];

    const int tid = threadIdx.x;
    const int lane = tid & 31, wid = tid >> 5;
    const int wm = wid >> 2, wn = wid & 3;
    const int NCH = K >> 4;

    const float4* Ag = reinterpret_cast<const float4*>(Afr) + (size_t)blockIdx.y * NCH * 512;
    const float4* Bg = reinterpret_cast<const float4*>(Bfr) + (size_t)blockIdx.x * NCH * 512;

    const uint32_t sAu = (uint32_t)__cvta_generic_to_shared(&sA[0][0]) + tid * 16;
    const uint32_t sBu = (uint32_t)__cvta_generic_to_shared(&sB[0][0]) + tid * 16;

    {
        const float4* ga = Ag + tid;  const float4* gb = Bg + tid;
        CP_ASYNC16(sAu, ga); CP_ASYNC16(sAu + 4096, ga + 256);
        CP_ASYNC16(sBu, gb); CP_ASYNC16(sBu + 4096, gb + 256);
        CP_COMMIT();
        if (NCH > 1) {
            ga += 512; gb += 512;
            CP_ASYNC16(sAu + 8192, ga); CP_ASYNC16(sAu + 8192 + 4096, ga + 256);
            CP_ASYNC16(sBu + 8192, gb); CP_ASYNC16(sBu + 8192 + 4096, gb + 256);
            CP_COMMIT();
        }
    }

    float acc[4][4][4] = {};
    for (int c = 0; c < NCH; c++) {
        if (c + 1 < NCH) asm volatile("cp.async.wait_group 1;");
        else             asm volatile("cp.async.wait_group 0;");
        __syncthreads();

        const int buf = c % 3;
        const float4* A4 = reinterpret_cast<const float4*>(sA[buf]);
        const float2* B2 = reinterpret_cast<const float2*>(sB[buf]);
#pragma unroll
        for (int k8 = 0; k8 < 2; k8++) {
            float4 af[4];
            float2 bf[4];
#pragma unroll
            for (int mf = 0; mf < 4; mf++)
                af[mf] = A4[(k8 * 8 + wm * 4 + mf) * 32 + lane];
#pragma unroll
            for (int nf = 0; nf < 4; nf++)
                bf[nf] = B2[(k8 * 16 + wn * 4 + nf) * 32 + lane];
#pragma unroll
            for (int mf = 0; mf < 4; mf++)
#pragma unroll
                for (int nf = 0; nf < 4; nf++)
                    mma_tf32(acc[mf][nf],
                             reinterpret_cast<const uint32_t*>(&af[mf]),
                             reinterpret_cast<const uint32_t*>(&bf[nf]));
        }
        if (c + 2 < NCH) {
            const int st = (c + 2) % 3;
            const float4* ga = Ag + (c + 2) * 512 + tid;
            const float4* gb = Bg + (c + 2) * 512 + tid;
            CP_ASYNC16(sAu + st * 8192, ga); CP_ASYNC16(sAu + st * 8192 + 4096, ga + 256);
            CP_ASYNC16(sBu + st * 8192, gb); CP_ASYNC16(sBu + st * 8192 + 4096, gb + 256);
            CP_COMMIT();
        }
    }

    const int gid = lane >> 2, tig = lane & 3;
    const int row0 = blockIdx.y * 128;
    const int col0 = blockIdx.x * 128;

    if (vfr != nullptr) {
#pragma unroll
        for (int mf = 0; mf < 4; mf++) {
            int m = row0 + wm * 64 + mf * 16 + gid;
#pragma unroll
            for (int nf = 0; nf < 4; nf++) {
                int n = col0 + wn * 32 + nf * 8 + tig * 2;
                store_vfrag(vfr, n >> 7, m, n & 127, acc[mf][nf][0]);
                store_vfrag(vfr, (n + 1) >> 7, m, (n + 1) & 127, acc[mf][nf][1]);
                store_vfrag(vfr, n >> 7, m + 8, n & 127, acc[mf][nf][2]);
                store_vfrag(vfr, (n + 1) >> 7, m + 8, (n + 1) & 127, acc[mf][nf][3]);
            }
        }
        return;
    }

    if (normw != nullptr && blockIdx.x < normct) {
        float* ssm = &sA[0][0];
        __syncthreads();
        float ss0[4], ss1[4];
#pragma unroll
        for (int mf = 0; mf < 4; mf++) {
            float s0 = 0.f, s1 = 0.f;
#pragma unroll
            for (int nf = 0; nf < 4; nf++) {
                s0 += acc[mf][nf][0] * acc[mf][nf][0] + acc[mf][nf][1] * acc[mf][nf][1];
                s1 += acc[mf][nf][2] * acc[mf][nf][2] + acc[mf][nf][3] * acc[mf][nf][3];
            }
            s0 += __shfl_xor_sync(0xffffffffu, s0, 1);
            s0 += __shfl_xor_sync(0xffffffffu, s0, 2);
            s1 += __shfl_xor_sync(0xffffffffu, s1, 1);
            s1 += __shfl_xor_sync(0xffffffffu, s1, 2);
            ss0[mf] = s0; ss1[mf] = s1;
        }
        if (tig == 0) {
#pragma unroll
            for (int mf = 0; mf < 4; mf++) {
                int r = wm * 64 + mf * 16 + gid;
                ssm[r * 4 + wn] = ss0[mf];
                ssm[(r + 8) * 4 + wn] = ss1[mf];
            }
        }
        __syncthreads();
#pragma unroll
        for (int mf = 0; mf < 4; mf++) {
            int r = wm * 64 + mf * 16 + gid;
            float t0 = ssm[r * 4] + ssm[r * 4 + 1] + ssm[r * 4 + 2] + ssm[r * 4 + 3];
            float t1 = ssm[(r + 8) * 4] + ssm[(r + 8) * 4 + 1]
                     + ssm[(r + 8) * 4 + 2] + ssm[(r + 8) * 4 + 3];
            float sc0 = rsqrtf(t0 * (1.0f / 128.0f) + 1e-6f);
            float sc1 = rsqrtf(t1 * (1.0f / 128.0f) + 1e-6f);
#pragma unroll
            for (int nf = 0; nf < 4; nf++) {
                int n = wn * 32 + nf * 8 + tig * 2;
                float w0 = __ldg(&normw[n]), w1 = __ldg(&normw[n + 1]);
                acc[mf][nf][0] *= sc0 * w0; acc[mf][nf][1] *= sc0 * w1;
                acc[mf][nf][2] *= sc1 * w0; acc[mf][nf][3] *= sc1 * w1;
            }
        }
    }

#pragma unroll
    for (int mf = 0; mf < 4; mf++) {
        int m = row0 + wm * 64 + mf * 16 + gid;
        int m1 = remap ? __ldg(&remap[m]) : m;
        int m2 = remap ? __ldg(&remap[m + 8]) : (m + 8);
#pragma unroll
        for (int nf = 0; nf < 4; nf++) {
            int n = col0 + wn * 32 + nf * 8 + tig * 2;
            *reinterpret_cast<float2*>(&C[(size_t)m1 * N + n]) =
                make_float2(acc[mf][nf][0], acc[mf][nf][1]);
            *reinterpret_cast<float2*>(&C[(size_t)m2 * N + n]) =
                make_float2(acc[mf][nf][2], acc[mf][nf][3]);
        }
    }
}

// ---------------- importance GEMM: fp32 split-K x8 ----------------
__global__ void __launch_bounds__(256) imp_gemm_kernel(
    const float* __restrict__ A, const float* __restrict__ B, float* __restrict__ Cp)
{
    __shared__ float As[16][64];
    __shared__ float Bs[16][64];
    const int tid = threadIdx.x;
    const int row0 = blockIdx.y * 64;
    const int z = blockIdx.z;
    const float* Ab = A + (size_t)row0 * HID + z * 256;
    const float* Bb = B + (size_t)z * 256 * 64;
    float acc[4][4] = {};
    const int tc = (tid & 15) * 4, tr = (tid >> 4) * 4;
    const int ar = tid >> 2, ac = (tid & 3) * 4;
    const int br = tid >> 4, bc = (tid & 15) * 4;

    for (int k0 = 0; k0 < 256; k0 += 16) {
        float4 va = *reinterpret_cast<const float4*>(Ab + (size_t)ar * HID + k0 + ac);
        As[ac + 0][ar] = va.x; As[ac + 1][ar] = va.y;
        As[ac + 2][ar] = va.z; As[ac + 3][ar] = va.w;
        float4 vb = *reinterpret_cast<const float4*>(Bb + (size_t)(k0 + br) * 64 + bc);
        *reinterpret_cast<float4*>(&Bs[br][bc]) = vb;
        __syncthreads();
#pragma unroll
        for (int k = 0; k < 16; k++) {
            float ra[4], rb[4];
#pragma unroll
            for (int m = 0; m < 4; m++) ra[m] = As[k][tr + m];
#pragma unroll
            for (int n = 0; n < 4; n++) rb[n] = Bs[k][tc + n];
#pragma unroll
            for (int m = 0; m < 4; m++)
#pragma unroll
                for (int n = 0; n < 4; n++) acc[m][n] += ra[m] * rb[n];
        }
        __syncthreads();
    }
#pragma unroll
    for (int m = 0; m < 4; m++) {
        float4 v = make_float4(acc[m][0], acc[m][1], acc[m][2], acc[m][3]);
        *reinterpret_cast<float4*>(&Cp[((size_t)z * SEQ + row0 + tr + m) * 64 + tc]) = v;
    }
}

// ---------------- importance logits epilogue ----------------
__global__ void imp_logits_kernel(const float* __restrict__ T, const float* __restrict__ b1,
                                  const float* __restrict__ w2, const float* __restrict__ b2,
                                  float* __restrict__ logits, float* __restrict__ weights) {
    const float LOG_ADJ = 2.5494451709255714f;
    int s = blockIdx.x;
    int j = threadIdx.x;
    float v1 = 0.f, v2 = 0.f;
#pragma unroll
    for (int z = 0; z < 8; z++) {
        v1 += T[((size_t)z * SEQ + s) * 64 + j];
        v2 += T[((size_t)z * SEQ + s) * 64 + j + 32];
    }
    float v = tanhf(v1 + b1[j]) * w2[j] + tanhf(v2 + b1[j + 32]) * w2[j + 32];
#pragma unroll
    for (int o = 16; o > 0; o >>= 1) v += __shfl_xor_sync(0xffffffffu, v, o);
    if (j == 0) {
        float lg = v + b2[0] - LOG_ADJ;
        logits[s] = lg;
        weights[s] = 1.0f / (1.0f + expf(-lg));
    }
}

// ---------------- top-k via single-block bitonic sort ----------------
__global__ void topk_kernel(const float* __restrict__ logits,
                            int* __restrict__ topk_list, int* __restrict__ is_topk) {
    extern __shared__ unsigned long long skeys[];
    int tid = threadIdx.x;
    for (int i = tid; i < SEQ; i += 1024) {
        unsigned u = __float_as_uint(logits[i]);
        u = (u & 0x80000000u) ? ~u : (u | 0x80000000u);
        skeys[i] = ((unsigned long long)(~u) << 32) | (unsigned)i;
        is_topk[i] = 0;
    }
    __syncthreads();
    for (int k = 2; k <= SEQ; k <<= 1) {
        for (int j = k >> 1; j > 0; j >>= 1) {
            for (int i = tid; i < SEQ; i += 1024) {
                int ixj = i ^ j;
                if (ixj > i) {
                    bool up = ((i & k) == 0);
                    unsigned long long a = skeys[i], b = skeys[ixj];
                    if ((a > b) == up) { skeys[i] = b; skeys[ixj] = a; }
                }
            }
            __syncthreads();
        }
    }
    for (int i = tid; i < TK; i += 1024) {
        int pos = (int)(skeys[i] & 0xffffffffu);
        topk_list[i] = pos;
        is_topk[pos] = 1;
    }
}

// ---------------- sketch stage A (kbo-split x4 for occupancy) ----------------
__global__ void sketchA_kernel(const float* __restrict__ X, int hstride, int hbase,
                               const float* __restrict__ weights,
                               const int* __restrict__ is_topk, int rest,
                               const float* __restrict__ kb, float* __restrict__ P) {
    int h = blockIdx.x;
    int ib = blockIdx.y;
    int z = blockIdx.z;          // kbo quarter: [z*8, z*8+8)
    int d = threadIdx.x;
    __shared__ float kbs[8 * 256];
    for (int t = d; t < 8 * 256; t += 128) kbs[t] = kb[z * 8 * 256 + t];
    __shared__ float ws[256];
    for (int j = d; j < 256; j += 128) {
        int t = ib * 256 + j;
        float w = weights[t];
        if (rest && is_topk[t]) w = 0.0f;
        ws[j] = w;
    }
    __syncthreads();
    float acc[8] = {};
    for (int j = 0; j < 256; j++) {
        float xv = X[((size_t)(ib * 256 + j) * hstride + hbase + h) * DH + d] * ws[j];
#pragma unroll
        for (int kbo = 0; kbo < 8; kbo++) acc[kbo] += xv * kbs[kbo * 256 + j];
    }
#pragma unroll
    for (int kbo = 0; kbo < 8; kbo++)
        P[(((size_t)h * 32 + z * 8 + kbo) * 32 + ib) * DH + d] = acc[kbo];
}

// ---------------- sketch stage B (kao-split x2); mode: 0=qfrag,1=kfrag,3=dense -----
__global__ void sketchB_kernel(const float* __restrict__ P, int heads,
                               const float* __restrict__ ka,
                               const float* __restrict__ scale_p,
                               float* __restrict__ dst, int mode) {
    int h = blockIdx.x;
    int kbo = blockIdx.y;
    int zk = blockIdx.z;         // kao half: [zk*10, zk*10+10)
    int d = threadIdx.x;
    __shared__ float kas[10 * 32];
    for (int t = d; t < 10 * 32; t += 128)
        kas[t] = ka[(zk * 10 + t / 32) * DH + (t % 32)];
    __syncthreads();
    float p[32];
#pragma unroll
    for (int i = 0; i < 32; i++) p[i] = P[(((size_t)h * 32 + kbo) * 32 + i) * DH + d];
    float scale = scale_p[0];
    if (mode == 0) scale *= ATT_SCALE;
#pragma unroll
    for (int kao = 0; kao < 10; kao++) {
        float acc = 0.f;
#pragma unroll
        for (int i = 0; i < 32; i++) acc += p[i] * kas[kao * 32 + i];
        int s = TK + kbo * 20 + zk * 10 + kao;
        float val = acc * scale;
        if (mode == 0)      store_qfrag(dst, h, s, d, val);
        else if (mode == 1) store_kfrag(dst, h, s, d, val);
        else                dst[(size_t)(s - TK) * (heads * DH) + h * DH + d] = val;
    }
}

// ---------------- gather + RoPE (q and k only) ----------------
__global__ void gather_rope_kernel(const float* __restrict__ q, const float* __restrict__ k,
                                   const float* __restrict__ cosb, const float* __restrict__ sinb,
                                   const int* __restrict__ topk_list,
                                   float* __restrict__ Qfr, float* __restrict__ Kfr) {
    int j = blockIdx.x;
    int hy = blockIdx.y;   // 0..19
    int d = threadIdx.x;
    int pos = topk_list[j];
    float c = cosb[(size_t)pos * DH + d];
    float s = sinb[(size_t)pos * DH + d];
    if (hy < 16) {
        const float* src = q + ((size_t)pos * NH + hy) * DH;
        float x = src[d];
        float r = (d < 64) ? -src[d + 64] : src[d - 64];
        store_qfrag(Qfr, hy, j, d, (x * c + r * s) * ATT_SCALE);
    } else {
        int h = hy - 16;
        const float* src = k + (size_t)pos * 512 + h * DH;
        float x = src[d];
        float r = (d < 64) ? -src[d + 64] : src[d - 64];
        store_kfrag(Kfr, h, j, d, x * c + r * s);
    }
}

// ---------------- tensor-core flash attention (split-KV, cp.async K/V) -------
#define FA2_SMEM ((16384 + 2*8192 + 2*8192 + 512) * 4)
__global__ void __launch_bounds__(256, 1) fa_mma_kernel(
    const float* __restrict__ Qfr, const float* __restrict__ Kfr,
    const float* __restrict__ Vfr, float* __restrict__ Op,
    float* __restrict__ ML, int kt0)
{
    extern __shared__ float fsm[];
    float* Qsm = fsm;
    float* Ksm = fsm + 16384;
    float* Vsm = fsm + 32768;
    float* mpart = fsm + 49152;
    float* spart = fsm + 49408;

    const int qt = blockIdx.x;
    const int h  = blockIdx.y;
    const int kvh = h >> 2;
    const int tid = threadIdx.x;
    const int lane = tid & 31, wid = tid >> 5;
    const int wm = wid >> 1, wn = wid & 1;
    const int gid = lane >> 2, tig = lane & 3;

    const uint32_t ksmU = (uint32_t)__cvta_generic_to_shared(Ksm) + tid * 16;
    const uint32_t vsmU = (uint32_t)__cvta_generic_to_shared(Vsm) + tid * 16;

    {
        const float4* Kg = reinterpret_cast<const float4*>(Kfr + (size_t)(kvh * NKT + kt0) * 8192);
        const float4* Vg = reinterpret_cast<const float4*>(Vfr + (size_t)(kvh * NKT + kt0) * 8192);
#pragma unroll
        for (int i = 0; i < 8; i++) {
            CP_ASYNC16(ksmU + i * 4096, Kg + tid + i * 256);
            CP_ASYNC16(vsmU + i * 4096, Vg + tid + i * 256);
        }
        CP_COMMIT();
    }

    {
        const float4* Qg = reinterpret_cast<const float4*>(Qfr + (size_t)(h * NQT + qt) * 16384);
        float4* Qs4w = reinterpret_cast<float4*>(Qsm);
#pragma unroll
        for (int i = 0; i < 16; i++) Qs4w[tid + i * 256] = Qg[tid + i * 256];
    }

    float m_old[2][2], l_run[2][2];
#pragma unroll
    for (int a = 0; a < 2; a++)
#pragma unroll
        for (int b = 0; b < 2; b++) { m_old[a][b] = -1e30f; l_run[a][b] = 0.f; }
    float oacc[2][8][4] = {};

    const float4* Qs4 = reinterpret_cast<const float4*>(Qsm);

    for (int t = 0; t < KSPL; t++) {
        const int buf = t & 1;
        if (t + 1 < KSPL) {
            const float4* Kg = reinterpret_cast<const float4*>(Kfr + (size_t)(kvh * NKT + kt0 + t + 1) * 8192);
            const float4* Vg = reinterpret_cast<const float4*>(Vfr + (size_t)(kvh * NKT + kt0 + t + 1) * 8192);
            const uint32_t kd = ksmU + (1 - buf) * 32768;
            const uint32_t vd = vsmU + (1 - buf) * 32768;
#pragma unroll
            for (int i = 0; i < 8; i++) {
                CP_ASYNC16(kd + i * 4096, Kg + tid + i * 256);
                CP_ASYNC16(vd + i * 4096, Vg + tid + i * 256);
            }
            CP_COMMIT();
            asm volatile("cp.async.wait_group 1;");
        } else {
            asm volatile("cp.async.wait_group 0;");
        }
        __syncthreads();

        const float2* Ks2 = reinterpret_cast<const float2*>(Ksm + buf * 8192);
        const float2* Vs2 = reinterpret_cast<const float2*>(Vsm + buf * 8192);
        float* Psm = Ksm + buf * 8192;
        const float4* Ps4 = reinterpret_cast<const float4*>(Psm);

        float sacc[2][4][4] = {};
#pragma unroll
        for (int k8 = 0; k8 < 16; k8++) {
            float4 af[2];
            float2 bf[4];
            af[0] = Qs4[(k8 * 8 + wm * 2 + 0) * 32 + lane];
            af[1] = Qs4[(k8 * 8 + wm * 2 + 1) * 32 + lane];
#pragma unroll
            for (int nf = 0; nf < 4; nf++) bf[nf] = Ks2[(k8 * 8 + wn * 4 + nf) * 32 + lane];
#pragma unroll
            for (int mf = 0; mf < 2; mf++)
#pragma unroll
                for (int nf = 0; nf < 4; nf++)
                    mma_tf32(sacc[mf][nf],
                             reinterpret_cast<const uint32_t*>(&af[mf]),
                             reinterpret_cast<const uint32_t*>(&bf[nf]));
        }

        float mloc[2][2];
#pragma unroll
        for (int mf = 0; mf < 2; mf++) {
            float m0 = fmaxf(sacc[mf][0][0], sacc[mf][0][1]);
            float m1 = fmaxf(sacc[mf][0][2], sacc[mf][0][3]);
#pragma unroll
            for (int nf = 1; nf < 4; nf++) {
                m0 = fmaxf(m0, fmaxf(sacc[mf][nf][0], sacc[mf][nf][1]));
                m1 = fmaxf(m1, fmaxf(sacc[mf][nf][2], sacc[mf][nf][3]));
            }
            m0 = fmaxf(m0, __shfl_xor_sync(0xffffffffu, m0, 1));
            m0 = fmaxf(m0, __shfl_xor_sync(0xffffffffu, m0, 2));
            m1 = fmaxf(m1, __shfl_xor_sync(0xffffffffu, m1, 1));
            m1 = fmaxf(m1, __shfl_xor_sync(0xffffffffu, m1, 2));
            mloc[mf][0] = m0; mloc[mf][1] = m1;
        }
        if (tig == 0) {
#pragma unroll
            for (int mf = 0; mf < 2; mf++) {
                int r = wm * 32 + mf * 16 + gid;
                mpart[wn * 128 + r] = mloc[mf][0];
                mpart[wn * 128 + r + 8] = mloc[mf][1];
            }
        }
        __syncthreads();

        float mnew[2][2], corr[2][2];
#pragma unroll
        for (int mf = 0; mf < 2; mf++)
#pragma unroll
            for (int hi = 0; hi < 2; hi++) {
                int r = wm * 32 + mf * 16 + gid + hi * 8;
                float mt = fmaxf(mpart[r], mpart[128 + r]);
                float mn = fmaxf(m_old[mf][hi], mt);
                corr[mf][hi] = __expf(m_old[mf][hi] - mn);
                mnew[mf][hi] = mn;
                m_old[mf][hi] = mn;
            }

        float sloc[2][2] = {};
#pragma unroll
        for (int mf = 0; mf < 2; mf++)
#pragma unroll
            for (int nf = 0; nf < 4; nf++) {
                sacc[mf][nf][0] = __expf(sacc[mf][nf][0] - mnew[mf][0]);
                sacc[mf][nf][1] = __expf(sacc[mf][nf][1] - mnew[mf][0]);
                sacc[mf][nf][2] = __expf(sacc[mf][nf][2] - mnew[mf][1]);
                sacc[mf][nf][3] = __expf(sacc[mf][nf][3] - mnew[mf][1]);
                sloc[mf][0] += sacc[mf][nf][0] + sacc[mf][nf][1];
                sloc[mf][1] += sacc[mf][nf][2] + sacc[mf][nf][3];
            }
#pragma unroll
        for (int mf = 0; mf < 2; mf++) {
            sloc[mf][0] += __shfl_xor_sync(0xffffffffu, sloc[mf][0], 1);
            sloc[mf][0] += __shfl_xor_sync(0xffffffffu, sloc[mf][0], 2);
            sloc[mf][1] += __shfl_xor_sync(0xffffffffu, sloc[mf][1], 1);
            sloc[mf][1] += __shfl_xor_sync(0xffffffffu, sloc[mf][1], 2);
        }
        if (tig == 0) {
#pragma unroll
            for (int mf = 0; mf < 2; mf++) {
                int r = wm * 32 + mf * 16 + gid;
                spart[wn * 128 + r] = sloc[mf][0];
                spart[wn * 128 + r + 8] = sloc[mf][1];
            }
        }

#pragma unroll
        for (int mf = 0; mf < 2; mf++)
#pragma unroll
            for (int nf = 0; nf < 4; nf++) {
                int k8p = wn * 4 + nf;
                int mfg = wm * 2 + mf;
#pragma unroll
                for (int b = 0; b < 2; b++) {
                    int c = tig * 2 + b;
                    int khi = (c >= 4);
                    int base = ((k8p * 8 + mfg) * 32 + (gid << 2) + (c & 3)) * 4 + khi * 2;
                    *reinterpret_cast<float2*>(Psm + base) =
                        make_float2(tf32f(sacc[mf][nf][b]), tf32f(sacc[mf][nf][2 + b]));
                }
            }
        __syncthreads();

#pragma unroll
        for (int mf = 0; mf < 2; mf++)
#pragma unroll
            for (int hi = 0; hi < 2; hi++) {
                int r = wm * 32 + mf * 16 + gid + hi * 8;
                l_run[mf][hi] = l_run[mf][hi] * corr[mf][hi] + spart[r] + spart[128 + r];
            }
#pragma unroll
        for (int mf = 0; mf < 2; mf++)
#pragma unroll
            for (int nf = 0; nf < 8; nf++) {
                oacc[mf][nf][0] *= corr[mf][0]; oacc[mf][nf][1] *= corr[mf][0];
                oacc[mf][nf][2] *= corr[mf][1]; oacc[mf][nf][3] *= corr[mf][1];
            }

#pragma unroll
        for (int k8 = 0; k8 < 8; k8++) {
            float4 af[2];
            af[0] = Ps4[(k8 * 8 + wm * 2 + 0) * 32 + lane];
            af[1] = Ps4[(k8 * 8 + wm * 2 + 1) * 32 + lane];
#pragma unroll
            for (int nf = 0; nf < 8; nf++) {
                float2 bf = Vs2[(k8 * 16 + wn * 8 + nf) * 32 + lane];
#pragma unroll
                for (int mf = 0; mf < 2; mf++)
                    mma_tf32(oacc[mf][nf],
                             reinterpret_cast<const uint32_t*>(&af[mf]),
                             reinterpret_cast<const uint32_t*>(&bf));
            }
        }
        __syncthreads();
    }

#pragma unroll
    for (int mf = 0; mf < 2; mf++) {
        int r0 = qt * 128 + wm * 32 + mf * 16 + gid;
        if (wn == 0 && tig == 0) {
            size_t row0i = (size_t)r0 * NH + h;
            size_t row1i = (size_t)(r0 + 8) * NH + h;
            ML[row0i * 2] = m_old[mf][0]; ML[row0i * 2 + 1] = l_run[mf][0];
            ML[row1i * 2] = m_old[mf][1]; ML[row1i * 2 + 1] = l_run[mf][1];
        }
#pragma unroll
        for (int nf = 0; nf < 8; nf++) {
            int col = wn * 64 + nf * 8 + tig * 2;
            *reinterpret_cast<float2*>(&Op[((size_t)r0 * NH + h) * DH + col]) =
                make_float2(oacc[mf][nf][0], oacc[mf][nf][1]);
            *reinterpret_cast<float2*>(&Op[((size_t)(r0 + 8) * NH + h) * DH + col]) =
                make_float2(oacc[mf][nf][2], oacc[mf][nf][3]);
        }
    }
}

// ---------------- fa combine ----------------
__global__ void fa_combine_kernel(float* __restrict__ O0, const float* __restrict__ O1,
                                  const float* __restrict__ ML) {
    size_t row = (size_t)blockIdx.x * NH + blockIdx.y;
    int d = threadIdx.x;
    float m0 = ML[row * 2], l0 = ML[row * 2 + 1];
    float m1 = ML[(size_t)NQF * NH * 2 + row * 2], l1 = ML[(size_t)NQF * NH * 2 + row * 2 + 1];
    float m = fmaxf(m0, m1);
    float w0 = __expf(m0 - m), w1 = __expf(m1 - m);
    float inv = 1.0f / (w0 * l0 + w1 * l1);
    O0[row * DH + d] = (O0[row * DH + d] * w0 + O1[row * DH + d] * w1) * inv;
}

// ---------------- expand stage C ----------------
__global__ void expandC_kernel(const float* __restrict__ Z, const float* __restrict__ ka,
                               float* __restrict__ E1) {
    int i = blockIdx.y;
    int hd = blockIdx.x * 256 + threadIdx.x;
    __shared__ float kav[20];
    if (threadIdx.x < 20) kav[threadIdx.x] = ka[threadIdx.x * DH + i];
    __syncthreads();
    for (int kbo = 0; kbo < 32; kbo++) {
        float acc = 0.f;
#pragma unroll
        for (int kao = 0; kao < 20; kao++)
            acc += Z[((size_t)(kbo * 20 + kao)) * HID + hd] * kav[kao];
        E1[((size_t)i * 32 + kbo) * HID + hd] = acc;
    }
}

// ---------------- expand stage D ----------------
__global__ void expandD_kernel(const float* __restrict__ E1, const float* __restrict__ kb,
                               const int* __restrict__ is_topk, float* __restrict__ OUT) {
    int i = blockIdx.y;
    int hd = blockIdx.x * 128 + threadIdx.x;
    __shared__ float kbs[32 * 256];
    for (int t = threadIdx.x; t < 32 * 256; t += 128) kbs[t] = kb[t];
    float e[32];
#pragma unroll
    for (int kbo = 0; kbo < 32; kbo++) e[kbo] = E1[((size_t)i * 32 + kbo) * HID + hd];
    __syncthreads();
    for (int j = 0; j < 256; j++) {
        int row = i * 256 + j;
        if (is_topk[row]) continue;
        float acc = 0.f;
#pragma unroll
        for (int kbo = 0; kbo < 32; kbo++) acc += e[kbo] * kbs[kbo * 256 + j];
        OUT[(size_t)row * HID + hd] = acc;
    }
}

// ---------------- host launcher ----------------
extern "C" void kernel_launch(void* const* d_in, const int* in_sizes, int n_in,
                              void* d_out, int out_size) {
    const float* hs    = (const float*)d_in[0];
    const float* cosb  = (const float*)d_in[1];
    const float* sinb  = (const float*)d_in[2];
    const float* wq    = (const float*)d_in[3];
    const float* wk    = (const float*)d_in[4];
    const float* wv    = (const float*)d_in[5];
    const float* wo    = (const float*)d_in[6];
    const float* qnw   = (const float*)d_in[7];
    const float* knw   = (const float*)d_in[8];
    const float* w1    = (const float*)d_in[9];
    const float* b1    = (const float*)d_in[10];
    const float* w2    = (const float*)d_in[11];
    const float* b2    = (const float*)d_in[12];
    const float* ka    = (const float*)d_in[13];
    const float* kb    = (const float*)d_in[14];
    const float* sscale= (const float*)d_in[15];
    float* out = (float*)d_out;

    float *pT, *pLg, *pW, *pQ, *pK, *pPq, *pPk, *pPh, *pHSr, *pQfr, *pKfr, *pVfr,
          *pAO, *pAO2, *pML, *pE1, *pZ, *pAfr, *pAfr2, *pBfr;
    int *pTop, *pIs;
    cudaGetSymbolAddress((void**)&pT, g_T);
    cudaGetSymbolAddress((void**)&pLg, g_logits);
    cudaGetSymbolAddress((void**)&pW, g_weights);
    cudaGetSymbolAddress((void**)&pQ, g_q);
    cudaGetSymbolAddress((void**)&pK, g_k);
    cudaGetSymbolAddress((void**)&pPq, g_Pq);
    cudaGetSymbolAddress((void**)&pPk, g_Pk);
    cudaGetSymbolAddress((void**)&pPh, g_Ph);
    cudaGetSymbolAddress((void**)&pHSr, g_HSr);
    cudaGetSymbolAddress((void**)&pQfr, g_Qfr);
    cudaGetSymbolAddress((void**)&pKfr, g_Kfr);
    cudaGetSymbolAddress((void**)&pVfr, g_Vfr);
    cudaGetSymbolAddress((void**)&pAO, g_AO);
    cudaGetSymbolAddress((void**)&pAO2, g_AO2);
    cudaGetSymbolAddress((void**)&pML, g_ML);
    cudaGetSymbolAddress((void**)&pE1, g_E1);
    cudaGetSymbolAddress((void**)&pZ, g_Z);
    cudaGetSymbolAddress((void**)&pAfr, g_Afr);
    cudaGetSymbolAddress((void**)&pAfr2, g_Afr2);
    cudaGetSymbolAddress((void**)&pBfr, g_Bfr);
    cudaGetSymbolAddress((void**)&pTop, g_topk);
    cudaGetSymbolAddress((void**)&pIs, g_istop);

    float* pBwk = pBfr + (size_t)16 * 128 * 2048;
    float* pBwv = pBfr + (size_t)20 * 128 * 2048;
    float* pBwo = pBfr + (size_t)24 * 128 * 2048;
    float* pML2 = pML + (size_t)NQF * NH * 2;
    float* pAfr2b = pAfr2 + (size_t)16 * (HID / 16) * 2048;

    cudaFuncSetAttribute(topk_kernel, cudaFuncAttributeMaxDynamicSharedMemorySize, SEQ * 8);
    cudaFuncSetAttribute(fa_mma_kernel, cudaFuncAttributeMaxDynamicSharedMemorySize, FA2_SMEM);

    static cudaStream_t s1 = nullptr;
    static cudaEvent_t evFork = nullptr, evImp = nullptr, evAfr = nullptr,
                       evVf = nullptr, evK = nullptr, evKf = nullptr,
                       evQg = nullptr, evFA1 = nullptr, evAO = nullptr, evExp = nullptr;
    if (s1 == nullptr) {
        cudaStreamCreateWithFlags(&s1, cudaStreamNonBlocking);
        cudaEventCreateWithFlags(&evFork, cudaEventDisableTiming);
        cudaEventCreateWithFlags(&evImp, cudaEventDisableTiming);
        cudaEventCreateWithFlags(&evAfr, cudaEventDisableTiming);
        cudaEventCreateWithFlags(&evVf, cudaEventDisableTiming);
        cudaEventCreateWithFlags(&evK, cudaEventDisableTiming);
        cudaEventCreateWithFlags(&evKf, cudaEventDisableTiming);
        cudaEventCreateWithFlags(&evQg, cudaEventDisableTiming);
        cudaEventCreateWithFlags(&evFA1, cudaEventDisableTiming);
        cudaEventCreateWithFlags(&evAO, cudaEventDisableTiming);
        cudaEventCreateWithFlags(&evExp, cudaEventDisableTiming);
    }

    // ---- fork ----
    cudaEventRecord(evFork, 0);
    cudaStreamWaitEvent(s1, evFork, 0);

    // ---- s1: importance chain ----
    imp_gemm_kernel<<<dim3(1, SEQ / 64, 8), 256, 0, s1>>>(hs, w1, pT);
    imp_logits_kernel<<<SEQ, 32, 0, s1>>>(pT, b1, w2, b2, pLg, pW);
    topk_kernel<<<1, 1024, SEQ * 8, s1>>>(pLg, pTop, pIs);
    cudaEventRecord(evImp, s1);

    // ---- s1: V path ----
    sketchA_kernel<<<dim3(16, 32, 4), DH, 0, s1>>>(hs, 16, 0, pW, pIs, 1, kb, pPh);
    sketchB_kernel<<<dim3(16, 32, 2), DH, 0, s1>>>(pPh, 16, ka, sscale, pHSr, 3);
    convA_kernel<<<dim3(HID / 16, 16), 256, 0, s1>>>(hs, pTop, pAfr2, HID);
    convA_kernel<<<dim3(HID / 16, 5), 256, 0, s1>>>(pHSr, nullptr, pAfr2b, HID);
    convB_kernel<<<dim3(HID / 16, 512 / 128), 256, 0, s1>>>(wv, pBwv, HID, 512, 0);
    mma_gemm_kernel<<<dim3(512 / 128, NQF / 128), 256, 0, s1>>>(
        pAfr2, pBwv, pVfr, nullptr, nullptr, 0, pVfr, 512, HID);
    cudaEventRecord(evVf, s1);

    // ---- default: Q projection chain ----
    convA_kernel<<<dim3(HID / 16, SEQ / 128), 256>>>(hs, nullptr, pAfr, HID);
    cudaEventRecord(evAfr, 0);
    convB_kernel<<<dim3(HID / 16, HID / 128), 256>>>(wq, pBfr, HID, HID, 0);
    mma_gemm_kernel<<<dim3(HID / 128, SEQ / 128), 256>>>(pAfr, pBfr, pQ, nullptr, qnw, 16, nullptr, HID, HID);

    // ---- s1: K projection + k-sketch ----
    convB_kernel<<<dim3(HID / 16, 512 / 128), 256, 0, s1>>>(wk, pBwk, HID, 512, 0);
    cudaStreamWaitEvent(s1, evAfr, 0);
    mma_gemm_kernel<<<dim3(512 / 128, SEQ / 128), 256, 0, s1>>>(
        pAfr, pBwk, pK, nullptr, knw, 4, nullptr, 512, HID);
    cudaEventRecord(evK, s1);
    sketchA_kernel<<<dim3(NKV, 32, 4), DH, 0, s1>>>(pK, 4, 0, pW, pIs, 1, kb, pPk);
    sketchB_kernel<<<dim3(NKV, 32, 2), DH, 0, s1>>>(pPk, NKV, ka, sscale, pKfr, 1);
    cudaEventRecord(evKf, s1);
    convB_kernel<<<dim3(HID / 16, HID / 128), 256, 0, s1>>>(wo, pBwo, HID, HID, 0);

    // ---- default: q sketch + gather ----
    cudaStreamWaitEvent(0, evImp, 0);
    sketchA_kernel<<<dim3(NH, 32, 4), DH>>>(pQ, 16, 0, pW, pIs, 0, kb, pPq);
    sketchB_kernel<<<dim3(NH, 32, 2), DH>>>(pPq, NH, ka, sscale, pQfr, 0);
    cudaStreamWaitEvent(0, evK, 0);
    gather_rope_kernel<<<dim3(TK, 20), DH>>>(pQ, pK, cosb, sinb, pTop, pQfr, pKfr);
    cudaEventRecord(evQg, 0);

    // ---- attention: split-KV x2 + combine ----
    cudaStreamWaitEvent(0, evKf, 0);
    cudaStreamWaitEvent(0, evVf, 0);
    cudaStreamWaitEvent(s1, evQg, 0);
    fa_mma_kernel<<<dim3(NQT, NH), 256, FA2_SMEM>>>(pQfr, pKfr, pVfr, pAO, pML, 0);
    fa_mma_kernel<<<dim3(NQT, NH), 256, FA2_SMEM, s1>>>(pQfr, pKfr, pVfr, pAO2, pML2, KSPL);
    cudaEventRecord(evFA1, s1);
    cudaStreamWaitEvent(0, evFA1, 0);
    fa_combine_kernel<<<dim3(NQF, NH), DH>>>(pAO, pAO2, pML);

    // ---- epilogue ----
    convA_kernel<<<dim3(HID / 16, NQF / 128), 256>>>(pAO, nullptr, pAfr, HID);
    cudaEventRecord(evAO, 0);
    cudaStreamWaitEvent(s1, evAO, 0);
    mma_gemm_kernel<<<dim3(HID / 128, SK / 128), 256, 0, s1>>>(
        pAfr + (size_t)16 * (HID / 16) * 2048, pBwo, pZ, nullptr, nullptr, 0, nullptr, HID, HID);
    expandC_kernel<<<dim3(HID / 256, 32), 256, 0, s1>>>(pZ, ka, pE1);
    expandD_kernel<<<dim3(HID / 128, 32), DH, 0, s1>>>(pE1, kb, pIs, out);
    cudaEventRecord(evExp, s1);
    mma_gemm_kernel<<<dim3(HID / 128, TK / 128), 256>>>(pAfr, pBwo, out, pTop, nullptr, 0, nullptr, HID, HID);

    // ---- join ----
    cudaStreamWaitEvent(0, evExp, 0);
}

// round 14
// speedup vs baseline: 1.0296x; 1.0296x over previous
#include <cuda_runtime.h>
#include <cuda_bf16.h>
#include <math.h>
#include <cstdint>

// Problem constants
#define SEQ   8192
#define HID   2048
#define NH    16
#define NKV   4
#define DH    128
#define TK    2048
#define SK    640
#define NQF   (TK + SK)        // 2688
#define NQT   (NQF / 128)      // 21 q tiles
#define NKT   (NQF / 64)       // 42 key tiles
#define KSPL  21               // key tiles per split (2 splits)
#define ATT_SCALE 0.08838834764831843f   // 1/sqrt(128)

// ---------------- scratch (device globals; no allocation) ----------------
__device__ float g_T[8 * SEQ * 64];
__device__ float g_logits[SEQ];
__device__ float g_weights[SEQ];
__device__ float g_q[SEQ * NH * DH];       // normalized q
__device__ float g_k[SEQ * 512];           // normalized k (4 heads x 128)
__device__ int   g_topk[TK];
__device__ int   g_istop[SEQ];
__device__ float g_Pq[NH * 32 * 32 * DH];  // q-sketch stage-A scratch
__device__ float g_Pk[NKV * 32 * 32 * DH]; // k-sketch stage-A scratch
__device__ float g_Ph[16 * 32 * 32 * DH];  // hs-sketch stage-A scratch
__device__ float g_HSr[SK * HID];          // rest-weighted hs sketch rows
__device__ float g_Qfr[NH * NQT * 16 * 8 * 32 * 4];
__device__ float g_Kfr[NKV * NKT * 16 * 8 * 32 * 2];
__device__ float g_Vfr[NKV * NKT * 8 * 16 * 32 * 2];
__device__ float g_AO[NQF * NH * DH];      // split-0 partial, then combined AO
__device__ float g_AO2[NQF * NH * DH];     // split-1 partial
__device__ float g_ML[2 * NQF * NH * 2];
__device__ float g_E1[32 * 32 * HID];
__device__ float g_Z[SK * HID];
__device__ float g_Afr[SEQ * HID];         // A fragments (hs, later AO)
__device__ float g_Afr2[NQF * HID];        // A fragments for V GEMM (topk hs | HSr)
__device__ float g_Bfr[40 * 128 * 2048];   // wq[0:16) | wk[16:20) | wv[20:24) | wo[24:40)

// ======================= tf32 mma.sync helpers =======================
__device__ __forceinline__ float tf32f(float x) {
    uint32_t r; asm("cvt.rna.tf32.f32 %0, %1;" : "=r"(r) : "f"(x));
    return __uint_as_float(r);
}

__device__ __forceinline__ void mma_tf32(float* c, const uint32_t* a, const uint32_t* b) {
    asm volatile("mma.sync.aligned.m16n8k8.row.col.f32.tf32.tf32.f32 "
        "{%0,%1,%2,%3}, {%4,%5,%6,%7}, {%8,%9}, {%0,%1,%2,%3};"
        : "+f"(c[0]), "+f"(c[1]), "+f"(c[2]), "+f"(c[3])
        : "r"(a[0]), "r"(a[1]), "r"(a[2]), "r"(a[3]), "r"(b[0]), "r"(b[1]));
}

#define CP_ASYNC16(dst_u32, src_ptr) \
    asm volatile("cp.async.cg.shared.global [%0], [%1], 16;" :: "r"(dst_u32), "l"(src_ptr))
#define CP_COMMIT() asm volatile("cp.async.commit_group;")

__device__ __forceinline__ void store_qfrag(float* Qg, int h, int tok, int d, float v) {
    int qt = tok >> 7, m = tok & 127;
    int k8 = d >> 3, mf = m >> 4;
    int lane = ((m & 7) << 2) | (d & 3);
    int reg = 2 * ((d & 7) >= 4) + ((m & 15) >= 8);
    size_t idx = ((((size_t)(h * NQT + qt) * 16 + k8) * 8 + mf) * 32 + lane) * 4 + reg;
    Qg[idx] = tf32f(v);
}
__device__ __forceinline__ void store_kfrag(float* Kg, int kvh, int tok, int d, float v) {
    int kt = tok >> 6, key = tok & 63;
    int k8 = d >> 3, nf = key >> 3;
    int lane = ((key & 7) << 2) | (d & 3);
    int reg = ((d & 7) >= 4);
    size_t idx = ((((size_t)(kvh * NKT + kt) * 16 + k8) * 8 + nf) * 32 + lane) * 2 + reg;
    Kg[idx] = tf32f(v);
}
__device__ __forceinline__ void store_vfrag(float* Vg, int kvh, int tok, int d, float v) {
    int kt = tok >> 6, key = tok & 63;
    int k8 = key >> 3, nf = d >> 3;
    int lane = ((d & 7) << 2) | (key & 3);
    int reg = ((key & 7) >= 4);
    size_t idx = ((((size_t)(kvh * NKT + kt) * 8 + k8) * 16 + nf) * 32 + lane) * 2 + reg;
    Vg[idx] = tf32f(v);
}

// ======================= fragment conversion pre-passes =======================
__global__ void __launch_bounds__(256) convA_kernel(const float* __restrict__ A,
                                                    const int* __restrict__ remap,
                                                    float* __restrict__ Afr, int K) {
    __shared__ float sm[2048];
    const int rt = blockIdx.y, c = blockIdx.x;
    const int tid = threadIdx.x;
#pragma unroll
    for (int i = 0; i < 2; i++) {
        int f = tid + i * 256;
        int r = f >> 2, c4 = f & 3;
        int act = remap ? __ldg(&remap[rt * 128 + r]) : (rt * 128 + r);
        float4 v = *reinterpret_cast<const float4*>(A + (size_t)act * K + c * 16 + c4 * 4);
        int mf = r >> 4, gid = r & 7, mhi = (r >> 3) & 1;
        float vv[4] = {v.x, v.y, v.z, v.w};
#pragma unroll
        for (int j = 0; j < 4; j++) {
            int k = c4 * 4 + j;
            int slot = ((k >> 3) * 8 + mf) * 128 + ((gid << 2) | (k & 3)) * 4
                     + 2 * ((k & 7) >= 4) + mhi;
            sm[slot] = tf32f(vv[j]);
        }
    }
    __syncthreads();
    float4* out = reinterpret_cast<float4*>(Afr + ((size_t)(rt * (K >> 4) + c)) * 2048);
    const float4* s4 = reinterpret_cast<const float4*>(sm);
#pragma unroll
    for (int i = 0; i < 2; i++) out[tid + i * 256] = s4[tid + i * 256];
}

__global__ void __launch_bounds__(256) convB_kernel(const float* __restrict__ B,
                                                    float* __restrict__ Bfr, int K, int N,
                                                    int ctbase) {
    __shared__ float sm[2048];
    const int ct = blockIdx.y + ctbase, c = blockIdx.x;
    const int tid = threadIdx.x;
    const float* Bb = B + ((size_t)(c * 16)) * N + blockIdx.y * 128;
#pragma unroll
    for (int i = 0; i < 2; i++) {
        int f = tid + i * 256;
        int kk = f >> 5, n4 = f & 31;
        float4 v = *reinterpret_cast<const float4*>(Bb + (size_t)kk * N + n4 * 4);
        int k8in = kk >> 3, reg = ((kk & 7) >= 4);
        float vv[4] = {v.x, v.y, v.z, v.w};
#pragma unroll
        for (int j = 0; j < 4; j++) {
            int n = n4 * 4 + j;
            int slot = (k8in * 16 + (n >> 3)) * 64 + (((n & 7) << 2) | (kk & 3)) * 2 + reg;
            sm[slot] = tf32f(vv[j]);
        }
    }
    __syncthreads();
    float4* out = reinterpret_cast<float4*>(Bfr + ((size_t)(ct * (K >> 4) + c)) * 2048);
    const float4* s4 = reinterpret_cast<const float4*>(sm);
#pragma unroll
    for (int i = 0; i < 2; i++) out[tid + i * 256] = s4[tid + i * 256];
}

// ======= tf32 GEMM: 128x128, cp.async 3-stage, 2 CTA/SM; optional rmsnorm / remap /
//         vfrag-epilogue ===
__global__ void __launch_bounds__(256, 2) mma_gemm_kernel(
    const float* __restrict__ Afr, const float* __restrict__ Bfr,
    float* __restrict__ C, const int* __restrict__ remap,
    const float* __restrict__ normw, int normct, float* __restrict__ vfr,
    int N, int K)
{
    __shared__ float sA[3][2048];
    __shared__ float sB[3][2048];

    const int tid = threadIdx.x;
    const int lane = tid & 31, wid = tid >> 5;
    const int wm = wid >> 2, wn = wid & 3;
    const int NCH = K >> 4;

    const float4* Ag = reinterpret_cast<const float4*>(Afr) + (size_t)blockIdx.y * NCH * 512;
    const float4* Bg = reinterpret_cast<const float4*>(Bfr) + (size_t)blockIdx.x * NCH * 512;

    const uint32_t sAu = (uint32_t)__cvta_generic_to_shared(&sA[0][0]) + tid * 16;
    const uint32_t sBu = (uint32_t)__cvta_generic_to_shared(&sB[0][0]) + tid * 16;

    {
        const float4* ga = Ag + tid;  const float4* gb = Bg + tid;
        CP_ASYNC16(sAu, ga); CP_ASYNC16(sAu + 4096, ga + 256);
        CP_ASYNC16(sBu, gb); CP_ASYNC16(sBu + 4096, gb + 256);
        CP_COMMIT();
        if (NCH > 1) {
            ga += 512; gb += 512;
            CP_ASYNC16(sAu + 8192, ga); CP_ASYNC16(sAu + 8192 + 4096, ga + 256);
            CP_ASYNC16(sBu + 8192, gb); CP_ASYNC16(sBu + 8192 + 4096, gb + 256);
            CP_COMMIT();
        }
    }

    float acc[4][4][4] = {};
    for (int c = 0; c < NCH; c++) {
        if (c + 1 < NCH) asm volatile("cp.async.wait_group 1;");
        else             asm volatile("cp.async.wait_group 0;");
        __syncthreads();

        const int buf = c % 3;
        const float4* A4 = reinterpret_cast<const float4*>(sA[buf]);
        const float2* B2 = reinterpret_cast<const float2*>(sB[buf]);
#pragma unroll
        for (int k8 = 0; k8 < 2; k8++) {
            float4 af[4];
            float2 bf[4];
#pragma unroll
            for (int mf = 0; mf < 4; mf++)
                af[mf] = A4[(k8 * 8 + wm * 4 + mf) * 32 + lane];
#pragma unroll
            for (int nf = 0; nf < 4; nf++)
                bf[nf] = B2[(k8 * 16 + wn * 4 + nf) * 32 + lane];
#pragma unroll
            for (int mf = 0; mf < 4; mf++)
#pragma unroll
                for (int nf = 0; nf < 4; nf++)
                    mma_tf32(acc[mf][nf],
                             reinterpret_cast<const uint32_t*>(&af[mf]),
                             reinterpret_cast<const uint32_t*>(&bf[nf]));
        }
        if (c + 2 < NCH) {
            const int st = (c + 2) % 3;
            const float4* ga = Ag + (c + 2) * 512 + tid;
            const float4* gb = Bg + (c + 2) * 512 + tid;
            CP_ASYNC16(sAu + st * 8192, ga); CP_ASYNC16(sAu + st * 8192 + 4096, ga + 256);
            CP_ASYNC16(sBu + st * 8192, gb); CP_ASYNC16(sBu + st * 8192 + 4096, gb + 256);
            CP_COMMIT();
        }
    }

    const int gid = lane >> 2, tig = lane & 3;
    const int row0 = blockIdx.y * 128;
    const int col0 = blockIdx.x * 128;

    if (vfr != nullptr) {
#pragma unroll
        for (int mf = 0; mf < 4; mf++) {
            int m = row0 + wm * 64 + mf * 16 + gid;
#pragma unroll
            for (int nf = 0; nf < 4; nf++) {
                int n = col0 + wn * 32 + nf * 8 + tig * 2;
                store_vfrag(vfr, n >> 7, m, n & 127, acc[mf][nf][0]);
                store_vfrag(vfr, (n + 1) >> 7, m, (n + 1) & 127, acc[mf][nf][1]);
                store_vfrag(vfr, n >> 7, m + 8, n & 127, acc[mf][nf][2]);
                store_vfrag(vfr, (n + 1) >> 7, m + 8, (n + 1) & 127, acc[mf][nf][3]);
            }
        }
        return;
    }

    if (normw != nullptr && blockIdx.x < normct) {
        float* ssm = &sA[0][0];
        __syncthreads();
        float ss0[4], ss1[4];
#pragma unroll
        for (int mf = 0; mf < 4; mf++) {
            float s0 = 0.f, s1 = 0.f;
#pragma unroll
            for (int nf = 0; nf < 4; nf++) {
                s0 += acc[mf][nf][0] * acc[mf][nf][0] + acc[mf][nf][1] * acc[mf][nf][1];
                s1 += acc[mf][nf][2] * acc[mf][nf][2] + acc[mf][nf][3] * acc[mf][nf][3];
            }
            s0 += __shfl_xor_sync(0xffffffffu, s0, 1);
            s0 += __shfl_xor_sync(0xffffffffu, s0, 2);
            s1 += __shfl_xor_sync(0xffffffffu, s1, 1);
            s1 += __shfl_xor_sync(0xffffffffu, s1, 2);
            ss0[mf] = s0; ss1[mf] = s1;
        }
        if (tig == 0) {
#pragma unroll
            for (int mf = 0; mf < 4; mf++) {
                int r = wm * 64 + mf * 16 + gid;
                ssm[r * 4 + wn] = ss0[mf];
                ssm[(r + 8) * 4 + wn] = ss1[mf];
            }
        }
        __syncthreads();
#pragma unroll
        for (int mf = 0; mf < 4; mf++) {
            int r = wm * 64 + mf * 16 + gid;
            float t0 = ssm[r * 4] + ssm[r * 4 + 1] + ssm[r * 4 + 2] + ssm[r * 4 + 3];
            float t1 = ssm[(r + 8) * 4] + ssm[(r + 8) * 4 + 1]
                     + ssm[(r + 8) * 4 + 2] + ssm[(r + 8) * 4 + 3];
            float sc0 = rsqrtf(t0 * (1.0f / 128.0f) + 1e-6f);
            float sc1 = rsqrtf(t1 * (1.0f / 128.0f) + 1e-6f);
#pragma unroll
            for (int nf = 0; nf < 4; nf++) {
                int n = wn * 32 + nf * 8 + tig * 2;
                float w0 = __ldg(&normw[n]), w1 = __ldg(&normw[n + 1]);
                acc[mf][nf][0] *= sc0 * w0; acc[mf][nf][1] *= sc0 * w1;
                acc[mf][nf][2] *= sc1 * w0; acc[mf][nf][3] *= sc1 * w1;
            }
        }
    }

#pragma unroll
    for (int mf = 0; mf < 4; mf++) {
        int m = row0 + wm * 64 + mf * 16 + gid;
        int m1 = remap ? __ldg(&remap[m]) : m;
        int m2 = remap ? __ldg(&remap[m + 8]) : (m + 8);
#pragma unroll
        for (int nf = 0; nf < 4; nf++) {
            int n = col0 + wn * 32 + nf * 8 + tig * 2;
            *reinterpret_cast<float2*>(&C[(size_t)m1 * N + n]) =
                make_float2(acc[mf][nf][0], acc[mf][nf][1]);
            *reinterpret_cast<float2*>(&C[(size_t)m2 * N + n]) =
                make_float2(acc[mf][nf][2], acc[mf][nf][3]);
        }
    }
}

// ---------------- importance GEMM: fp32 split-K x8 ----------------
__global__ void __launch_bounds__(256) imp_gemm_kernel(
    const float* __restrict__ A, const float* __restrict__ B, float* __restrict__ Cp)
{
    __shared__ float As[16][64];
    __shared__ float Bs[16][64];
    const int tid = threadIdx.x;
    const int row0 = blockIdx.y * 64;
    const int z = blockIdx.z;
    const float* Ab = A + (size_t)row0 * HID + z * 256;
    const float* Bb = B + (size_t)z * 256 * 64;
    float acc[4][4] = {};
    const int tc = (tid & 15) * 4, tr = (tid >> 4) * 4;
    const int ar = tid >> 2, ac = (tid & 3) * 4;
    const int br = tid >> 4, bc = (tid & 15) * 4;

    for (int k0 = 0; k0 < 256; k0 += 16) {
        float4 va = *reinterpret_cast<const float4*>(Ab + (size_t)ar * HID + k0 + ac);
        As[ac + 0][ar] = va.x; As[ac + 1][ar] = va.y;
        As[ac + 2][ar] = va.z; As[ac + 3][ar] = va.w;
        float4 vb = *reinterpret_cast<const float4*>(Bb + (size_t)(k0 + br) * 64 + bc);
        *reinterpret_cast<float4*>(&Bs[br][bc]) = vb;
        __syncthreads();
#pragma unroll
        for (int k = 0; k < 16; k++) {
            float ra[4], rb[4];
#pragma unroll
            for (int m = 0; m < 4; m++) ra[m] = As[k][tr + m];
#pragma unroll
            for (int n = 0; n < 4; n++) rb[n] = Bs[k][tc + n];
#pragma unroll
            for (int m = 0; m < 4; m++)
#pragma unroll
                for (int n = 0; n < 4; n++) acc[m][n] += ra[m] * rb[n];
        }
        __syncthreads();
    }
#pragma unroll
    for (int m = 0; m < 4; m++) {
        float4 v = make_float4(acc[m][0], acc[m][1], acc[m][2], acc[m][3]);
        *reinterpret_cast<float4*>(&Cp[((size_t)z * SEQ + row0 + tr + m) * 64 + tc]) = v;
    }
}

// ---------------- importance logits epilogue ----------------
__global__ void imp_logits_kernel(const float* __restrict__ T, const float* __restrict__ b1,
                                  const float* __restrict__ w2, const float* __restrict__ b2,
                                  float* __restrict__ logits, float* __restrict__ weights) {
    const float LOG_ADJ = 2.5494451709255714f;
    int s = blockIdx.x;
    int j = threadIdx.x;
    float v1 = 0.f, v2 = 0.f;
#pragma unroll
    for (int z = 0; z < 8; z++) {
        v1 += T[((size_t)z * SEQ + s) * 64 + j];
        v2 += T[((size_t)z * SEQ + s) * 64 + j + 32];
    }
    float v = tanhf(v1 + b1[j]) * w2[j] + tanhf(v2 + b1[j + 32]) * w2[j + 32];
#pragma unroll
    for (int o = 16; o > 0; o >>= 1) v += __shfl_xor_sync(0xffffffffu, v, o);
    if (j == 0) {
        float lg = v + b2[0] - LOG_ADJ;
        logits[s] = lg;
        weights[s] = 1.0f / (1.0f + expf(-lg));
    }
}

// ---------------- top-k via single-block bitonic sort ----------------
__global__ void topk_kernel(const float* __restrict__ logits,
                            int* __restrict__ topk_list, int* __restrict__ is_topk) {
    extern __shared__ unsigned long long skeys[];
    int tid = threadIdx.x;
    for (int i = tid; i < SEQ; i += 1024) {
        unsigned u = __float_as_uint(logits[i]);
        u = (u & 0x80000000u) ? ~u : (u | 0x80000000u);
        skeys[i] = ((unsigned long long)(~u) << 32) | (unsigned)i;
        is_topk[i] = 0;
    }
    __syncthreads();
    for (int k = 2; k <= SEQ; k <<= 1) {
        for (int j = k >> 1; j > 0; j >>= 1) {
            for (int i = tid; i < SEQ; i += 1024) {
                int ixj = i ^ j;
                if (ixj > i) {
                    bool up = ((i & k) == 0);
                    unsigned long long a = skeys[i], b = skeys[ixj];
                    if ((a > b) == up) { skeys[i] = b; skeys[ixj] = a; }
                }
            }
            __syncthreads();
        }
    }
    for (int i = tid; i < TK; i += 1024) {
        int pos = (int)(skeys[i] & 0xffffffffu);
        topk_list[i] = pos;
        is_topk[pos] = 1;
    }
}

// ---------------- sketch stage A (kbo-split x2, j-unrolled x4 for MLP) ----------------
__global__ void sketchA_kernel(const float* __restrict__ X, int hstride, int hbase,
                               const float* __restrict__ weights,
                               const int* __restrict__ is_topk, int rest,
                               const float* __restrict__ kb, float* __restrict__ P) {
    int h = blockIdx.x;
    int ib = blockIdx.y;
    int z = blockIdx.z;          // kbo half: [z*16, z*16+16)
    int d = threadIdx.x;
    __shared__ float kbs[16 * 256];
    for (int t = d; t < 16 * 256; t += 128) kbs[t] = kb[z * 16 * 256 + t];
    __shared__ float ws[256];
    for (int j = d; j < 256; j += 128) {
        int t = ib * 256 + j;
        float w = weights[t];
        if (rest && is_topk[t]) w = 0.0f;
        ws[j] = w;
    }
    __syncthreads();
    float acc[16] = {};
    const size_t rowstride = (size_t)hstride * DH;
    const float* Xb = X + ((size_t)(ib * 256) * hstride + hbase + h) * DH + d;
    for (int j = 0; j < 256; j += 4) {
        // front-batch 4 independent global loads (MLP=4)
        float x0 = Xb[(size_t)(j + 0) * rowstride];
        float x1 = Xb[(size_t)(j + 1) * rowstride];
        float x2 = Xb[(size_t)(j + 2) * rowstride];
        float x3 = Xb[(size_t)(j + 3) * rowstride];
        x0 *= ws[j + 0]; x1 *= ws[j + 1]; x2 *= ws[j + 2]; x3 *= ws[j + 3];
#pragma unroll
        for (int kbo = 0; kbo < 16; kbo++) {
            float a = acc[kbo];
            a += x0 * kbs[kbo * 256 + j + 0];
            a += x1 * kbs[kbo * 256 + j + 1];
            a += x2 * kbs[kbo * 256 + j + 2];
            a += x3 * kbs[kbo * 256 + j + 3];
            acc[kbo] = a;
        }
    }
#pragma unroll
    for (int kbo = 0; kbo < 16; kbo++)
        P[(((size_t)h * 32 + z * 16 + kbo) * 32 + ib) * DH + d] = acc[kbo];
}

// ---------------- sketch stage B (kao-split x2); mode: 0=qfrag,1=kfrag,3=dense -----
__global__ void sketchB_kernel(const float* __restrict__ P, int heads,
                               const float* __restrict__ ka,
                               const float* __restrict__ scale_p,
                               float* __restrict__ dst, int mode) {
    int h = blockIdx.x;
    int kbo = blockIdx.y;
    int zk = blockIdx.z;         // kao half: [zk*10, zk*10+10)
    int d = threadIdx.x;
    __shared__ float kas[10 * 32];
    for (int t = d; t < 10 * 32; t += 128)
        kas[t] = ka[(zk * 10 + t / 32) * DH + (t % 32)];
    __syncthreads();
    float p[32];
#pragma unroll
    for (int i = 0; i < 32; i++) p[i] = P[(((size_t)h * 32 + kbo) * 32 + i) * DH + d];
    float scale = scale_p[0];
    if (mode == 0) scale *= ATT_SCALE;
#pragma unroll
    for (int kao = 0; kao < 10; kao++) {
        float acc = 0.f;
#pragma unroll
        for (int i = 0; i < 32; i++) acc += p[i] * kas[kao * 32 + i];
        int s = TK + kbo * 20 + zk * 10 + kao;
        float val = acc * scale;
        if (mode == 0)      store_qfrag(dst, h, s, d, val);
        else if (mode == 1) store_kfrag(dst, h, s, d, val);
        else                dst[(size_t)(s - TK) * (heads * DH) + h * DH + d] = val;
    }
}

// ---------------- gather + RoPE (q and k only) ----------------
__global__ void gather_rope_kernel(const float* __restrict__ q, const float* __restrict__ k,
                                   const float* __restrict__ cosb, const float* __restrict__ sinb,
                                   const int* __restrict__ topk_list,
                                   float* __restrict__ Qfr, float* __restrict__ Kfr) {
    int j = blockIdx.x;
    int hy = blockIdx.y;   // 0..19
    int d = threadIdx.x;
    int pos = topk_list[j];
    float c = cosb[(size_t)pos * DH + d];
    float s = sinb[(size_t)pos * DH + d];
    if (hy < 16) {
        const float* src = q + ((size_t)pos * NH + hy) * DH;
        float x = src[d];
        float r = (d < 64) ? -src[d + 64] : src[d - 64];
        store_qfrag(Qfr, hy, j, d, (x * c + r * s) * ATT_SCALE);
    } else {
        int h = hy - 16;
        const float* src = k + (size_t)pos * 512 + h * DH;
        float x = src[d];
        float r = (d < 64) ? -src[d + 64] : src[d - 64];
        store_kfrag(Kfr, h, j, d, x * c + r * s);
    }
}

// ---------------- tensor-core flash attention (split-KV, cp.async K/V) -------
#define FA2_SMEM ((16384 + 2*8192 + 2*8192 + 512) * 4)
__global__ void __launch_bounds__(256, 1) fa_mma_kernel(
    const float* __restrict__ Qfr, const float* __restrict__ Kfr,
    const float* __restrict__ Vfr, float* __restrict__ Op,
    float* __restrict__ ML, int kt0)
{
    extern __shared__ float fsm[];
    float* Qsm = fsm;
    float* Ksm = fsm + 16384;
    float* Vsm = fsm + 32768;
    float* mpart = fsm + 49152;
    float* spart = fsm + 49408;

    const int qt = blockIdx.x;
    const int h  = blockIdx.y;
    const int kvh = h >> 2;
    const int tid = threadIdx.x;
    const int lane = tid & 31, wid = tid >> 5;
    const int wm = wid >> 1, wn = wid & 1;
    const int gid = lane >> 2, tig = lane & 3;

    const uint32_t ksmU = (uint32_t)__cvta_generic_to_shared(Ksm) + tid * 16;
    const uint32_t vsmU = (uint32_t)__cvta_generic_to_shared(Vsm) + tid * 16;

    {
        const float4* Kg = reinterpret_cast<const float4*>(Kfr + (size_t)(kvh * NKT + kt0) * 8192);
        const float4* Vg = reinterpret_cast<const float4*>(Vfr + (size_t)(kvh * NKT + kt0) * 8192);
#pragma unroll
        for (int i = 0; i < 8; i++) {
            CP_ASYNC16(ksmU + i * 4096, Kg + tid + i * 256);
            CP_ASYNC16(vsmU + i * 4096, Vg + tid + i * 256);
        }
        CP_COMMIT();
    }

    {
        const float4* Qg = reinterpret_cast<const float4*>(Qfr + (size_t)(h * NQT + qt) * 16384);
        float4* Qs4w = reinterpret_cast<float4*>(Qsm);
#pragma unroll
        for (int i = 0; i < 16; i++) Qs4w[tid + i * 256] = Qg[tid + i * 256];
    }

    float m_old[2][2], l_run[2][2];
#pragma unroll
    for (int a = 0; a < 2; a++)
#pragma unroll
        for (int b = 0; b < 2; b++) { m_old[a][b] = -1e30f; l_run[a][b] = 0.f; }
    float oacc[2][8][4] = {};

    const float4* Qs4 = reinterpret_cast<const float4*>(Qsm);

    for (int t = 0; t < KSPL; t++) {
        const int buf = t & 1;
        if (t + 1 < KSPL) {
            const float4* Kg = reinterpret_cast<const float4*>(Kfr + (size_t)(kvh * NKT + kt0 + t + 1) * 8192);
            const float4* Vg = reinterpret_cast<const float4*>(Vfr + (size_t)(kvh * NKT + kt0 + t + 1) * 8192);
            const uint32_t kd = ksmU + (1 - buf) * 32768;
            const uint32_t vd = vsmU + (1 - buf) * 32768;
#pragma unroll
            for (int i = 0; i < 8; i++) {
                CP_ASYNC16(kd + i * 4096, Kg + tid + i * 256);
                CP_ASYNC16(vd + i * 4096, Vg + tid + i * 256);
            }
            CP_COMMIT();
            asm volatile("cp.async.wait_group 1;");
        } else {
            asm volatile("cp.async.wait_group 0;");
        }
        __syncthreads();

        const float2* Ks2 = reinterpret_cast<const float2*>(Ksm + buf * 8192);
        const float2* Vs2 = reinterpret_cast<const float2*>(Vsm + buf * 8192);
        float* Psm = Ksm + buf * 8192;
        const float4* Ps4 = reinterpret_cast<const float4*>(Psm);

        float sacc[2][4][4] = {};
#pragma unroll
        for (int k8 = 0; k8 < 16; k8++) {
            float4 af[2];
            float2 bf[4];
            af[0] = Qs4[(k8 * 8 + wm * 2 + 0) * 32 + lane];
            af[1] = Qs4[(k8 * 8 + wm * 2 + 1) * 32 + lane];
#pragma unroll
            for (int nf = 0; nf < 4; nf++) bf[nf] = Ks2[(k8 * 8 + wn * 4 + nf) * 32 + lane];
#pragma unroll
            for (int mf = 0; mf < 2; mf++)
#pragma unroll
                for (int nf = 0; nf < 4; nf++)
                    mma_tf32(sacc[mf][nf],
                             reinterpret_cast<const uint32_t*>(&af[mf]),
                             reinterpret_cast<const uint32_t*>(&bf[nf]));
        }

        float mloc[2][2];
#pragma unroll
        for (int mf = 0; mf < 2; mf++) {
            float m0 = fmaxf(sacc[mf][0][0], sacc[mf][0][1]);
            float m1 = fmaxf(sacc[mf][0][2], sacc[mf][0][3]);
#pragma unroll
            for (int nf = 1; nf < 4; nf++) {
                m0 = fmaxf(m0, fmaxf(sacc[mf][nf][0], sacc[mf][nf][1]));
                m1 = fmaxf(m1, fmaxf(sacc[mf][nf][2], sacc[mf][nf][3]));
            }
            m0 = fmaxf(m0, __shfl_xor_sync(0xffffffffu, m0, 1));
            m0 = fmaxf(m0, __shfl_xor_sync(0xffffffffu, m0, 2));
            m1 = fmaxf(m1, __shfl_xor_sync(0xffffffffu, m1, 1));
            m1 = fmaxf(m1, __shfl_xor_sync(0xffffffffu, m1, 2));
            mloc[mf][0] = m0; mloc[mf][1] = m1;
        }
        if (tig == 0) {
#pragma unroll
            for (int mf = 0; mf < 2; mf++) {
                int r = wm * 32 + mf * 16 + gid;
                mpart[wn * 128 + r] = mloc[mf][0];
                mpart[wn * 128 + r + 8] = mloc[mf][1];
            }
        }
        __syncthreads();

        float mnew[2][2], corr[2][2];
#pragma unroll
        for (int mf = 0; mf < 2; mf++)
#pragma unroll
            for (int hi = 0; hi < 2; hi++) {
                int r = wm * 32 + mf * 16 + gid + hi * 8;
                float mt = fmaxf(mpart[r], mpart[128 + r]);
                float mn = fmaxf(m_old[mf][hi], mt);
                corr[mf][hi] = __expf(m_old[mf][hi] - mn);
                mnew[mf][hi] = mn;
                m_old[mf][hi] = mn;
            }

        float sloc[2][2] = {};
#pragma unroll
        for (int mf = 0; mf < 2; mf++)
#pragma unroll
            for (int nf = 0; nf < 4; nf++) {
                sacc[mf][nf][0] = __expf(sacc[mf][nf][0] - mnew[mf][0]);
                sacc[mf][nf][1] = __expf(sacc[mf][nf][1] - mnew[mf][0]);
                sacc[mf][nf][2] = __expf(sacc[mf][nf][2] - mnew[mf][1]);
                sacc[mf][nf][3] = __expf(sacc[mf][nf][3] - mnew[mf][1]);
                sloc[mf][0] += sacc[mf][nf][0] + sacc[mf][nf][1];
                sloc[mf][1] += sacc[mf][nf][2] + sacc[mf][nf][3];
            }
#pragma unroll
        for (int mf = 0; mf < 2; mf++) {
            sloc[mf][0] += __shfl_xor_sync(0xffffffffu, sloc[mf][0], 1);
            sloc[mf][0] += __shfl_xor_sync(0xffffffffu, sloc[mf][0], 2);
            sloc[mf][1] += __shfl_xor_sync(0xffffffffu, sloc[mf][1], 1);
            sloc[mf][1] += __shfl_xor_sync(0xffffffffu, sloc[mf][1], 2);
        }
        if (tig == 0) {
#pragma unroll
            for (int mf = 0; mf < 2; mf++) {
                int r = wm * 32 + mf * 16 + gid;
                spart[wn * 128 + r] = sloc[mf][0];
                spart[wn * 128 + r + 8] = sloc[mf][1];
            }
        }

#pragma unroll
        for (int mf = 0; mf < 2; mf++)
#pragma unroll
            for (int nf = 0; nf < 4; nf++) {
                int k8p = wn * 4 + nf;
                int mfg = wm * 2 + mf;
#pragma unroll
                for (int b = 0; b < 2; b++) {
                    int c = tig * 2 + b;
                    int khi = (c >= 4);
                    int base = ((k8p * 8 + mfg) * 32 + (gid << 2) + (c & 3)) * 4 + khi * 2;
                    *reinterpret_cast<float2*>(Psm + base) =
                        make_float2(tf32f(sacc[mf][nf][b]), tf32f(sacc[mf][nf][2 + b]));
                }
            }
        __syncthreads();

#pragma unroll
        for (int mf = 0; mf < 2; mf++)
#pragma unroll
            for (int hi = 0; hi < 2; hi++) {
                int r = wm * 32 + mf * 16 + gid + hi * 8;
                l_run[mf][hi] = l_run[mf][hi] * corr[mf][hi] + spart[r] + spart[128 + r];
            }
#pragma unroll
        for (int mf = 0; mf < 2; mf++)
#pragma unroll
            for (int nf = 0; nf < 8; nf++) {
                oacc[mf][nf][0] *= corr[mf][0]; oacc[mf][nf][1] *= corr[mf][0];
                oacc[mf][nf][2] *= corr[mf][1]; oacc[mf][nf][3] *= corr[mf][1];
            }

#pragma unroll
        for (int k8 = 0; k8 < 8; k8++) {
            float4 af[2];
            af[0] = Ps4[(k8 * 8 + wm * 2 + 0) * 32 + lane];
            af[1] = Ps4[(k8 * 8 + wm * 2 + 1) * 32 + lane];
#pragma unroll
            for (int nf = 0; nf < 8; nf++) {
                float2 bf = Vs2[(k8 * 16 + wn * 8 + nf) * 32 + lane];
#pragma unroll
                for (int mf = 0; mf < 2; mf++)
                    mma_tf32(oacc[mf][nf],
                             reinterpret_cast<const uint32_t*>(&af[mf]),
                             reinterpret_cast<const uint32_t*>(&bf));
            }
        }
        __syncthreads();
    }

#pragma unroll
    for (int mf = 0; mf < 2; mf++) {
        int r0 = qt * 128 + wm * 32 + mf * 16 + gid;
        if (wn == 0 && tig == 0) {
            size_t row0i = (size_t)r0 * NH + h;
            size_t row1i = (size_t)(r0 + 8) * NH + h;
            ML[row0i * 2] = m_old[mf][0]; ML[row0i * 2 + 1] = l_run[mf][0];
            ML[row1i * 2] = m_old[mf][1]; ML[row1i * 2 + 1] = l_run[mf][1];
        }
#pragma unroll
        for (int nf = 0; nf < 8; nf++) {
            int col = wn * 64 + nf * 8 + tig * 2;
            *reinterpret_cast<float2*>(&Op[((size_t)r0 * NH + h) * DH + col]) =
                make_float2(oacc[mf][nf][0], oacc[mf][nf][1]);
            *reinterpret_cast<float2*>(&Op[((size_t)(r0 + 8) * NH + h) * DH + col]) =
                make_float2(oacc[mf][nf][2], oacc[mf][nf][3]);
        }
    }
}

// ---------------- fa combine ----------------
__global__ void fa_combine_kernel(float* __restrict__ O0, const float* __restrict__ O1,
                                  const float* __restrict__ ML) {
    size_t row = (size_t)blockIdx.x * NH + blockIdx.y;
    int d = threadIdx.x;
    float m0 = ML[row * 2], l0 = ML[row * 2 + 1];
    float m1 = ML[(size_t)NQF * NH * 2 + row * 2], l1 = ML[(size_t)NQF * NH * 2 + row * 2 + 1];
    float m = fmaxf(m0, m1);
    float w0 = __expf(m0 - m), w1 = __expf(m1 - m);
    float inv = 1.0f / (w0 * l0 + w1 * l1);
    O0[row * DH + d] = (O0[row * DH + d] * w0 + O1[row * DH + d] * w1) * inv;
}

// ---------------- expand stage C ----------------
__global__ void expandC_kernel(const float* __restrict__ Z, const float* __restrict__ ka,
                               float* __restrict__ E1) {
    int i = blockIdx.y;
    int hd = blockIdx.x * 256 + threadIdx.x;
    __shared__ float kav[20];
    if (threadIdx.x < 20) kav[threadIdx.x] = ka[threadIdx.x * DH + i];
    __syncthreads();
    for (int kbo = 0; kbo < 32; kbo++) {
        float acc = 0.f;
#pragma unroll
        for (int kao = 0; kao < 20; kao++)
            acc += Z[((size_t)(kbo * 20 + kao)) * HID + hd] * kav[kao];
        E1[((size_t)i * 32 + kbo) * HID + hd] = acc;
    }
}

// ---------------- expand stage D ----------------
__global__ void expandD_kernel(const float* __restrict__ E1, const float* __restrict__ kb,
                               const int* __restrict__ is_topk, float* __restrict__ OUT) {
    int i = blockIdx.y;
    int hd = blockIdx.x * 128 + threadIdx.x;
    __shared__ float kbs[32 * 256];
    for (int t = threadIdx.x; t < 32 * 256; t += 128) kbs[t] = kb[t];
    float e[32];
#pragma unroll
    for (int kbo = 0; kbo < 32; kbo++) e[kbo] = E1[((size_t)i * 32 + kbo) * HID + hd];
    __syncthreads();
    for (int j = 0; j < 256; j++) {
        int row = i * 256 + j;
        if (is_topk[row]) continue;
        float acc = 0.f;
#pragma unroll
        for (int kbo = 0; kbo < 32; kbo++) acc += e[kbo] * kbs[kbo * 256 + j];
        OUT[(size_t)row * HID + hd] = acc;
    }
}

// ---------------- host launcher ----------------
extern "C" void kernel_launch(void* const* d_in, const int* in_sizes, int n_in,
                              void* d_out, int out_size) {
    const float* hs    = (const float*)d_in[0];
    const float* cosb  = (const float*)d_in[1];
    const float* sinb  = (const float*)d_in[2];
    const float* wq    = (const float*)d_in[3];
    const float* wk    = (const float*)d_in[4];
    const float* wv    = (const float*)d_in[5];
    const float* wo    = (const float*)d_in[6];
    const float* qnw   = (const float*)d_in[7];
    const float* knw   = (const float*)d_in[8];
    const float* w1    = (const float*)d_in[9];
    const float* b1    = (const float*)d_in[10];
    const float* w2    = (const float*)d_in[11];
    const float* b2    = (const float*)d_in[12];
    const float* ka    = (const float*)d_in[13];
    const float* kb    = (const float*)d_in[14];
    const float* sscale= (const float*)d_in[15];
    float* out = (float*)d_out;

    float *pT, *pLg, *pW, *pQ, *pK, *pPq, *pPk, *pPh, *pHSr, *pQfr, *pKfr, *pVfr,
          *pAO, *pAO2, *pML, *pE1, *pZ, *pAfr, *pAfr2, *pBfr;
    int *pTop, *pIs;
    cudaGetSymbolAddress((void**)&pT, g_T);
    cudaGetSymbolAddress((void**)&pLg, g_logits);
    cudaGetSymbolAddress((void**)&pW, g_weights);
    cudaGetSymbolAddress((void**)&pQ, g_q);
    cudaGetSymbolAddress((void**)&pK, g_k);
    cudaGetSymbolAddress((void**)&pPq, g_Pq);
    cudaGetSymbolAddress((void**)&pPk, g_Pk);
    cudaGetSymbolAddress((void**)&pPh, g_Ph);
    cudaGetSymbolAddress((void**)&pHSr, g_HSr);
    cudaGetSymbolAddress((void**)&pQfr, g_Qfr);
    cudaGetSymbolAddress((void**)&pKfr, g_Kfr);
    cudaGetSymbolAddress((void**)&pVfr, g_Vfr);
    cudaGetSymbolAddress((void**)&pAO, g_AO);
    cudaGetSymbolAddress((void**)&pAO2, g_AO2);
    cudaGetSymbolAddress((void**)&pML, g_ML);
    cudaGetSymbolAddress((void**)&pE1, g_E1);
    cudaGetSymbolAddress((void**)&pZ, g_Z);
    cudaGetSymbolAddress((void**)&pAfr, g_Afr);
    cudaGetSymbolAddress((void**)&pAfr2, g_Afr2);
    cudaGetSymbolAddress((void**)&pBfr, g_Bfr);
    cudaGetSymbolAddress((void**)&pTop, g_topk);
    cudaGetSymbolAddress((void**)&pIs, g_istop);

    float* pBwk = pBfr + (size_t)16 * 128 * 2048;
    float* pBwv = pBfr + (size_t)20 * 128 * 2048;
    float* pBwo = pBfr + (size_t)24 * 128 * 2048;
    float* pML2 = pML + (size_t)NQF * NH * 2;
    float* pAfr2b = pAfr2 + (size_t)16 * (HID / 16) * 2048;

    cudaFuncSetAttribute(topk_kernel, cudaFuncAttributeMaxDynamicSharedMemorySize, SEQ * 8);
    cudaFuncSetAttribute(fa_mma_kernel, cudaFuncAttributeMaxDynamicSharedMemorySize, FA2_SMEM);

    static cudaStream_t s1 = nullptr;
    static cudaEvent_t evFork = nullptr, evImp = nullptr, evAfr = nullptr,
                       evVf = nullptr, evK = nullptr, evKf = nullptr,
                       evQg = nullptr, evFA1 = nullptr, evAO = nullptr, evExp = nullptr;
    if (s1 == nullptr) {
        cudaStreamCreateWithFlags(&s1, cudaStreamNonBlocking);
        cudaEventCreateWithFlags(&evFork, cudaEventDisableTiming);
        cudaEventCreateWithFlags(&evImp, cudaEventDisableTiming);
        cudaEventCreateWithFlags(&evAfr, cudaEventDisableTiming);
        cudaEventCreateWithFlags(&evVf, cudaEventDisableTiming);
        cudaEventCreateWithFlags(&evK, cudaEventDisableTiming);
        cudaEventCreateWithFlags(&evKf, cudaEventDisableTiming);
        cudaEventCreateWithFlags(&evQg, cudaEventDisableTiming);
        cudaEventCreateWithFlags(&evFA1, cudaEventDisableTiming);
        cudaEventCreateWithFlags(&evAO, cudaEventDisableTiming);
        cudaEventCreateWithFlags(&evExp, cudaEventDisableTiming);
    }

    // ---- fork ----
    cudaEventRecord(evFork, 0);
    cudaStreamWaitEvent(s1, evFork, 0);

    // ---- s1: importance chain ----
    imp_gemm_kernel<<<dim3(1, SEQ / 64, 8), 256, 0, s1>>>(hs, w1, pT);
    imp_logits_kernel<<<SEQ, 32, 0, s1>>>(pT, b1, w2, b2, pLg, pW);
    topk_kernel<<<1, 1024, SEQ * 8, s1>>>(pLg, pTop, pIs);
    cudaEventRecord(evImp, s1);

    // ---- s1: V path ----
    sketchA_kernel<<<dim3(16, 32, 2), DH, 0, s1>>>(hs, 16, 0, pW, pIs, 1, kb, pPh);
    sketchB_kernel<<<dim3(16, 32, 2), DH, 0, s1>>>(pPh, 16, ka, sscale, pHSr, 3);
    convA_kernel<<<dim3(HID / 16, 16), 256, 0, s1>>>(hs, pTop, pAfr2, HID);
    convA_kernel<<<dim3(HID / 16, 5), 256, 0, s1>>>(pHSr, nullptr, pAfr2b, HID);
    convB_kernel<<<dim3(HID / 16, 512 / 128), 256, 0, s1>>>(wv, pBwv, HID, 512, 0);
    mma_gemm_kernel<<<dim3(512 / 128, NQF / 128), 256, 0, s1>>>(
        pAfr2, pBwv, pVfr, nullptr, nullptr, 0, pVfr, 512, HID);
    cudaEventRecord(evVf, s1);

    // ---- default: Q projection chain ----
    convA_kernel<<<dim3(HID / 16, SEQ / 128), 256>>>(hs, nullptr, pAfr, HID);
    cudaEventRecord(evAfr, 0);
    convB_kernel<<<dim3(HID / 16, HID / 128), 256>>>(wq, pBfr, HID, HID, 0);
    mma_gemm_kernel<<<dim3(HID / 128, SEQ / 128), 256>>>(pAfr, pBfr, pQ, nullptr, qnw, 16, nullptr, HID, HID);

    // ---- s1: K projection + k-sketch ----
    convB_kernel<<<dim3(HID / 16, 512 / 128), 256, 0, s1>>>(wk, pBwk, HID, 512, 0);
    cudaStreamWaitEvent(s1, evAfr, 0);
    mma_gemm_kernel<<<dim3(512 / 128, SEQ / 128), 256, 0, s1>>>(
        pAfr, pBwk, pK, nullptr, knw, 4, nullptr, 512, HID);
    cudaEventRecord(evK, s1);
    sketchA_kernel<<<dim3(NKV, 32, 2), DH, 0, s1>>>(pK, 4, 0, pW, pIs, 1, kb, pPk);
    sketchB_kernel<<<dim3(NKV, 32, 2), DH, 0, s1>>>(pPk, NKV, ka, sscale, pKfr, 1);
    cudaEventRecord(evKf, s1);
    convB_kernel<<<dim3(HID / 16, HID / 128), 256, 0, s1>>>(wo, pBwo, HID, HID, 0);

    // ---- default: q sketch + gather ----
    cudaStreamWaitEvent(0, evImp, 0);
    sketchA_kernel<<<dim3(NH, 32, 2), DH>>>(pQ, 16, 0, pW, pIs, 0, kb, pPq);
    sketchB_kernel<<<dim3(NH, 32, 2), DH>>>(pPq, NH, ka, sscale, pQfr, 0);
    cudaStreamWaitEvent(0, evK, 0);
    gather_rope_kernel<<<dim3(TK, 20), DH>>>(pQ, pK, cosb, sinb, pTop, pQfr, pKfr);
    cudaEventRecord(evQg, 0);

    // ---- attention: split-KV x2 + combine ----
    cudaStreamWaitEvent(0, evKf, 0);
    cudaStreamWaitEvent(0, evVf, 0);
    cudaStreamWaitEvent(s1, evQg, 0);
    fa_mma_kernel<<<dim3(NQT, NH), 256, FA2_SMEM>>>(pQfr, pKfr, pVfr, pAO, pML, 0);
    fa_mma_kernel<<<dim3(NQT, NH), 256, FA2_SMEM, s1>>>(pQfr, pKfr, pVfr, pAO2, pML2, KSPL);
    cudaEventRecord(evFA1, s1);
    cudaStreamWaitEvent(0, evFA1, 0);
    fa_combine_kernel<<<dim3(NQF, NH), DH>>>(pAO, pAO2, pML);

    // ---- epilogue ----
    convA_kernel<<<dim3(HID / 16, NQF / 128), 256>>>(pAO, nullptr, pAfr, HID);
    cudaEventRecord(evAO, 0);
    cudaStreamWaitEvent(s1, evAO, 0);
    mma_gemm_kernel<<<dim3(HID / 128, SK / 128), 256, 0, s1>>>(
        pAfr + (size_t)16 * (HID / 16) * 2048, pBwo, pZ, nullptr, nullptr, 0, nullptr, HID, HID);
    expandC_kernel<<<dim3(HID / 256, 32), 256, 0, s1>>>(pZ, ka, pE1);
    expandD_kernel<<<dim3(HID / 128, 32), DH, 0, s1>>>(pE1, kb, pIs, out);
    cudaEventRecord(evExp, s1);
    mma_gemm_kernel<<<dim3(HID / 128, TK / 128), 256>>>(pAfr, pBwo, out, pTop, nullptr, 0, nullptr, HID, HID);

    // ---- join ----
    cudaStreamWaitEvent(0, evExp, 0);
}

// round 15
// speedup vs baseline: 1.0299x; 1.0003x over previous
#include <cuda_runtime.h>
#include <cuda_bf16.h>
#include <math.h>
#include <cstdint>

// Problem constants
#define SEQ   8192
#define HID   2048
#define NH    16
#define NKV   4
#define DH    128
#define TK    2048
#define SK    640
#define NQF   (TK + SK)        // 2688
#define NQT   (NQF / 128)      // 21 q tiles
#define NKT   (NQF / 64)       // 42 key tiles
#define KSPL  21               // key tiles per split (2 splits)
#define ATT_SCALE 0.08838834764831843f   // 1/sqrt(128)

// ---------------- scratch (device globals; no allocation) ----------------
__device__ float g_T[8 * SEQ * 64];
__device__ float g_logits[SEQ];
__device__ float g_weights[SEQ];
__device__ float g_q[SEQ * NH * DH];       // normalized q
__device__ float g_k[SEQ * 512];           // normalized k (4 heads x 128)
__device__ int   g_topk[TK];
__device__ int   g_istop[SEQ];
__device__ float g_Pq[NH * 32 * 32 * DH];  // q-sketch stage-A scratch
__device__ float g_Pk[NKV * 32 * 32 * DH]; // k-sketch stage-A scratch
__device__ float g_Ph[16 * 32 * 32 * DH];  // hs-sketch stage-A scratch
__device__ float g_HSr[SK * HID];          // rest-weighted hs sketch rows
__device__ float g_Qfr[NH * NQT * 16 * 8 * 32 * 4];
__device__ float g_Kfr[NKV * NKT * 16 * 8 * 32 * 2];
__device__ float g_Vfr[NKV * NKT * 8 * 16 * 32 * 2];
__device__ float g_AO[NQF * NH * DH];      // split-0 partial, then combined AO
__device__ float g_AO2[NQF * NH * DH];     // split-1 partial
__device__ float g_ML[2 * NQF * NH * 2];
__device__ float g_E1[32 * 32 * HID];
__device__ float g_Z[SK * HID];
__device__ float g_Afr[SEQ * HID];         // A fragments (hs, later AO)
__device__ float g_Afr2[NQF * HID];        // A fragments for V GEMM (topk hs | HSr)
__device__ float g_Bfr[40 * 128 * 2048];   // wq[0:16) | wk[16:20) | wv[20:24) | wo[24:40)

// ======================= tf32 mma.sync helpers =======================
__device__ __forceinline__ float tf32f(float x) {
    uint32_t r; asm("cvt.rna.tf32.f32 %0, %1;" : "=r"(r) : "f"(x));
    return __uint_as_float(r);
}

__device__ __forceinline__ void mma_tf32(float* c, const uint32_t* a, const uint32_t* b) {
    asm volatile("mma.sync.aligned.m16n8k8.row.col.f32.tf32.tf32.f32 "
        "{%0,%1,%2,%3}, {%4,%5,%6,%7}, {%8,%9}, {%0,%1,%2,%3};"
        : "+f"(c[0]), "+f"(c[1]), "+f"(c[2]), "+f"(c[3])
        : "r"(a[0]), "r"(a[1]), "r"(a[2]), "r"(a[3]), "r"(b[0]), "r"(b[1]));
}

#define CP_ASYNC16(dst_u32, src_ptr) \
    asm volatile("cp.async.cg.shared.global [%0], [%1], 16;" :: "r"(dst_u32), "l"(src_ptr))
#define CP_COMMIT() asm volatile("cp.async.commit_group;")

__device__ __forceinline__ void store_qfrag(float* Qg, int h, int tok, int d, float v) {
    int qt = tok >> 7, m = tok & 127;
    int k8 = d >> 3, mf = m >> 4;
    int lane = ((m & 7) << 2) | (d & 3);
    int reg = 2 * ((d & 7) >= 4) + ((m & 15) >= 8);
    size_t idx = ((((size_t)(h * NQT + qt) * 16 + k8) * 8 + mf) * 32 + lane) * 4 + reg;
    Qg[idx] = tf32f(v);
}
__device__ __forceinline__ void store_kfrag(float* Kg, int kvh, int tok, int d, float v) {
    int kt = tok >> 6, key = tok & 63;
    int k8 = d >> 3, nf = key >> 3;
    int lane = ((key & 7) << 2) | (d & 3);
    int reg = ((d & 7) >= 4);
    size_t idx = ((((size_t)(kvh * NKT + kt) * 16 + k8) * 8 + nf) * 32 + lane) * 2 + reg;
    Kg[idx] = tf32f(v);
}
__device__ __forceinline__ void store_vfrag(float* Vg, int kvh, int tok, int d, float v) {
    int kt = tok >> 6, key = tok & 63;
    int k8 = key >> 3, nf = d >> 3;
    int lane = ((d & 7) << 2) | (key & 3);
    int reg = ((key & 7) >= 4);
    size_t idx = ((((size_t)(kvh * NKT + kt) * 8 + k8) * 16 + nf) * 32 + lane) * 2 + reg;
    Vg[idx] = tf32f(v);
}

// ======================= fragment conversion pre-passes =======================
__global__ void __launch_bounds__(256) convA_kernel(const float* __restrict__ A,
                                                    const int* __restrict__ remap,
                                                    float* __restrict__ Afr, int K) {
    __shared__ float sm[2048];
    const int rt = blockIdx.y, c = blockIdx.x;
    const int tid = threadIdx.x;
#pragma unroll
    for (int i = 0; i < 2; i++) {
        int f = tid + i * 256;
        int r = f >> 2, c4 = f & 3;
        int act = remap ? __ldg(&remap[rt * 128 + r]) : (rt * 128 + r);
        float4 v = *reinterpret_cast<const float4*>(A + (size_t)act * K + c * 16 + c4 * 4);
        int mf = r >> 4, gid = r & 7, mhi = (r >> 3) & 1;
        float vv[4] = {v.x, v.y, v.z, v.w};
#pragma unroll
        for (int j = 0; j < 4; j++) {
            int k = c4 * 4 + j;
            int slot = ((k >> 3) * 8 + mf) * 128 + ((gid << 2) | (k & 3)) * 4
                     + 2 * ((k & 7) >= 4) + mhi;
            sm[slot] = tf32f(vv[j]);
        }
    }
    __syncthreads();
    float4* out = reinterpret_cast<float4*>(Afr + ((size_t)(rt * (K >> 4) + c)) * 2048);
    const float4* s4 = reinterpret_cast<const float4*>(sm);
#pragma unroll
    for (int i = 0; i < 2; i++) out[tid + i * 256] = s4[tid + i * 256];
}

__global__ void __launch_bounds__(256) convB_kernel(const float* __restrict__ B,
                                                    float* __restrict__ Bfr, int K, int N,
                                                    int ctbase) {
    __shared__ float sm[2048];
    const int ct = blockIdx.y + ctbase, c = blockIdx.x;
    const int tid = threadIdx.x;
    const float* Bb = B + ((size_t)(c * 16)) * N + blockIdx.y * 128;
#pragma unroll
    for (int i = 0; i < 2; i++) {
        int f = tid + i * 256;
        int kk = f >> 5, n4 = f & 31;
        float4 v = *reinterpret_cast<const float4*>(Bb + (size_t)kk * N + n4 * 4);
        int k8in = kk >> 3, reg = ((kk & 7) >= 4);
        float vv[4] = {v.x, v.y, v.z, v.w};
#pragma unroll
        for (int j = 0; j < 4; j++) {
            int n = n4 * 4 + j;
            int slot = (k8in * 16 + (n >> 3)) * 64 + (((n & 7) << 2) | (kk & 3)) * 2 + reg;
            sm[slot] = tf32f(vv[j]);
        }
    }
    __syncthreads();
    float4* out = reinterpret_cast<float4*>(Bfr + ((size_t)(ct * (K >> 4) + c)) * 2048);
    const float4* s4 = reinterpret_cast<const float4*>(sm);
#pragma unroll
    for (int i = 0; i < 2; i++) out[tid + i * 256] = s4[tid + i * 256];
}

// ======= tf32 GEMM: 128x128, cp.async 3-stage, 2 CTA/SM; optional rmsnorm / remap /
//         vfrag-epilogue ===
__global__ void __launch_bounds__(256, 2) mma_gemm_kernel(
    const float* __restrict__ Afr, const float* __restrict__ Bfr,
    float* __restrict__ C, const int* __restrict__ remap,
    const float* __restrict__ normw, int normct, float* __restrict__ vfr,
    int N, int K)
{
    __shared__ float sA[3][2048];
    __shared__ float sB[3][2048];

    const int tid = threadIdx.x;
    const int lane = tid & 31, wid = tid >> 5;
    const int wm = wid >> 2, wn = wid & 3;
    const int NCH = K >> 4;

    const float4* Ag = reinterpret_cast<const float4*>(Afr) + (size_t)blockIdx.y * NCH * 512;
    const float4* Bg = reinterpret_cast<const float4*>(Bfr) + (size_t)blockIdx.x * NCH * 512;

    const uint32_t sAu = (uint32_t)__cvta_generic_to_shared(&sA[0][0]) + tid * 16;
    const uint32_t sBu = (uint32_t)__cvta_generic_to_shared(&sB[0][0]) + tid * 16;

    {
        const float4* ga = Ag + tid;  const float4* gb = Bg + tid;
        CP_ASYNC16(sAu, ga); CP_ASYNC16(sAu + 4096, ga + 256);
        CP_ASYNC16(sBu, gb); CP_ASYNC16(sBu + 4096, gb + 256);
        CP_COMMIT();
        if (NCH > 1) {
            ga += 512; gb += 512;
            CP_ASYNC16(sAu + 8192, ga); CP_ASYNC16(sAu + 8192 + 4096, ga + 256);
            CP_ASYNC16(sBu + 8192, gb); CP_ASYNC16(sBu + 8192 + 4096, gb + 256);
            CP_COMMIT();
        }
    }

    float acc[4][4][4] = {};
    for (int c = 0; c < NCH; c++) {
        if (c + 1 < NCH) asm volatile("cp.async.wait_group 1;");
        else             asm volatile("cp.async.wait_group 0;");
        __syncthreads();

        const int buf = c % 3;
        const float4* A4 = reinterpret_cast<const float4*>(sA[buf]);
        const float2* B2 = reinterpret_cast<const float2*>(sB[buf]);
#pragma unroll
        for (int k8 = 0; k8 < 2; k8++) {
            float4 af[4];
            float2 bf[4];
#pragma unroll
            for (int mf = 0; mf < 4; mf++)
                af[mf] = A4[(k8 * 8 + wm * 4 + mf) * 32 + lane];
#pragma unroll
            for (int nf = 0; nf < 4; nf++)
                bf[nf] = B2[(k8 * 16 + wn * 4 + nf) * 32 + lane];
#pragma unroll
            for (int mf = 0; mf < 4; mf++)
#pragma unroll
                for (int nf = 0; nf < 4; nf++)
                    mma_tf32(acc[mf][nf],
                             reinterpret_cast<const uint32_t*>(&af[mf]),
                             reinterpret_cast<const uint32_t*>(&bf[nf]));
        }
        if (c + 2 < NCH) {
            const int st = (c + 2) % 3;
            const float4* ga = Ag + (c + 2) * 512 + tid;
            const float4* gb = Bg + (c + 2) * 512 + tid;
            CP_ASYNC16(sAu + st * 8192, ga); CP_ASYNC16(sAu + st * 8192 + 4096, ga + 256);
            CP_ASYNC16(sBu + st * 8192, gb); CP_ASYNC16(sBu + st * 8192 + 4096, gb + 256);
            CP_COMMIT();
        }
    }

    const int gid = lane >> 2, tig = lane & 3;
    const int row0 = blockIdx.y * 128;
    const int col0 = blockIdx.x * 128;

    if (vfr != nullptr) {
#pragma unroll
        for (int mf = 0; mf < 4; mf++) {
            int m = row0 + wm * 64 + mf * 16 + gid;
#pragma unroll
            for (int nf = 0; nf < 4; nf++) {
                int n = col0 + wn * 32 + nf * 8 + tig * 2;
                store_vfrag(vfr, n >> 7, m, n & 127, acc[mf][nf][0]);
                store_vfrag(vfr, (n + 1) >> 7, m, (n + 1) & 127, acc[mf][nf][1]);
                store_vfrag(vfr, n >> 7, m + 8, n & 127, acc[mf][nf][2]);
                store_vfrag(vfr, (n + 1) >> 7, m + 8, (n + 1) & 127, acc[mf][nf][3]);
            }
        }
        return;
    }

    if (normw != nullptr && blockIdx.x < normct) {
        float* ssm = &sA[0][0];
        __syncthreads();
        float ss0[4], ss1[4];
#pragma unroll
        for (int mf = 0; mf < 4; mf++) {
            float s0 = 0.f, s1 = 0.f;
#pragma unroll
            for (int nf = 0; nf < 4; nf++) {
                s0 += acc[mf][nf][0] * acc[mf][nf][0] + acc[mf][nf][1] * acc[mf][nf][1];
                s1 += acc[mf][nf][2] * acc[mf][nf][2] + acc[mf][nf][3] * acc[mf][nf][3];
            }
            s0 += __shfl_xor_sync(0xffffffffu, s0, 1);
            s0 += __shfl_xor_sync(0xffffffffu, s0, 2);
            s1 += __shfl_xor_sync(0xffffffffu, s1, 1);
            s1 += __shfl_xor_sync(0xffffffffu, s1, 2);
            ss0[mf] = s0; ss1[mf] = s1;
        }
        if (tig == 0) {
#pragma unroll
            for (int mf = 0; mf < 4; mf++) {
                int r = wm * 64 + mf * 16 + gid;
                ssm[r * 4 + wn] = ss0[mf];
                ssm[(r + 8) * 4 + wn] = ss1[mf];
            }
        }
        __syncthreads();
#pragma unroll
        for (int mf = 0; mf < 4; mf++) {
            int r = wm * 64 + mf * 16 + gid;
            float t0 = ssm[r * 4] + ssm[r * 4 + 1] + ssm[r * 4 + 2] + ssm[r * 4 + 3];
            float t1 = ssm[(r + 8) * 4] + ssm[(r + 8) * 4 + 1]
                     + ssm[(r + 8) * 4 + 2] + ssm[(r + 8) * 4 + 3];
            float sc0 = rsqrtf(t0 * (1.0f / 128.0f) + 1e-6f);
            float sc1 = rsqrtf(t1 * (1.0f / 128.0f) + 1e-6f);
#pragma unroll
            for (int nf = 0; nf < 4; nf++) {
                int n = wn * 32 + nf * 8 + tig * 2;
                float w0 = __ldg(&normw[n]), w1 = __ldg(&normw[n + 1]);
                acc[mf][nf][0] *= sc0 * w0; acc[mf][nf][1] *= sc0 * w1;
                acc[mf][nf][2] *= sc1 * w0; acc[mf][nf][3] *= sc1 * w1;
            }
        }
    }

#pragma unroll
    for (int mf = 0; mf < 4; mf++) {
        int m = row0 + wm * 64 + mf * 16 + gid;
        int m1 = remap ? __ldg(&remap[m]) : m;
        int m2 = remap ? __ldg(&remap[m + 8]) : (m + 8);
#pragma unroll
        for (int nf = 0; nf < 4; nf++) {
            int n = col0 + wn * 32 + nf * 8 + tig * 2;
            *reinterpret_cast<float2*>(&C[(size_t)m1 * N + n]) =
                make_float2(acc[mf][nf][0], acc[mf][nf][1]);
            *reinterpret_cast<float2*>(&C[(size_t)m2 * N + n]) =
                make_float2(acc[mf][nf][2], acc[mf][nf][3]);
        }
    }
}

// ---------------- importance GEMM: fp32 split-K x8 ----------------
__global__ void __launch_bounds__(256) imp_gemm_kernel(
    const float* __restrict__ A, const float* __restrict__ B, float* __restrict__ Cp)
{
    __shared__ float As[16][64];
    __shared__ float Bs[16][64];
    const int tid = threadIdx.x;
    const int row0 = blockIdx.y * 64;
    const int z = blockIdx.z;
    const float* Ab = A + (size_t)row0 * HID + z * 256;
    const float* Bb = B + (size_t)z * 256 * 64;
    float acc[4][4] = {};
    const int tc = (tid & 15) * 4, tr = (tid >> 4) * 4;
    const int ar = tid >> 2, ac = (tid & 3) * 4;
    const int br = tid >> 4, bc = (tid & 15) * 4;

    for (int k0 = 0; k0 < 256; k0 += 16) {
        float4 va = *reinterpret_cast<const float4*>(Ab + (size_t)ar * HID + k0 + ac);
        As[ac + 0][ar] = va.x; As[ac + 1][ar] = va.y;
        As[ac + 2][ar] = va.z; As[ac + 3][ar] = va.w;
        float4 vb = *reinterpret_cast<const float4*>(Bb + (size_t)(k0 + br) * 64 + bc);
        *reinterpret_cast<float4*>(&Bs[br][bc]) = vb;
        __syncthreads();
#pragma unroll
        for (int k = 0; k < 16; k++) {
            float ra[4], rb[4];
#pragma unroll
            for (int m = 0; m < 4; m++) ra[m] = As[k][tr + m];
#pragma unroll
            for (int n = 0; n < 4; n++) rb[n] = Bs[k][tc + n];
#pragma unroll
            for (int m = 0; m < 4; m++)
#pragma unroll
                for (int n = 0; n < 4; n++) acc[m][n] += ra[m] * rb[n];
        }
        __syncthreads();
    }
#pragma unroll
    for (int m = 0; m < 4; m++) {
        float4 v = make_float4(acc[m][0], acc[m][1], acc[m][2], acc[m][3]);
        *reinterpret_cast<float4*>(&Cp[((size_t)z * SEQ + row0 + tr + m) * 64 + tc]) = v;
    }
}

// ---------------- importance logits epilogue ----------------
__global__ void imp_logits_kernel(const float* __restrict__ T, const float* __restrict__ b1,
                                  const float* __restrict__ w2, const float* __restrict__ b2,
                                  float* __restrict__ logits, float* __restrict__ weights) {
    const float LOG_ADJ = 2.5494451709255714f;
    int s = blockIdx.x;
    int j = threadIdx.x;
    float v1 = 0.f, v2 = 0.f;
#pragma unroll
    for (int z = 0; z < 8; z++) {
        v1 += T[((size_t)z * SEQ + s) * 64 + j];
        v2 += T[((size_t)z * SEQ + s) * 64 + j + 32];
    }
    float v = tanhf(v1 + b1[j]) * w2[j] + tanhf(v2 + b1[j + 32]) * w2[j + 32];
#pragma unroll
    for (int o = 16; o > 0; o >>= 1) v += __shfl_xor_sync(0xffffffffu, v, o);
    if (j == 0) {
        float lg = v + b2[0] - LOG_ADJ;
        logits[s] = lg;
        weights[s] = 1.0f / (1.0f + expf(-lg));
    }
}

// ---------------- top-k via single-block bitonic sort ----------------
__global__ void topk_kernel(const float* __restrict__ logits,
                            int* __restrict__ topk_list, int* __restrict__ is_topk) {
    extern __shared__ unsigned long long skeys[];
    int tid = threadIdx.x;
    for (int i = tid; i < SEQ; i += 1024) {
        unsigned u = __float_as_uint(logits[i]);
        u = (u & 0x80000000u) ? ~u : (u | 0x80000000u);
        skeys[i] = ((unsigned long long)(~u) << 32) | (unsigned)i;
        is_topk[i] = 0;
    }
    __syncthreads();
    for (int k = 2; k <= SEQ; k <<= 1) {
        for (int j = k >> 1; j > 0; j >>= 1) {
            for (int i = tid; i < SEQ; i += 1024) {
                int ixj = i ^ j;
                if (ixj > i) {
                    bool up = ((i & k) == 0);
                    unsigned long long a = skeys[i], b = skeys[ixj];
                    if ((a > b) == up) { skeys[i] = b; skeys[ixj] = a; }
                }
            }
            __syncthreads();
        }
    }
    for (int i = tid; i < TK; i += 1024) {
        int pos = (int)(skeys[i] & 0xffffffffu);
        topk_list[i] = pos;
        is_topk[pos] = 1;
    }
}

// ---------------- sketch stage A (kbo-split x2, j-unrolled x8 for MLP) ----------------
__global__ void sketchA_kernel(const float* __restrict__ X, int hstride, int hbase,
                               const float* __restrict__ weights,
                               const int* __restrict__ is_topk, int rest,
                               const float* __restrict__ kb, float* __restrict__ P) {
    int h = blockIdx.x;
    int ib = blockIdx.y;
    int z = blockIdx.z;          // kbo half: [z*16, z*16+16)
    int d = threadIdx.x;
    __shared__ float kbs[16 * 256];
    for (int t = d; t < 16 * 256; t += 128) kbs[t] = kb[z * 16 * 256 + t];
    __shared__ float ws[256];
    for (int j = d; j < 256; j += 128) {
        int t = ib * 256 + j;
        float w = weights[t];
        if (rest && is_topk[t]) w = 0.0f;
        ws[j] = w;
    }
    __syncthreads();
    float acc[16] = {};
    const size_t rowstride = (size_t)hstride * DH;
    const float* Xb = X + ((size_t)(ib * 256) * hstride + hbase + h) * DH + d;
    for (int j = 0; j < 256; j += 8) {
        // front-batch 8 independent global loads (MLP=8)
        float x0 = Xb[(size_t)(j + 0) * rowstride];
        float x1 = Xb[(size_t)(j + 1) * rowstride];
        float x2 = Xb[(size_t)(j + 2) * rowstride];
        float x3 = Xb[(size_t)(j + 3) * rowstride];
        float x4 = Xb[(size_t)(j + 4) * rowstride];
        float x5 = Xb[(size_t)(j + 5) * rowstride];
        float x6 = Xb[(size_t)(j + 6) * rowstride];
        float x7 = Xb[(size_t)(j + 7) * rowstride];
        x0 *= ws[j + 0]; x1 *= ws[j + 1]; x2 *= ws[j + 2]; x3 *= ws[j + 3];
        x4 *= ws[j + 4]; x5 *= ws[j + 5]; x6 *= ws[j + 6]; x7 *= ws[j + 7];
#pragma unroll
        for (int kbo = 0; kbo < 16; kbo++) {
            float a = acc[kbo];
            a += x0 * kbs[kbo * 256 + j + 0];
            a += x1 * kbs[kbo * 256 + j + 1];
            a += x2 * kbs[kbo * 256 + j + 2];
            a += x3 * kbs[kbo * 256 + j + 3];
            a += x4 * kbs[kbo * 256 + j + 4];
            a += x5 * kbs[kbo * 256 + j + 5];
            a += x6 * kbs[kbo * 256 + j + 6];
            a += x7 * kbs[kbo * 256 + j + 7];
            acc[kbo] = a;
        }
    }
#pragma unroll
    for (int kbo = 0; kbo < 16; kbo++)
        P[(((size_t)h * 32 + z * 16 + kbo) * 32 + ib) * DH + d] = acc[kbo];
}

// ---------------- sketch stage B (kao-split x2); mode: 0=qfrag,1=kfrag,3=dense -----
__global__ void sketchB_kernel(const float* __restrict__ P, int heads,
                               const float* __restrict__ ka,
                               const float* __restrict__ scale_p,
                               float* __restrict__ dst, int mode) {
    int h = blockIdx.x;
    int kbo = blockIdx.y;
    int zk = blockIdx.z;         // kao half: [zk*10, zk*10+10)
    int d = threadIdx.x;
    __shared__ float kas[10 * 32];
    for (int t = d; t < 10 * 32; t += 128)
        kas[t] = ka[(zk * 10 + t / 32) * DH + (t % 32)];
    __syncthreads();
    float p[32];
#pragma unroll
    for (int i = 0; i < 32; i++) p[i] = P[(((size_t)h * 32 + kbo) * 32 + i) * DH + d];
    float scale = scale_p[0];
    if (mode == 0) scale *= ATT_SCALE;
#pragma unroll
    for (int kao = 0; kao < 10; kao++) {
        float acc = 0.f;
#pragma unroll
        for (int i = 0; i < 32; i++) acc += p[i] * kas[kao * 32 + i];
        int s = TK + kbo * 20 + zk * 10 + kao;
        float val = acc * scale;
        if (mode == 0)      store_qfrag(dst, h, s, d, val);
        else if (mode == 1) store_kfrag(dst, h, s, d, val);
        else                dst[(size_t)(s - TK) * (heads * DH) + h * DH + d] = val;
    }
}

// ---------------- gather + RoPE (q and k only) ----------------
__global__ void gather_rope_kernel(const float* __restrict__ q, const float* __restrict__ k,
                                   const float* __restrict__ cosb, const float* __restrict__ sinb,
                                   const int* __restrict__ topk_list,
                                   float* __restrict__ Qfr, float* __restrict__ Kfr) {
    int j = blockIdx.x;
    int hy = blockIdx.y;   // 0..19
    int d = threadIdx.x;
    int pos = topk_list[j];
    float c = cosb[(size_t)pos * DH + d];
    float s = sinb[(size_t)pos * DH + d];
    if (hy < 16) {
        const float* src = q + ((size_t)pos * NH + hy) * DH;
        float x = src[d];
        float r = (d < 64) ? -src[d + 64] : src[d - 64];
        store_qfrag(Qfr, hy, j, d, (x * c + r * s) * ATT_SCALE);
    } else {
        int h = hy - 16;
        const float* src = k + (size_t)pos * 512 + h * DH;
        float x = src[d];
        float r = (d < 64) ? -src[d + 64] : src[d - 64];
        store_kfrag(Kfr, h, j, d, x * c + r * s);
    }
}

// ---------------- tensor-core flash attention (split-KV, cp.async K/V) -------
#define FA2_SMEM ((16384 + 2*8192 + 2*8192 + 512) * 4)
__global__ void __launch_bounds__(256, 1) fa_mma_kernel(
    const float* __restrict__ Qfr, const float* __restrict__ Kfr,
    const float* __restrict__ Vfr, float* __restrict__ Op,
    float* __restrict__ ML, int kt0)
{
    extern __shared__ float fsm[];
    float* Qsm = fsm;
    float* Ksm = fsm + 16384;
    float* Vsm = fsm + 32768;
    float* mpart = fsm + 49152;
    float* spart = fsm + 49408;

    const int qt = blockIdx.x;
    const int h  = blockIdx.y;
    const int kvh = h >> 2;
    const int tid = threadIdx.x;
    const int lane = tid & 31, wid = tid >> 5;
    const int wm = wid >> 1, wn = wid & 1;
    const int gid = lane >> 2, tig = lane & 3;

    const uint32_t ksmU = (uint32_t)__cvta_generic_to_shared(Ksm) + tid * 16;
    const uint32_t vsmU = (uint32_t)__cvta_generic_to_shared(Vsm) + tid * 16;

    {
        const float4* Kg = reinterpret_cast<const float4*>(Kfr + (size_t)(kvh * NKT + kt0) * 8192);
        const float4* Vg = reinterpret_cast<const float4*>(Vfr + (size_t)(kvh * NKT + kt0) * 8192);
#pragma unroll
        for (int i = 0; i < 8; i++) {
            CP_ASYNC16(ksmU + i * 4096, Kg + tid + i * 256);
            CP_ASYNC16(vsmU + i * 4096, Vg + tid + i * 256);
        }
        CP_COMMIT();
    }

    {
        const float4* Qg = reinterpret_cast<const float4*>(Qfr + (size_t)(h * NQT + qt) * 16384);
        float4* Qs4w = reinterpret_cast<float4*>(Qsm);
#pragma unroll
        for (int i = 0; i < 16; i++) Qs4w[tid + i * 256] = Qg[tid + i * 256];
    }

    float m_old[2][2], l_run[2][2];
#pragma unroll
    for (int a = 0; a < 2; a++)
#pragma unroll
        for (int b = 0; b < 2; b++) { m_old[a][b] = -1e30f; l_run[a][b] = 0.f; }
    float oacc[2][8][4] = {};

    const float4* Qs4 = reinterpret_cast<const float4*>(Qsm);

    for (int t = 0; t < KSPL; t++) {
        const int buf = t & 1;
        if (t + 1 < KSPL) {
            const float4* Kg = reinterpret_cast<const float4*>(Kfr + (size_t)(kvh * NKT + kt0 + t + 1) * 8192);
            const float4* Vg = reinterpret_cast<const float4*>(Vfr + (size_t)(kvh * NKT + kt0 + t + 1) * 8192);
            const uint32_t kd = ksmU + (1 - buf) * 32768;
            const uint32_t vd = vsmU + (1 - buf) * 32768;
#pragma unroll
            for (int i = 0; i < 8; i++) {
                CP_ASYNC16(kd + i * 4096, Kg + tid + i * 256);
                CP_ASYNC16(vd + i * 4096, Vg + tid + i * 256);
            }
            CP_COMMIT();
            asm volatile("cp.async.wait_group 1;");
        } else {
            asm volatile("cp.async.wait_group 0;");
        }
        __syncthreads();

        const float2* Ks2 = reinterpret_cast<const float2*>(Ksm + buf * 8192);
        const float2* Vs2 = reinterpret_cast<const float2*>(Vsm + buf * 8192);
        float* Psm = Ksm + buf * 8192;
        const float4* Ps4 = reinterpret_cast<const float4*>(Psm);

        float sacc[2][4][4] = {};
#pragma unroll
        for (int k8 = 0; k8 < 16; k8++) {
            float4 af[2];
            float2 bf[4];
            af[0] = Qs4[(k8 * 8 + wm * 2 + 0) * 32 + lane];
            af[1] = Qs4[(k8 * 8 + wm * 2 + 1) * 32 + lane];
#pragma unroll
            for (int nf = 0; nf < 4; nf++) bf[nf] = Ks2[(k8 * 8 + wn * 4 + nf) * 32 + lane];
#pragma unroll
            for (int mf = 0; mf < 2; mf++)
#pragma unroll
                for (int nf = 0; nf < 4; nf++)
                    mma_tf32(sacc[mf][nf],
                             reinterpret_cast<const uint32_t*>(&af[mf]),
                             reinterpret_cast<const uint32_t*>(&bf[nf]));
        }

        float mloc[2][2];
#pragma unroll
        for (int mf = 0; mf < 2; mf++) {
            float m0 = fmaxf(sacc[mf][0][0], sacc[mf][0][1]);
            float m1 = fmaxf(sacc[mf][0][2], sacc[mf][0][3]);
#pragma unroll
            for (int nf = 1; nf < 4; nf++) {
                m0 = fmaxf(m0, fmaxf(sacc[mf][nf][0], sacc[mf][nf][1]));
                m1 = fmaxf(m1, fmaxf(sacc[mf][nf][2], sacc[mf][nf][3]));
            }
            m0 = fmaxf(m0, __shfl_xor_sync(0xffffffffu, m0, 1));
            m0 = fmaxf(m0, __shfl_xor_sync(0xffffffffu, m0, 2));
            m1 = fmaxf(m1, __shfl_xor_sync(0xffffffffu, m1, 1));
            m1 = fmaxf(m1, __shfl_xor_sync(0xffffffffu, m1, 2));
            mloc[mf][0] = m0; mloc[mf][1] = m1;
        }
        if (tig == 0) {
#pragma unroll
            for (int mf = 0; mf < 2; mf++) {
                int r = wm * 32 + mf * 16 + gid;
                mpart[wn * 128 + r] = mloc[mf][0];
                mpart[wn * 128 + r + 8] = mloc[mf][1];
            }
        }
        __syncthreads();

        float mnew[2][2], corr[2][2];
#pragma unroll
        for (int mf = 0; mf < 2; mf++)
#pragma unroll
            for (int hi = 0; hi < 2; hi++) {
                int r = wm * 32 + mf * 16 + gid + hi * 8;
                float mt = fmaxf(mpart[r], mpart[128 + r]);
                float mn = fmaxf(m_old[mf][hi], mt);
                corr[mf][hi] = __expf(m_old[mf][hi] - mn);
                mnew[mf][hi] = mn;
                m_old[mf][hi] = mn;
            }

        float sloc[2][2] = {};
#pragma unroll
        for (int mf = 0; mf < 2; mf++)
#pragma unroll
            for (int nf = 0; nf < 4; nf++) {
                sacc[mf][nf][0] = __expf(sacc[mf][nf][0] - mnew[mf][0]);
                sacc[mf][nf][1] = __expf(sacc[mf][nf][1] - mnew[mf][0]);
                sacc[mf][nf][2] = __expf(sacc[mf][nf][2] - mnew[mf][1]);
                sacc[mf][nf][3] = __expf(sacc[mf][nf][3] - mnew[mf][1]);
                sloc[mf][0] += sacc[mf][nf][0] + sacc[mf][nf][1];
                sloc[mf][1] += sacc[mf][nf][2] + sacc[mf][nf][3];
            }
#pragma unroll
        for (int mf = 0; mf < 2; mf++) {
            sloc[mf][0] += __shfl_xor_sync(0xffffffffu, sloc[mf][0], 1);
            sloc[mf][0] += __shfl_xor_sync(0xffffffffu, sloc[mf][0], 2);
            sloc[mf][1] += __shfl_xor_sync(0xffffffffu, sloc[mf][1], 1);
            sloc[mf][1] += __shfl_xor_sync(0xffffffffu, sloc[mf][1], 2);
        }
        if (tig == 0) {
#pragma unroll
            for (int mf = 0; mf < 2; mf++) {
                int r = wm * 32 + mf * 16 + gid;
                spart[wn * 128 + r] = sloc[mf][0];
                spart[wn * 128 + r + 8] = sloc[mf][1];
            }
        }

#pragma unroll
        for (int mf = 0; mf < 2; mf++)
#pragma unroll
            for (int nf = 0; nf < 4; nf++) {
                int k8p = wn * 4 + nf;
                int mfg = wm * 2 + mf;
#pragma unroll
                for (int b = 0; b < 2; b++) {
                    int c = tig * 2 + b;
                    int khi = (c >= 4);
                    int base = ((k8p * 8 + mfg) * 32 + (gid << 2) + (c & 3)) * 4 + khi * 2;
                    *reinterpret_cast<float2*>(Psm + base) =
                        make_float2(tf32f(sacc[mf][nf][b]), tf32f(sacc[mf][nf][2 + b]));
                }
            }
        __syncthreads();

#pragma unroll
        for (int mf = 0; mf < 2; mf++)
#pragma unroll
            for (int hi = 0; hi < 2; hi++) {
                int r = wm * 32 + mf * 16 + gid + hi * 8;
                l_run[mf][hi] = l_run[mf][hi] * corr[mf][hi] + spart[r] + spart[128 + r];
            }
#pragma unroll
        for (int mf = 0; mf < 2; mf++)
#pragma unroll
            for (int nf = 0; nf < 8; nf++) {
                oacc[mf][nf][0] *= corr[mf][0]; oacc[mf][nf][1] *= corr[mf][0];
                oacc[mf][nf][2] *= corr[mf][1]; oacc[mf][nf][3] *= corr[mf][1];
            }

#pragma unroll
        for (int k8 = 0; k8 < 8; k8++) {
            float4 af[2];
            af[0] = Ps4[(k8 * 8 + wm * 2 + 0) * 32 + lane];
            af[1] = Ps4[(k8 * 8 + wm * 2 + 1) * 32 + lane];
#pragma unroll
            for (int nf = 0; nf < 8; nf++) {
                float2 bf = Vs2[(k8 * 16 + wn * 8 + nf) * 32 + lane];
#pragma unroll
                for (int mf = 0; mf < 2; mf++)
                    mma_tf32(oacc[mf][nf],
                             reinterpret_cast<const uint32_t*>(&af[mf]),
                             reinterpret_cast<const uint32_t*>(&bf));
            }
        }
        __syncthreads();
    }

#pragma unroll
    for (int mf = 0; mf < 2; mf++) {
        int r0 = qt * 128 + wm * 32 + mf * 16 + gid;
        if (wn == 0 && tig == 0) {
            size_t row0i = (size_t)r0 * NH + h;
            size_t row1i = (size_t)(r0 + 8) * NH + h;
            ML[row0i * 2] = m_old[mf][0]; ML[row0i * 2 + 1] = l_run[mf][0];
            ML[row1i * 2] = m_old[mf][1]; ML[row1i * 2 + 1] = l_run[mf][1];
        }
#pragma unroll
        for (int nf = 0; nf < 8; nf++) {
            int col = wn * 64 + nf * 8 + tig * 2;
            *reinterpret_cast<float2*>(&Op[((size_t)r0 * NH + h) * DH + col]) =
                make_float2(oacc[mf][nf][0], oacc[mf][nf][1]);
            *reinterpret_cast<float2*>(&Op[((size_t)(r0 + 8) * NH + h) * DH + col]) =
                make_float2(oacc[mf][nf][2], oacc[mf][nf][3]);
        }
    }
}

// ---------------- fa combine ----------------
__global__ void fa_combine_kernel(float* __restrict__ O0, const float* __restrict__ O1,
                                  const float* __restrict__ ML) {
    size_t row = (size_t)blockIdx.x * NH + blockIdx.y;
    int d = threadIdx.x;
    float m0 = ML[row * 2], l0 = ML[row * 2 + 1];
    float m1 = ML[(size_t)NQF * NH * 2 + row * 2], l1 = ML[(size_t)NQF * NH * 2 + row * 2 + 1];
    float m = fmaxf(m0, m1);
    float w0 = __expf(m0 - m), w1 = __expf(m1 - m);
    float inv = 1.0f / (w0 * l0 + w1 * l1);
    O0[row * DH + d] = (O0[row * DH + d] * w0 + O1[row * DH + d] * w1) * inv;
}

// ---------------- expand stage C ----------------
__global__ void expandC_kernel(const float* __restrict__ Z, const float* __restrict__ ka,
                               float* __restrict__ E1) {
    int i = blockIdx.y;
    int hd = blockIdx.x * 256 + threadIdx.x;
    __shared__ float kav[20];
    if (threadIdx.x < 20) kav[threadIdx.x] = ka[threadIdx.x * DH + i];
    __syncthreads();
    for (int kbo = 0; kbo < 32; kbo++) {
        float acc = 0.f;
#pragma unroll
        for (int kao = 0; kao < 20; kao++)
            acc += Z[((size_t)(kbo * 20 + kao)) * HID + hd] * kav[kao];
        E1[((size_t)i * 32 + kbo) * HID + hd] = acc;
    }
}

// ---------------- expand stage D ----------------
__global__ void expandD_kernel(const float* __restrict__ E1, const float* __restrict__ kb,
                               const int* __restrict__ is_topk, float* __restrict__ OUT) {
    int i = blockIdx.y;
    int hd = blockIdx.x * 128 + threadIdx.x;
    __shared__ float kbs[32 * 256];
    for (int t = threadIdx.x; t < 32 * 256; t += 128) kbs[t] = kb[t];
    float e[32];
#pragma unroll
    for (int kbo = 0; kbo < 32; kbo++) e[kbo] = E1[((size_t)i * 32 + kbo) * HID + hd];
    __syncthreads();
    for (int j = 0; j < 256; j++) {
        int row = i * 256 + j;
        if (is_topk[row]) continue;
        float acc = 0.f;
#pragma unroll
        for (int kbo = 0; kbo < 32; kbo++) acc += e[kbo] * kbs[kbo * 256 + j];
        OUT[(size_t)row * HID + hd] = acc;
    }
}

// ---------------- host launcher ----------------
extern "C" void kernel_launch(void* const* d_in, const int* in_sizes, int n_in,
                              void* d_out, int out_size) {
    const float* hs    = (const float*)d_in[0];
    const float* cosb  = (const float*)d_in[1];
    const float* sinb  = (const float*)d_in[2];
    const float* wq    = (const float*)d_in[3];
    const float* wk    = (const float*)d_in[4];
    const float* wv    = (const float*)d_in[5];
    const float* wo    = (const float*)d_in[6];
    const float* qnw   = (const float*)d_in[7];
    const float* knw   = (const float*)d_in[8];
    const float* w1    = (const float*)d_in[9];
    const float* b1    = (const float*)d_in[10];
    const float* w2    = (const float*)d_in[11];
    const float* b2    = (const float*)d_in[12];
    const float* ka    = (const float*)d_in[13];
    const float* kb    = (const float*)d_in[14];
    const float* sscale= (const float*)d_in[15];
    float* out = (float*)d_out;

    float *pT, *pLg, *pW, *pQ, *pK, *pPq, *pPk, *pPh, *pHSr, *pQfr, *pKfr, *pVfr,
          *pAO, *pAO2, *pML, *pE1, *pZ, *pAfr, *pAfr2, *pBfr;
    int *pTop, *pIs;
    cudaGetSymbolAddress((void**)&pT, g_T);
    cudaGetSymbolAddress((void**)&pLg, g_logits);
    cudaGetSymbolAddress((void**)&pW, g_weights);
    cudaGetSymbolAddress((void**)&pQ, g_q);
    cudaGetSymbolAddress((void**)&pK, g_k);
    cudaGetSymbolAddress((void**)&pPq, g_Pq);
    cudaGetSymbolAddress((void**)&pPk, g_Pk);
    cudaGetSymbolAddress((void**)&pPh, g_Ph);
    cudaGetSymbolAddress((void**)&pHSr, g_HSr);
    cudaGetSymbolAddress((void**)&pQfr, g_Qfr);
    cudaGetSymbolAddress((void**)&pKfr, g_Kfr);
    cudaGetSymbolAddress((void**)&pVfr, g_Vfr);
    cudaGetSymbolAddress((void**)&pAO, g_AO);
    cudaGetSymbolAddress((void**)&pAO2, g_AO2);
    cudaGetSymbolAddress((void**)&pML, g_ML);
    cudaGetSymbolAddress((void**)&pE1, g_E1);
    cudaGetSymbolAddress((void**)&pZ, g_Z);
    cudaGetSymbolAddress((void**)&pAfr, g_Afr);
    cudaGetSymbolAddress((void**)&pAfr2, g_Afr2);
    cudaGetSymbolAddress((void**)&pBfr, g_Bfr);
    cudaGetSymbolAddress((void**)&pTop, g_topk);
    cudaGetSymbolAddress((void**)&pIs, g_istop);

    float* pBwk = pBfr + (size_t)16 * 128 * 2048;
    float* pBwv = pBfr + (size_t)20 * 128 * 2048;
    float* pBwo = pBfr + (size_t)24 * 128 * 2048;
    float* pML2 = pML + (size_t)NQF * NH * 2;
    float* pAfr2b = pAfr2 + (size_t)16 * (HID / 16) * 2048;

    cudaFuncSetAttribute(topk_kernel, cudaFuncAttributeMaxDynamicSharedMemorySize, SEQ * 8);
    cudaFuncSetAttribute(fa_mma_kernel, cudaFuncAttributeMaxDynamicSharedMemorySize, FA2_SMEM);

    static cudaStream_t s1 = nullptr;
    static cudaEvent_t evFork = nullptr, evImp = nullptr, evAfr = nullptr,
                       evVf = nullptr, evK = nullptr, evKf = nullptr,
                       evQg = nullptr, evFA1 = nullptr, evAO = nullptr, evExp = nullptr;
    if (s1 == nullptr) {
        cudaStreamCreateWithFlags(&s1, cudaStreamNonBlocking);
        cudaEventCreateWithFlags(&evFork, cudaEventDisableTiming);
        cudaEventCreateWithFlags(&evImp, cudaEventDisableTiming);
        cudaEventCreateWithFlags(&evAfr, cudaEventDisableTiming);
        cudaEventCreateWithFlags(&evVf, cudaEventDisableTiming);
        cudaEventCreateWithFlags(&evK, cudaEventDisableTiming);
        cudaEventCreateWithFlags(&evKf, cudaEventDisableTiming);
        cudaEventCreateWithFlags(&evQg, cudaEventDisableTiming);
        cudaEventCreateWithFlags(&evFA1, cudaEventDisableTiming);
        cudaEventCreateWithFlags(&evAO, cudaEventDisableTiming);
        cudaEventCreateWithFlags(&evExp, cudaEventDisableTiming);
    }

    // ---- fork ----
    cudaEventRecord(evFork, 0);
    cudaStreamWaitEvent(s1, evFork, 0);

    // ---- s1: importance chain ----
    imp_gemm_kernel<<<dim3(1, SEQ / 64, 8), 256, 0, s1>>>(hs, w1, pT);
    imp_logits_kernel<<<SEQ, 32, 0, s1>>>(pT, b1, w2, b2, pLg, pW);
    topk_kernel<<<1, 1024, SEQ * 8, s1>>>(pLg, pTop, pIs);
    cudaEventRecord(evImp, s1);

    // ---- s1: V path ----
    sketchA_kernel<<<dim3(16, 32, 2), DH, 0, s1>>>(hs, 16, 0, pW, pIs, 1, kb, pPh);
    sketchB_kernel<<<dim3(16, 32, 2), DH, 0, s1>>>(pPh, 16, ka, sscale, pHSr, 3);
    convA_kernel<<<dim3(HID / 16, 16), 256, 0, s1>>>(hs, pTop, pAfr2, HID);
    convA_kernel<<<dim3(HID / 16, 5), 256, 0, s1>>>(pHSr, nullptr, pAfr2b, HID);
    convB_kernel<<<dim3(HID / 16, 512 / 128), 256, 0, s1>>>(wv, pBwv, HID, 512, 0);
    mma_gemm_kernel<<<dim3(512 / 128, NQF / 128), 256, 0, s1>>>(
        pAfr2, pBwv, pVfr, nullptr, nullptr, 0, pVfr, 512, HID);
    cudaEventRecord(evVf, s1);

    // ---- default: Q projection chain ----
    convA_kernel<<<dim3(HID / 16, SEQ / 128), 256>>>(hs, nullptr, pAfr, HID);
    cudaEventRecord(evAfr, 0);
    convB_kernel<<<dim3(HID / 16, HID / 128), 256>>>(wq, pBfr, HID, HID, 0);
    mma_gemm_kernel<<<dim3(HID / 128, SEQ / 128), 256>>>(pAfr, pBfr, pQ, nullptr, qnw, 16, nullptr, HID, HID);

    // ---- s1: K projection + k-sketch ----
    convB_kernel<<<dim3(HID / 16, 512 / 128), 256, 0, s1>>>(wk, pBwk, HID, 512, 0);
    cudaStreamWaitEvent(s1, evAfr, 0);
    mma_gemm_kernel<<<dim3(512 / 128, SEQ / 128), 256, 0, s1>>>(
        pAfr, pBwk, pK, nullptr, knw, 4, nullptr, 512, HID);
    cudaEventRecord(evK, s1);
    sketchA_kernel<<<dim3(NKV, 32, 2), DH, 0, s1>>>(pK, 4, 0, pW, pIs, 1, kb, pPk);
    sketchB_kernel<<<dim3(NKV, 32, 2), DH, 0, s1>>>(pPk, NKV, ka, sscale, pKfr, 1);
    cudaEventRecord(evKf, s1);
    convB_kernel<<<dim3(HID / 16, HID / 128), 256, 0, s1>>>(wo, pBwo, HID, HID, 0);

    // ---- default: q sketch + gather ----
    cudaStreamWaitEvent(0, evImp, 0);
    sketchA_kernel<<<dim3(NH, 32, 2), DH>>>(pQ, 16, 0, pW, pIs, 0, kb, pPq);
    sketchB_kernel<<<dim3(NH, 32, 2), DH>>>(pPq, NH, ka, sscale, pQfr, 0);
    cudaStreamWaitEvent(0, evK, 0);
    gather_rope_kernel<<<dim3(TK, 20), DH>>>(pQ, pK, cosb, sinb, pTop, pQfr, pKfr);
    cudaEventRecord(evQg, 0);

    // ---- attention: split-KV x2 + combine ----
    cudaStreamWaitEvent(0, evKf, 0);
    cudaStreamWaitEvent(0, evVf, 0);
    cudaStreamWaitEvent(s1, evQg, 0);
    fa_mma_kernel<<<dim3(NQT, NH), 256, FA2_SMEM>>>(pQfr, pKfr, pVfr, pAO, pML, 0);
    fa_mma_kernel<<<dim3(NQT, NH), 256, FA2_SMEM, s1>>>(pQfr, pKfr, pVfr, pAO2, pML2, KSPL);
    cudaEventRecord(evFA1, s1);
    cudaStreamWaitEvent(0, evFA1, 0);
    fa_combine_kernel<<<dim3(NQF, NH), DH>>>(pAO, pAO2, pML);

    // ---- epilogue ----
    convA_kernel<<<dim3(HID / 16, NQF / 128), 256>>>(pAO, nullptr, pAfr, HID);
    cudaEventRecord(evAO, 0);
    cudaStreamWaitEvent(s1, evAO, 0);
    mma_gemm_kernel<<<dim3(HID / 128, SK / 128), 256, 0, s1>>>(
        pAfr + (size_t)16 * (HID / 16) * 2048, pBwo, pZ, nullptr, nullptr, 0, nullptr, HID, HID);
    expandC_kernel<<<dim3(HID / 256, 32), 256, 0, s1>>>(pZ, ka, pE1);
    expandD_kernel<<<dim3(HID / 128, 32), DH, 0, s1>>>(pE1, kb, pIs, out);
    cudaEventRecord(evExp, s1);
    mma_gemm_kernel<<<dim3(HID / 128, TK / 128), 256>>>(pAfr, pBwo, out, pTop, nullptr, 0, nullptr, HID, HID);

    // ---- join ----
    cudaStreamWaitEvent(0, evExp, 0);
}

// round 16
// speedup vs baseline: 1.0964x; 1.0645x over previous
#include <cuda_runtime.h>
#include <cuda_bf16.h>
#include <math.h>
#include <cstdint>

// Problem constants
#define SEQ   8192
#define HID   2048
#define NH    16
#define NKV   4
#define DH    128
#define TK    2048
#define SK    640
#define NQF   (TK + SK)        // 2688
#define NQT   (NQF / 128)      // 21 q tiles
#define NKT   (NQF / 64)       // 42 key tiles
#define KSPL  21               // key tiles per split (2 splits)
#define ATT_SCALE 0.08838834764831843f   // 1/sqrt(128)

// ---------------- scratch (device globals; no allocation) ----------------
__device__ float g_T[8 * SEQ * 64];
__device__ float g_logits[SEQ];
__device__ float g_weights[SEQ];
__device__ float g_q[SEQ * NH * DH];       // normalized q
__device__ float g_k[SEQ * 512];           // normalized k (4 heads x 128)
__device__ int   g_topk[TK];
__device__ int   g_istop[SEQ];
__device__ float g_Pq[NH * 32 * 32 * DH];  // q-sketch stage-A scratch
__device__ float g_Pk[NKV * 32 * 32 * DH]; // k-sketch stage-A scratch
__device__ float g_Ph[16 * 32 * 32 * DH];  // hs-sketch stage-A scratch
__device__ float g_HSr[SK * HID];          // rest-weighted hs sketch rows
__device__ float g_Qfr[NH * NQT * 16 * 8 * 32 * 4];
__device__ float g_Kfr[NKV * NKT * 16 * 8 * 32 * 2];
__device__ float g_Vfr[NKV * NKT * 8 * 16 * 32 * 2];
__device__ float g_AO[NQF * NH * DH];      // split-0 partial, then combined AO
__device__ float g_AO2[NQF * NH * DH];     // split-1 partial
__device__ float g_ML[2 * NQF * NH * 2];
__device__ float g_E1[32 * 32 * HID];
__device__ float g_Z[SK * HID];
__device__ float g_Afr[SEQ * HID];         // A fragments (hs, later AO)
__device__ float g_Afr2[NQF * HID];        // A fragments for V GEMM (topk hs | HSr)
__device__ float g_Bfr[40 * 128 * 2048];   // wq[0:16) | wk[16:20) | wv[20:24) | wo[24:40)

// ======================= tf32 mma.sync helpers =======================
__device__ __forceinline__ float tf32f(float x) {
    uint32_t r; asm("cvt.rna.tf32.f32 %0, %1;" : "=r"(r) : "f"(x));
    return __uint_as_float(r);
}

__device__ __forceinline__ void mma_tf32(float* c, const uint32_t* a, const uint32_t* b) {
    asm volatile("mma.sync.aligned.m16n8k8.row.col.f32.tf32.tf32.f32 "
        "{%0,%1,%2,%3}, {%4,%5,%6,%7}, {%8,%9}, {%0,%1,%2,%3};"
        : "+f"(c[0]), "+f"(c[1]), "+f"(c[2]), "+f"(c[3])
        : "r"(a[0]), "r"(a[1]), "r"(a[2]), "r"(a[3]), "r"(b[0]), "r"(b[1]));
}

#define CP_ASYNC16(dst_u32, src_ptr) \
    asm volatile("cp.async.cg.shared.global [%0], [%1], 16;" :: "r"(dst_u32), "l"(src_ptr))
#define CP_COMMIT() asm volatile("cp.async.commit_group;")

__device__ __forceinline__ void store_qfrag(float* Qg, int h, int tok, int d, float v) {
    int qt = tok >> 7, m = tok & 127;
    int k8 = d >> 3, mf = m >> 4;
    int lane = ((m & 7) << 2) | (d & 3);
    int reg = 2 * ((d & 7) >= 4) + ((m & 15) >= 8);
    size_t idx = ((((size_t)(h * NQT + qt) * 16 + k8) * 8 + mf) * 32 + lane) * 4 + reg;
    Qg[idx] = tf32f(v);
}
__device__ __forceinline__ void store_kfrag(float* Kg, int kvh, int tok, int d, float v) {
    int kt = tok >> 6, key = tok & 63;
    int k8 = d >> 3, nf = key >> 3;
    int lane = ((key & 7) << 2) | (d & 3);
    int reg = ((d & 7) >= 4);
    size_t idx = ((((size_t)(kvh * NKT + kt) * 16 + k8) * 8 + nf) * 32 + lane) * 2 + reg;
    Kg[idx] = tf32f(v);
}
__device__ __forceinline__ void store_vfrag(float* Vg, int kvh, int tok, int d, float v) {
    int kt = tok >> 6, key = tok & 63;
    int k8 = key >> 3, nf = d >> 3;
    int lane = ((d & 7) << 2) | (key & 3);
    int reg = ((key & 7) >= 4);
    size_t idx = ((((size_t)(kvh * NKT + kt) * 8 + k8) * 16 + nf) * 32 + lane) * 2 + reg;
    Vg[idx] = tf32f(v);
}

// ======================= fragment conversion pre-passes =======================
__global__ void __launch_bounds__(256) convA_kernel(const float* __restrict__ A,
                                                    const int* __restrict__ remap,
                                                    float* __restrict__ Afr, int K) {
    __shared__ float sm[2048];
    const int rt = blockIdx.y, c = blockIdx.x;
    const int tid = threadIdx.x;
#pragma unroll
    for (int i = 0; i < 2; i++) {
        int f = tid + i * 256;
        int r = f >> 2, c4 = f & 3;
        int act = remap ? __ldg(&remap[rt * 128 + r]) : (rt * 128 + r);
        float4 v = *reinterpret_cast<const float4*>(A + (size_t)act * K + c * 16 + c4 * 4);
        int mf = r >> 4, gid = r & 7, mhi = (r >> 3) & 1;
        float vv[4] = {v.x, v.y, v.z, v.w};
#pragma unroll
        for (int j = 0; j < 4; j++) {
            int k = c4 * 4 + j;
            int slot = ((k >> 3) * 8 + mf) * 128 + ((gid << 2) | (k & 3)) * 4
                     + 2 * ((k & 7) >= 4) + mhi;
            sm[slot] = tf32f(vv[j]);
        }
    }
    __syncthreads();
    float4* out = reinterpret_cast<float4*>(Afr + ((size_t)(rt * (K >> 4) + c)) * 2048);
    const float4* s4 = reinterpret_cast<const float4*>(sm);
#pragma unroll
    for (int i = 0; i < 2; i++) out[tid + i * 256] = s4[tid + i * 256];
}

__global__ void __launch_bounds__(256) convB_kernel(const float* __restrict__ B,
                                                    float* __restrict__ Bfr, int K, int N,
                                                    int ctbase) {
    __shared__ float sm[2048];
    const int ct = blockIdx.y + ctbase, c = blockIdx.x;
    const int tid = threadIdx.x;
    const float* Bb = B + ((size_t)(c * 16)) * N + blockIdx.y * 128;
#pragma unroll
    for (int i = 0; i < 2; i++) {
        int f = tid + i * 256;
        int kk = f >> 5, n4 = f & 31;
        float4 v = *reinterpret_cast<const float4*>(Bb + (size_t)kk * N + n4 * 4);
        int k8in = kk >> 3, reg = ((kk & 7) >= 4);
        float vv[4] = {v.x, v.y, v.z, v.w};
#pragma unroll
        for (int j = 0; j < 4; j++) {
            int n = n4 * 4 + j;
            int slot = (k8in * 16 + (n >> 3)) * 64 + (((n & 7) << 2) | (kk & 3)) * 2 + reg;
            sm[slot] = tf32f(vv[j]);
        }
    }
    __syncthreads();
    float4* out = reinterpret_cast<float4*>(Bfr + ((size_t)(ct * (K >> 4) + c)) * 2048);
    const float4* s4 = reinterpret_cast<const float4*>(sm);
#pragma unroll
    for (int i = 0; i < 2; i++) out[tid + i * 256] = s4[tid + i * 256];
}

// ======= tf32 GEMM: 128x128 CTA, 4 warps @ 64x64 warp tiles, cp.async 3-stage,
//         2 CTA/SM; optional rmsnorm / remap / vfrag-epilogue ===
__global__ void __launch_bounds__(128, 2) mma_gemm_kernel(
    const float* __restrict__ Afr, const float* __restrict__ Bfr,
    float* __restrict__ C, const int* __restrict__ remap,
    const float* __restrict__ normw, int normct, float* __restrict__ vfr,
    int N, int K)
{
    __shared__ float sA[3][2048];
    __shared__ float sB[3][2048];

    const int tid = threadIdx.x;
    const int lane = tid & 31, wid = tid >> 5;
    const int wm = wid >> 1, wn = wid & 1;       // 2x2 warp grid, 64x64 tiles
    const int NCH = K >> 4;

    const float4* Ag = reinterpret_cast<const float4*>(Afr) + (size_t)blockIdx.y * NCH * 512;
    const float4* Bg = reinterpret_cast<const float4*>(Bfr) + (size_t)blockIdx.x * NCH * 512;

    const uint32_t sAu = (uint32_t)__cvta_generic_to_shared(&sA[0][0]) + tid * 16;
    const uint32_t sBu = (uint32_t)__cvta_generic_to_shared(&sB[0][0]) + tid * 16;

    // prologue: stage chunks 0 and 1 (512 float4 per side, 4 per thread)
    {
#pragma unroll
        for (int i = 0; i < 4; i++) {
            CP_ASYNC16(sAu + i * 2048, Ag + tid + i * 128);
            CP_ASYNC16(sBu + i * 2048, Bg + tid + i * 128);
        }
        CP_COMMIT();
        if (NCH > 1) {
#pragma unroll
            for (int i = 0; i < 4; i++) {
                CP_ASYNC16(sAu + 8192 + i * 2048, Ag + 512 + tid + i * 128);
                CP_ASYNC16(sBu + 8192 + i * 2048, Bg + 512 + tid + i * 128);
            }
            CP_COMMIT();
        }
    }

    float acc[4][8][4] = {};
    for (int c = 0; c < NCH; c++) {
        if (c + 1 < NCH) asm volatile("cp.async.wait_group 1;");
        else             asm volatile("cp.async.wait_group 0;");
        __syncthreads();

        const int buf = c % 3;
        const float4* A4 = reinterpret_cast<const float4*>(sA[buf]);
        const float2* B2 = reinterpret_cast<const float2*>(sB[buf]);
#pragma unroll
        for (int k8 = 0; k8 < 2; k8++) {
            float4 af[4];
            float2 bf[8];
#pragma unroll
            for (int mf = 0; mf < 4; mf++)
                af[mf] = A4[(k8 * 8 + wm * 4 + mf) * 32 + lane];
#pragma unroll
            for (int nf = 0; nf < 8; nf++)
                bf[nf] = B2[(k8 * 16 + wn * 8 + nf) * 32 + lane];
#pragma unroll
            for (int mf = 0; mf < 4; mf++)
#pragma unroll
                for (int nf = 0; nf < 8; nf++)
                    mma_tf32(acc[mf][nf],
                             reinterpret_cast<const uint32_t*>(&af[mf]),
                             reinterpret_cast<const uint32_t*>(&bf[nf]));
        }
        if (c + 2 < NCH) {
            const int st = (c + 2) % 3;
            const float4* ga = Ag + (c + 2) * 512 + tid;
            const float4* gb = Bg + (c + 2) * 512 + tid;
#pragma unroll
            for (int i = 0; i < 4; i++) {
                CP_ASYNC16(sAu + st * 8192 + i * 2048, ga + i * 128);
                CP_ASYNC16(sBu + st * 8192 + i * 2048, gb + i * 128);
            }
            CP_COMMIT();
        }
    }

    const int gid = lane >> 2, tig = lane & 3;
    const int row0 = blockIdx.y * 128;
    const int col0 = blockIdx.x * 128;

    // ---- vfrag epilogue ----
    if (vfr != nullptr) {
#pragma unroll
        for (int mf = 0; mf < 4; mf++) {
            int m = row0 + wm * 64 + mf * 16 + gid;
#pragma unroll
            for (int nf = 0; nf < 8; nf++) {
                int n = col0 + wn * 64 + nf * 8 + tig * 2;
                store_vfrag(vfr, n >> 7, m, n & 127, acc[mf][nf][0]);
                store_vfrag(vfr, (n + 1) >> 7, m, (n + 1) & 127, acc[mf][nf][1]);
                store_vfrag(vfr, n >> 7, m + 8, n & 127, acc[mf][nf][2]);
                store_vfrag(vfr, (n + 1) >> 7, m + 8, (n + 1) & 127, acc[mf][nf][3]);
            }
        }
        return;
    }

    // ---- optional fused rmsnorm over each 128-col (one-head) tile ----
    if (normw != nullptr && blockIdx.x < normct) {
        float* ssm = &sA[0][0];    // 128 rows x 2 wn-partials
        __syncthreads();
        float ss0[4], ss1[4];
#pragma unroll
        for (int mf = 0; mf < 4; mf++) {
            float s0 = 0.f, s1 = 0.f;
#pragma unroll
            for (int nf = 0; nf < 8; nf++) {
                s0 += acc[mf][nf][0] * acc[mf][nf][0] + acc[mf][nf][1] * acc[mf][nf][1];
                s1 += acc[mf][nf][2] * acc[mf][nf][2] + acc[mf][nf][3] * acc[mf][nf][3];
            }
            s0 += __shfl_xor_sync(0xffffffffu, s0, 1);
            s0 += __shfl_xor_sync(0xffffffffu, s0, 2);
            s1 += __shfl_xor_sync(0xffffffffu, s1, 1);
            s1 += __shfl_xor_sync(0xffffffffu, s1, 2);
            ss0[mf] = s0; ss1[mf] = s1;
        }
        if (tig == 0) {
#pragma unroll
            for (int mf = 0; mf < 4; mf++) {
                int r = wm * 64 + mf * 16 + gid;
                ssm[r * 2 + wn] = ss0[mf];
                ssm[(r + 8) * 2 + wn] = ss1[mf];
            }
        }
        __syncthreads();
#pragma unroll
        for (int mf = 0; mf < 4; mf++) {
            int r = wm * 64 + mf * 16 + gid;
            float t0 = ssm[r * 2] + ssm[r * 2 + 1];
            float t1 = ssm[(r + 8) * 2] + ssm[(r + 8) * 2 + 1];
            float sc0 = rsqrtf(t0 * (1.0f / 128.0f) + 1e-6f);
            float sc1 = rsqrtf(t1 * (1.0f / 128.0f) + 1e-6f);
#pragma unroll
            for (int nf = 0; nf < 8; nf++) {
                int n = wn * 64 + nf * 8 + tig * 2;
                float w0 = __ldg(&normw[n]), w1 = __ldg(&normw[n + 1]);
                acc[mf][nf][0] *= sc0 * w0; acc[mf][nf][1] *= sc0 * w1;
                acc[mf][nf][2] *= sc1 * w0; acc[mf][nf][3] *= sc1 * w1;
            }
        }
    }

#pragma unroll
    for (int mf = 0; mf < 4; mf++) {
        int m = row0 + wm * 64 + mf * 16 + gid;
        int m1 = remap ? __ldg(&remap[m]) : m;
        int m2 = remap ? __ldg(&remap[m + 8]) : (m + 8);
#pragma unroll
        for (int nf = 0; nf < 8; nf++) {
            int n = col0 + wn * 64 + nf * 8 + tig * 2;
            *reinterpret_cast<float2*>(&C[(size_t)m1 * N + n]) =
                make_float2(acc[mf][nf][0], acc[mf][nf][1]);
            *reinterpret_cast<float2*>(&C[(size_t)m2 * N + n]) =
                make_float2(acc[mf][nf][2], acc[mf][nf][3]);
        }
    }
}

// ---------------- importance GEMM: fp32 split-K x8 ----------------
__global__ void __launch_bounds__(256) imp_gemm_kernel(
    const float* __restrict__ A, const float* __restrict__ B, float* __restrict__ Cp)
{
    __shared__ float As[16][64];
    __shared__ float Bs[16][64];
    const int tid = threadIdx.x;
    const int row0 = blockIdx.y * 64;
    const int z = blockIdx.z;
    const float* Ab = A + (size_t)row0 * HID + z * 256;
    const float* Bb = B + (size_t)z * 256 * 64;
    float acc[4][4] = {};
    const int tc = (tid & 15) * 4, tr = (tid >> 4) * 4;
    const int ar = tid >> 2, ac = (tid & 3) * 4;
    const int br = tid >> 4, bc = (tid & 15) * 4;

    for (int k0 = 0; k0 < 256; k0 += 16) {
        float4 va = *reinterpret_cast<const float4*>(Ab + (size_t)ar * HID + k0 + ac);
        As[ac + 0][ar] = va.x; As[ac + 1][ar] = va.y;
        As[ac + 2][ar] = va.z; As[ac + 3][ar] = va.w;
        float4 vb = *reinterpret_cast<const float4*>(Bb + (size_t)(k0 + br) * 64 + bc);
        *reinterpret_cast<float4*>(&Bs[br][bc]) = vb;
        __syncthreads();
#pragma unroll
        for (int k = 0; k < 16; k++) {
            float ra[4], rb[4];
#pragma unroll
            for (int m = 0; m < 4; m++) ra[m] = As[k][tr + m];
#pragma unroll
            for (int n = 0; n < 4; n++) rb[n] = Bs[k][tc + n];
#pragma unroll
            for (int m = 0; m < 4; m++)
#pragma unroll
                for (int n = 0; n < 4; n++) acc[m][n] += ra[m] * rb[n];
        }
        __syncthreads();
    }
#pragma unroll
    for (int m = 0; m < 4; m++) {
        float4 v = make_float4(acc[m][0], acc[m][1], acc[m][2], acc[m][3]);
        *reinterpret_cast<float4*>(&Cp[((size_t)z * SEQ + row0 + tr + m) * 64 + tc]) = v;
    }
}

// ---------------- importance logits epilogue ----------------
__global__ void imp_logits_kernel(const float* __restrict__ T, const float* __restrict__ b1,
                                  const float* __restrict__ w2, const float* __restrict__ b2,
                                  float* __restrict__ logits, float* __restrict__ weights) {
    const float LOG_ADJ = 2.5494451709255714f;
    int s = blockIdx.x;
    int j = threadIdx.x;
    float v1 = 0.f, v2 = 0.f;
#pragma unroll
    for (int z = 0; z < 8; z++) {
        v1 += T[((size_t)z * SEQ + s) * 64 + j];
        v2 += T[((size_t)z * SEQ + s) * 64 + j + 32];
    }
    float v = tanhf(v1 + b1[j]) * w2[j] + tanhf(v2 + b1[j + 32]) * w2[j + 32];
#pragma unroll
    for (int o = 16; o > 0; o >>= 1) v += __shfl_xor_sync(0xffffffffu, v, o);
    if (j == 0) {
        float lg = v + b2[0] - LOG_ADJ;
        logits[s] = lg;
        weights[s] = 1.0f / (1.0f + expf(-lg));
    }
}

// ---------------- top-k via single-block bitonic sort ----------------
__global__ void topk_kernel(const float* __restrict__ logits,
                            int* __restrict__ topk_list, int* __restrict__ is_topk) {
    extern __shared__ unsigned long long skeys[];
    int tid = threadIdx.x;
    for (int i = tid; i < SEQ; i += 1024) {
        unsigned u = __float_as_uint(logits[i]);
        u = (u & 0x80000000u) ? ~u : (u | 0x80000000u);
        skeys[i] = ((unsigned long long)(~u) << 32) | (unsigned)i;
        is_topk[i] = 0;
    }
    __syncthreads();
    for (int k = 2; k <= SEQ; k <<= 1) {
        for (int j = k >> 1; j > 0; j >>= 1) {
            for (int i = tid; i < SEQ; i += 1024) {
                int ixj = i ^ j;
                if (ixj > i) {
                    bool up = ((i & k) == 0);
                    unsigned long long a = skeys[i], b = skeys[ixj];
                    if ((a > b) == up) { skeys[i] = b; skeys[ixj] = a; }
                }
            }
            __syncthreads();
        }
    }
    for (int i = tid; i < TK; i += 1024) {
        int pos = (int)(skeys[i] & 0xffffffffu);
        topk_list[i] = pos;
        is_topk[pos] = 1;
    }
}

// ---------------- sketch stage A (kbo-split x2, j-unrolled x8 for MLP) ----------------
__global__ void sketchA_kernel(const float* __restrict__ X, int hstride, int hbase,
                               const float* __restrict__ weights,
                               const int* __restrict__ is_topk, int rest,
                               const float* __restrict__ kb, float* __restrict__ P) {
    int h = blockIdx.x;
    int ib = blockIdx.y;
    int z = blockIdx.z;          // kbo half: [z*16, z*16+16)
    int d = threadIdx.x;
    __shared__ float kbs[16 * 256];
    for (int t = d; t < 16 * 256; t += 128) kbs[t] = kb[z * 16 * 256 + t];
    __shared__ float ws[256];
    for (int j = d; j < 256; j += 128) {
        int t = ib * 256 + j;
        float w = weights[t];
        if (rest && is_topk[t]) w = 0.0f;
        ws[j] = w;
    }
    __syncthreads();
    float acc[16] = {};
    const size_t rowstride = (size_t)hstride * DH;
    const float* Xb = X + ((size_t)(ib * 256) * hstride + hbase + h) * DH + d;
    for (int j = 0; j < 256; j += 8) {
        float x0 = Xb[(size_t)(j + 0) * rowstride];
        float x1 = Xb[(size_t)(j + 1) * rowstride];
        float x2 = Xb[(size_t)(j + 2) * rowstride];
        float x3 = Xb[(size_t)(j + 3) * rowstride];
        float x4 = Xb[(size_t)(j + 4) * rowstride];
        float x5 = Xb[(size_t)(j + 5) * rowstride];
        float x6 = Xb[(size_t)(j + 6) * rowstride];
        float x7 = Xb[(size_t)(j + 7) * rowstride];
        x0 *= ws[j + 0]; x1 *= ws[j + 1]; x2 *= ws[j + 2]; x3 *= ws[j + 3];
        x4 *= ws[j + 4]; x5 *= ws[j + 5]; x6 *= ws[j + 6]; x7 *= ws[j + 7];
#pragma unroll
        for (int kbo = 0; kbo < 16; kbo++) {
            float a = acc[kbo];
            a += x0 * kbs[kbo * 256 + j + 0];
            a += x1 * kbs[kbo * 256 + j + 1];
            a += x2 * kbs[kbo * 256 + j + 2];
            a += x3 * kbs[kbo * 256 + j + 3];
            a += x4 * kbs[kbo * 256 + j + 4];
            a += x5 * kbs[kbo * 256 + j + 5];
            a += x6 * kbs[kbo * 256 + j + 6];
            a += x7 * kbs[kbo * 256 + j + 7];
            acc[kbo] = a;
        }
    }
#pragma unroll
    for (int kbo = 0; kbo < 16; kbo++)
        P[(((size_t)h * 32 + z * 16 + kbo) * 32 + ib) * DH + d] = acc[kbo];
}

// ---------------- sketch stage B (kao-split x2); mode: 0=qfrag,1=kfrag,3=dense -----
__global__ void sketchB_kernel(const float* __restrict__ P, int heads,
                               const float* __restrict__ ka,
                               const float* __restrict__ scale_p,
                               float* __restrict__ dst, int mode) {
    int h = blockIdx.x;
    int kbo = blockIdx.y;
    int zk = blockIdx.z;         // kao half: [zk*10, zk*10+10)
    int d = threadIdx.x;
    __shared__ float kas[10 * 32];
    for (int t = d; t < 10 * 32; t += 128)
        kas[t] = ka[(zk * 10 + t / 32) * DH + (t % 32)];
    __syncthreads();
    float p[32];
#pragma unroll
    for (int i = 0; i < 32; i++) p[i] = P[(((size_t)h * 32 + kbo) * 32 + i) * DH + d];
    float scale = scale_p[0];
    if (mode == 0) scale *= ATT_SCALE;
#pragma unroll
    for (int kao = 0; kao < 10; kao++) {
        float acc = 0.f;
#pragma unroll
        for (int i = 0; i < 32; i++) acc += p[i] * kas[kao * 32 + i];
        int s = TK + kbo * 20 + zk * 10 + kao;
        float val = acc * scale;
        if (mode == 0)      store_qfrag(dst, h, s, d, val);
        else if (mode == 1) store_kfrag(dst, h, s, d, val);
        else                dst[(size_t)(s - TK) * (heads * DH) + h * DH + d] = val;
    }
}

// ---------------- gather + RoPE (q and k only) ----------------
__global__ void gather_rope_kernel(const float* __restrict__ q, const float* __restrict__ k,
                                   const float* __restrict__ cosb, const float* __restrict__ sinb,
                                   const int* __restrict__ topk_list,
                                   float* __restrict__ Qfr, float* __restrict__ Kfr) {
    int j = blockIdx.x;
    int hy = blockIdx.y;   // 0..19
    int d = threadIdx.x;
    int pos = topk_list[j];
    float c = cosb[(size_t)pos * DH + d];
    float s = sinb[(size_t)pos * DH + d];
    if (hy < 16) {
        const float* src = q + ((size_t)pos * NH + hy) * DH;
        float x = src[d];
        float r = (d < 64) ? -src[d + 64] : src[d - 64];
        store_qfrag(Qfr, hy, j, d, (x * c + r * s) * ATT_SCALE);
    } else {
        int h = hy - 16;
        const float* src = k + (size_t)pos * 512 + h * DH;
        float x = src[d];
        float r = (d < 64) ? -src[d + 64] : src[d - 64];
        store_kfrag(Kfr, h, j, d, x * c + r * s);
    }
}

// ---------------- tensor-core flash attention (split-KV, cp.async K/V) -------
#define FA2_SMEM ((16384 + 2*8192 + 2*8192 + 512) * 4)
__global__ void __launch_bounds__(256, 1) fa_mma_kernel(
    const float* __restrict__ Qfr, const float* __restrict__ Kfr,
    const float* __restrict__ Vfr, float* __restrict__ Op,
    float* __restrict__ ML, int kt0)
{
    extern __shared__ float fsm[];
    float* Qsm = fsm;
    float* Ksm = fsm + 16384;
    float* Vsm = fsm + 32768;
    float* mpart = fsm + 49152;
    float* spart = fsm + 49408;

    const int qt = blockIdx.x;
    const int h  = blockIdx.y;
    const int kvh = h >> 2;
    const int tid = threadIdx.x;
    const int lane = tid & 31, wid = tid >> 5;
    const int wm = wid >> 1, wn = wid & 1;
    const int gid = lane >> 2, tig = lane & 3;

    const uint32_t ksmU = (uint32_t)__cvta_generic_to_shared(Ksm) + tid * 16;
    const uint32_t vsmU = (uint32_t)__cvta_generic_to_shared(Vsm) + tid * 16;

    {
        const float4* Kg = reinterpret_cast<const float4*>(Kfr + (size_t)(kvh * NKT + kt0) * 8192);
        const float4* Vg = reinterpret_cast<const float4*>(Vfr + (size_t)(kvh * NKT + kt0) * 8192);
#pragma unroll
        for (int i = 0; i < 8; i++) {
            CP_ASYNC16(ksmU + i * 4096, Kg + tid + i * 256);
            CP_ASYNC16(vsmU + i * 4096, Vg + tid + i * 256);
        }
        CP_COMMIT();
    }

    {
        const float4* Qg = reinterpret_cast<const float4*>(Qfr + (size_t)(h * NQT + qt) * 16384);
        float4* Qs4w = reinterpret_cast<float4*>(Qsm);
#pragma unroll
        for (int i = 0; i < 16; i++) Qs4w[tid + i * 256] = Qg[tid + i * 256];
    }

    float m_old[2][2], l_run[2][2];
#pragma unroll
    for (int a = 0; a < 2; a++)
#pragma unroll
        for (int b = 0; b < 2; b++) { m_old[a][b] = -1e30f; l_run[a][b] = 0.f; }
    float oacc[2][8][4] = {};

    const float4* Qs4 = reinterpret_cast<const float4*>(Qsm);

    for (int t = 0; t < KSPL; t++) {
        const int buf = t & 1;
        if (t + 1 < KSPL) {
            const float4* Kg = reinterpret_cast<const float4*>(Kfr + (size_t)(kvh * NKT + kt0 + t + 1) * 8192);
            const float4* Vg = reinterpret_cast<const float4*>(Vfr + (size_t)(kvh * NKT + kt0 + t + 1) * 8192);
            const uint32_t kd = ksmU + (1 - buf) * 32768;
            const uint32_t vd = vsmU + (1 - buf) * 32768;
#pragma unroll
            for (int i = 0; i < 8; i++) {
                CP_ASYNC16(kd + i * 4096, Kg + tid + i * 256);
                CP_ASYNC16(vd + i * 4096, Vg + tid + i * 256);
            }
            CP_COMMIT();
            asm volatile("cp.async.wait_group 1;");
        } else {
            asm volatile("cp.async.wait_group 0;");
        }
        __syncthreads();

        const float2* Ks2 = reinterpret_cast<const float2*>(Ksm + buf * 8192);
        const float2* Vs2 = reinterpret_cast<const float2*>(Vsm + buf * 8192);
        float* Psm = Ksm + buf * 8192;
        const float4* Ps4 = reinterpret_cast<const float4*>(Psm);

        float sacc[2][4][4] = {};
#pragma unroll
        for (int k8 = 0; k8 < 16; k8++) {
            float4 af[2];
            float2 bf[4];
            af[0] = Qs4[(k8 * 8 + wm * 2 + 0) * 32 + lane];
            af[1] = Qs4[(k8 * 8 + wm * 2 + 1) * 32 + lane];
#pragma unroll
            for (int nf = 0; nf < 4; nf++) bf[nf] = Ks2[(k8 * 8 + wn * 4 + nf) * 32 + lane];
#pragma unroll
            for (int mf = 0; mf < 2; mf++)
#pragma unroll
                for (int nf = 0; nf < 4; nf++)
                    mma_tf32(sacc[mf][nf],
                             reinterpret_cast<const uint32_t*>(&af[mf]),
                             reinterpret_cast<const uint32_t*>(&bf[nf]));
        }

        float mloc[2][2];
#pragma unroll
        for (int mf = 0; mf < 2; mf++) {
            float m0 = fmaxf(sacc[mf][0][0], sacc[mf][0][1]);
            float m1 = fmaxf(sacc[mf][0][2], sacc[mf][0][3]);
#pragma unroll
            for (int nf = 1; nf < 4; nf++) {
                m0 = fmaxf(m0, fmaxf(sacc[mf][nf][0], sacc[mf][nf][1]));
                m1 = fmaxf(m1, fmaxf(sacc[mf][nf][2], sacc[mf][nf][3]));
            }
            m0 = fmaxf(m0, __shfl_xor_sync(0xffffffffu, m0, 1));
            m0 = fmaxf(m0, __shfl_xor_sync(0xffffffffu, m0, 2));
            m1 = fmaxf(m1, __shfl_xor_sync(0xffffffffu, m1, 1));
            m1 = fmaxf(m1, __shfl_xor_sync(0xffffffffu, m1, 2));
            mloc[mf][0] = m0; mloc[mf][1] = m1;
        }
        if (tig == 0) {
#pragma unroll
            for (int mf = 0; mf < 2; mf++) {
                int r = wm * 32 + mf * 16 + gid;
                mpart[wn * 128 + r] = mloc[mf][0];
                mpart[wn * 128 + r + 8] = mloc[mf][1];
            }
        }
        __syncthreads();

        float mnew[2][2], corr[2][2];
#pragma unroll
        for (int mf = 0; mf < 2; mf++)
#pragma unroll
            for (int hi = 0; hi < 2; hi++) {
                int r = wm * 32 + mf * 16 + gid + hi * 8;
                float mt = fmaxf(mpart[r], mpart[128 + r]);
                float mn = fmaxf(m_old[mf][hi], mt);
                corr[mf][hi] = __expf(m_old[mf][hi] - mn);
                mnew[mf][hi] = mn;
                m_old[mf][hi] = mn;
            }

        float sloc[2][2] = {};
#pragma unroll
        for (int mf = 0; mf < 2; mf++)
#pragma unroll
            for (int nf = 0; nf < 4; nf++) {
                sacc[mf][nf][0] = __expf(sacc[mf][nf][0] - mnew[mf][0]);
                sacc[mf][nf][1] = __expf(sacc[mf][nf][1] - mnew[mf][0]);
                sacc[mf][nf][2] = __expf(sacc[mf][nf][2] - mnew[mf][1]);
                sacc[mf][nf][3] = __expf(sacc[mf][nf][3] - mnew[mf][1]);
                sloc[mf][0] += sacc[mf][nf][0] + sacc[mf][nf][1];
                sloc[mf][1] += sacc[mf][nf][2] + sacc[mf][nf][3];
            }
#pragma unroll
        for (int mf = 0; mf < 2; mf++) {
            sloc[mf][0] += __shfl_xor_sync(0xffffffffu, sloc[mf][0], 1);
            sloc[mf][0] += __shfl_xor_sync(0xffffffffu, sloc[mf][0], 2);
            sloc[mf][1] += __shfl_xor_sync(0xffffffffu, sloc[mf][1], 1);
            sloc[mf][1] += __shfl_xor_sync(0xffffffffu, sloc[mf][1], 2);
        }
        if (tig == 0) {
#pragma unroll
            for (int mf = 0; mf < 2; mf++) {
                int r = wm * 32 + mf * 16 + gid;
                spart[wn * 128 + r] = sloc[mf][0];
                spart[wn * 128 + r + 8] = sloc[mf][1];
            }
        }

#pragma unroll
        for (int mf = 0; mf < 2; mf++)
#pragma unroll
            for (int nf = 0; nf < 4; nf++) {
                int k8p = wn * 4 + nf;
                int mfg = wm * 2 + mf;
#pragma unroll
                for (int b = 0; b < 2; b++) {
                    int c = tig * 2 + b;
                    int khi = (c >= 4);
                    int base = ((k8p * 8 + mfg) * 32 + (gid << 2) + (c & 3)) * 4 + khi * 2;
                    *reinterpret_cast<float2*>(Psm + base) =
                        make_float2(tf32f(sacc[mf][nf][b]), tf32f(sacc[mf][nf][2 + b]));
                }
            }
        __syncthreads();

#pragma unroll
        for (int mf = 0; mf < 2; mf++)
#pragma unroll
            for (int hi = 0; hi < 2; hi++) {
                int r = wm * 32 + mf * 16 + gid + hi * 8;
                l_run[mf][hi] = l_run[mf][hi] * corr[mf][hi] + spart[r] + spart[128 + r];
            }
#pragma unroll
        for (int mf = 0; mf < 2; mf++)
#pragma unroll
            for (int nf = 0; nf < 8; nf++) {
                oacc[mf][nf][0] *= corr[mf][0]; oacc[mf][nf][1] *= corr[mf][0];
                oacc[mf][nf][2] *= corr[mf][1]; oacc[mf][nf][3] *= corr[mf][1];
            }

#pragma unroll
        for (int k8 = 0; k8 < 8; k8++) {
            float4 af[2];
            af[0] = Ps4[(k8 * 8 + wm * 2 + 0) * 32 + lane];
            af[1] = Ps4[(k8 * 8 + wm * 2 + 1) * 32 + lane];
#pragma unroll
            for (int nf = 0; nf < 8; nf++) {
                float2 bf = Vs2[(k8 * 16 + wn * 8 + nf) * 32 + lane];
#pragma unroll
                for (int mf = 0; mf < 2; mf++)
                    mma_tf32(oacc[mf][nf],
                             reinterpret_cast<const uint32_t*>(&af[mf]),
                             reinterpret_cast<const uint32_t*>(&bf));
            }
        }
        __syncthreads();
    }

#pragma unroll
    for (int mf = 0; mf < 2; mf++) {
        int r0 = qt * 128 + wm * 32 + mf * 16 + gid;
        if (wn == 0 && tig == 0) {
            size_t row0i = (size_t)r0 * NH + h;
            size_t row1i = (size_t)(r0 + 8) * NH + h;
            ML[row0i * 2] = m_old[mf][0]; ML[row0i * 2 + 1] = l_run[mf][0];
            ML[row1i * 2] = m_old[mf][1]; ML[row1i * 2 + 1] = l_run[mf][1];
        }
#pragma unroll
        for (int nf = 0; nf < 8; nf++) {
            int col = wn * 64 + nf * 8 + tig * 2;
            *reinterpret_cast<float2*>(&Op[((size_t)r0 * NH + h) * DH + col]) =
                make_float2(oacc[mf][nf][0], oacc[mf][nf][1]);
            *reinterpret_cast<float2*>(&Op[((size_t)(r0 + 8) * NH + h) * DH + col]) =
                make_float2(oacc[mf][nf][2], oacc[mf][nf][3]);
        }
    }
}

// ---------------- fa combine ----------------
__global__ void fa_combine_kernel(float* __restrict__ O0, const float* __restrict__ O1,
                                  const float* __restrict__ ML) {
    size_t row = (size_t)blockIdx.x * NH + blockIdx.y;
    int d = threadIdx.x;
    float m0 = ML[row * 2], l0 = ML[row * 2 + 1];
    float m1 = ML[(size_t)NQF * NH * 2 + row * 2], l1 = ML[(size_t)NQF * NH * 2 + row * 2 + 1];
    float m = fmaxf(m0, m1);
    float w0 = __expf(m0 - m), w1 = __expf(m1 - m);
    float inv = 1.0f / (w0 * l0 + w1 * l1);
    O0[row * DH + d] = (O0[row * DH + d] * w0 + O1[row * DH + d] * w1) * inv;
}

// ---------------- expand stage C ----------------
__global__ void expandC_kernel(const float* __restrict__ Z, const float* __restrict__ ka,
                               float* __restrict__ E1) {
    int i = blockIdx.y;
    int hd = blockIdx.x * 256 + threadIdx.x;
    __shared__ float kav[20];
    if (threadIdx.x < 20) kav[threadIdx.x] = ka[threadIdx.x * DH + i];
    __syncthreads();
    for (int kbo = 0; kbo < 32; kbo++) {
        float acc = 0.f;
#pragma unroll
        for (int kao = 0; kao < 20; kao++)
            acc += Z[((size_t)(kbo * 20 + kao)) * HID + hd] * kav[kao];
        E1[((size_t)i * 32 + kbo) * HID + hd] = acc;
    }
}

// ---------------- expand stage D ----------------
__global__ void expandD_kernel(const float* __restrict__ E1, const float* __restrict__ kb,
                               const int* __restrict__ is_topk, float* __restrict__ OUT) {
    int i = blockIdx.y;
    int hd = blockIdx.x * 128 + threadIdx.x;
    __shared__ float kbs[32 * 256];
    for (int t = threadIdx.x; t < 32 * 256; t += 128) kbs[t] = kb[t];
    float e[32];
#pragma unroll
    for (int kbo = 0; kbo < 32; kbo++) e[kbo] = E1[((size_t)i * 32 + kbo) * HID + hd];
    __syncthreads();
    for (int j = 0; j < 256; j++) {
        int row = i * 256 + j;
        if (is_topk[row]) continue;
        float acc = 0.f;
#pragma unroll
        for (int kbo = 0; kbo < 32; kbo++) acc += e[kbo] * kbs[kbo * 256 + j];
        OUT[(size_t)row * HID + hd] = acc;
    }
}

// ---------------- host launcher ----------------
extern "C" void kernel_launch(void* const* d_in, const int* in_sizes, int n_in,
                              void* d_out, int out_size) {
    const float* hs    = (const float*)d_in[0];
    const float* cosb  = (const float*)d_in[1];
    const float* sinb  = (const float*)d_in[2];
    const float* wq    = (const float*)d_in[3];
    const float* wk    = (const float*)d_in[4];
    const float* wv    = (const float*)d_in[5];
    const float* wo    = (const float*)d_in[6];
    const float* qnw   = (const float*)d_in[7];
    const float* knw   = (const float*)d_in[8];
    const float* w1    = (const float*)d_in[9];
    const float* b1    = (const float*)d_in[10];
    const float* w2    = (const float*)d_in[11];
    const float* b2    = (const float*)d_in[12];
    const float* ka    = (const float*)d_in[13];
    const float* kb    = (const float*)d_in[14];
    const float* sscale= (const float*)d_in[15];
    float* out = (float*)d_out;

    float *pT, *pLg, *pW, *pQ, *pK, *pPq, *pPk, *pPh, *pHSr, *pQfr, *pKfr, *pVfr,
          *pAO, *pAO2, *pML, *pE1, *pZ, *pAfr, *pAfr2, *pBfr;
    int *pTop, *pIs;
    cudaGetSymbolAddress((void**)&pT, g_T);
    cudaGetSymbolAddress((void**)&pLg, g_logits);
    cudaGetSymbolAddress((void**)&pW, g_weights);
    cudaGetSymbolAddress((void**)&pQ, g_q);
    cudaGetSymbolAddress((void**)&pK, g_k);
    cudaGetSymbolAddress((void**)&pPq, g_Pq);
    cudaGetSymbolAddress((void**)&pPk, g_Pk);
    cudaGetSymbolAddress((void**)&pPh, g_Ph);
    cudaGetSymbolAddress((void**)&pHSr, g_HSr);
    cudaGetSymbolAddress((void**)&pQfr, g_Qfr);
    cudaGetSymbolAddress((void**)&pKfr, g_Kfr);
    cudaGetSymbolAddress((void**)&pVfr, g_Vfr);
    cudaGetSymbolAddress((void**)&pAO, g_AO);
    cudaGetSymbolAddress((void**)&pAO2, g_AO2);
    cudaGetSymbolAddress((void**)&pML, g_ML);
    cudaGetSymbolAddress((void**)&pE1, g_E1);
    cudaGetSymbolAddress((void**)&pZ, g_Z);
    cudaGetSymbolAddress((void**)&pAfr, g_Afr);
    cudaGetSymbolAddress((void**)&pAfr2, g_Afr2);
    cudaGetSymbolAddress((void**)&pBfr, g_Bfr);
    cudaGetSymbolAddress((void**)&pTop, g_topk);
    cudaGetSymbolAddress((void**)&pIs, g_istop);

    float* pBwk = pBfr + (size_t)16 * 128 * 2048;
    float* pBwv = pBfr + (size_t)20 * 128 * 2048;
    float* pBwo = pBfr + (size_t)24 * 128 * 2048;
    float* pML2 = pML + (size_t)NQF * NH * 2;
    float* pAfr2b = pAfr2 + (size_t)16 * (HID / 16) * 2048;

    cudaFuncSetAttribute(topk_kernel, cudaFuncAttributeMaxDynamicSharedMemorySize, SEQ * 8);
    cudaFuncSetAttribute(fa_mma_kernel, cudaFuncAttributeMaxDynamicSharedMemorySize, FA2_SMEM);

    static cudaStream_t s1 = nullptr;
    static cudaEvent_t evFork = nullptr, evImp = nullptr, evAfr = nullptr,
                       evVf = nullptr, evK = nullptr, evKf = nullptr,
                       evQg = nullptr, evFA1 = nullptr, evAO = nullptr, evExp = nullptr;
    if (s1 == nullptr) {
        cudaStreamCreateWithFlags(&s1, cudaStreamNonBlocking);
        cudaEventCreateWithFlags(&evFork, cudaEventDisableTiming);
        cudaEventCreateWithFlags(&evImp, cudaEventDisableTiming);
        cudaEventCreateWithFlags(&evAfr, cudaEventDisableTiming);
        cudaEventCreateWithFlags(&evVf, cudaEventDisableTiming);
        cudaEventCreateWithFlags(&evK, cudaEventDisableTiming);
        cudaEventCreateWithFlags(&evKf, cudaEventDisableTiming);
        cudaEventCreateWithFlags(&evQg, cudaEventDisableTiming);
        cudaEventCreateWithFlags(&evFA1, cudaEventDisableTiming);
        cudaEventCreateWithFlags(&evAO, cudaEventDisableTiming);
        cudaEventCreateWithFlags(&evExp, cudaEventDisableTiming);
    }

    // ---- fork ----
    cudaEventRecord(evFork, 0);
    cudaStreamWaitEvent(s1, evFork, 0);

    // ---- s1: importance chain ----
    imp_gemm_kernel<<<dim3(1, SEQ / 64, 8), 256, 0, s1>>>(hs, w1, pT);
    imp_logits_kernel<<<SEQ, 32, 0, s1>>>(pT, b1, w2, b2, pLg, pW);
    topk_kernel<<<1, 1024, SEQ * 8, s1>>>(pLg, pTop, pIs);
    cudaEventRecord(evImp, s1);

    // ---- s1: V path ----
    sketchA_kernel<<<dim3(16, 32, 2), DH, 0, s1>>>(hs, 16, 0, pW, pIs, 1, kb, pPh);
    sketchB_kernel<<<dim3(16, 32, 2), DH, 0, s1>>>(pPh, 16, ka, sscale, pHSr, 3);
    convA_kernel<<<dim3(HID / 16, 16), 256, 0, s1>>>(hs, pTop, pAfr2, HID);
    convA_kernel<<<dim3(HID / 16, 5), 256, 0, s1>>>(pHSr, nullptr, pAfr2b, HID);
    convB_kernel<<<dim3(HID / 16, 512 / 128), 256, 0, s1>>>(wv, pBwv, HID, 512, 0);
    mma_gemm_kernel<<<dim3(512 / 128, NQF / 128), 128, 0, s1>>>(
        pAfr2, pBwv, pVfr, nullptr, nullptr, 0, pVfr, 512, HID);
    cudaEventRecord(evVf, s1);

    // ---- default: Q projection chain ----
    convA_kernel<<<dim3(HID / 16, SEQ / 128), 256>>>(hs, nullptr, pAfr, HID);
    cudaEventRecord(evAfr, 0);
    convB_kernel<<<dim3(HID / 16, HID / 128), 256>>>(wq, pBfr, HID, HID, 0);
    mma_gemm_kernel<<<dim3(HID / 128, SEQ / 128), 128>>>(pAfr, pBfr, pQ, nullptr, qnw, 16, nullptr, HID, HID);

    // ---- s1: K projection + k-sketch ----
    convB_kernel<<<dim3(HID / 16, 512 / 128), 256, 0, s1>>>(wk, pBwk, HID, 512, 0);
    cudaStreamWaitEvent(s1, evAfr, 0);
    mma_gemm_kernel<<<dim3(512 / 128, SEQ / 128), 128, 0, s1>>>(
        pAfr, pBwk, pK, nullptr, knw, 4, nullptr, 512, HID);
    cudaEventRecord(evK, s1);
    sketchA_kernel<<<dim3(NKV, 32, 2), DH, 0, s1>>>(pK, 4, 0, pW, pIs, 1, kb, pPk);
    sketchB_kernel<<<dim3(NKV, 32, 2), DH, 0, s1>>>(pPk, NKV, ka, sscale, pKfr, 1);
    cudaEventRecord(evKf, s1);
    convB_kernel<<<dim3(HID / 16, HID / 128), 256, 0, s1>>>(wo, pBwo, HID, HID, 0);

    // ---- default: q sketch + gather ----
    cudaStreamWaitEvent(0, evImp, 0);
    sketchA_kernel<<<dim3(NH, 32, 2), DH>>>(pQ, 16, 0, pW, pIs, 0, kb, pPq);
    sketchB_kernel<<<dim3(NH, 32, 2), DH>>>(pPq, NH, ka, sscale, pQfr, 0);
    cudaStreamWaitEvent(0, evK, 0);
    gather_rope_kernel<<<dim3(TK, 20), DH>>>(pQ, pK, cosb, sinb, pTop, pQfr, pKfr);
    cudaEventRecord(evQg, 0);

    // ---- attention: split-KV x2 + combine ----
    cudaStreamWaitEvent(0, evKf, 0);
    cudaStreamWaitEvent(0, evVf, 0);
    cudaStreamWaitEvent(s1, evQg, 0);
    fa_mma_kernel<<<dim3(NQT, NH), 256, FA2_SMEM>>>(pQfr, pKfr, pVfr, pAO, pML, 0);
    fa_mma_kernel<<<dim3(NQT, NH), 256, FA2_SMEM, s1>>>(pQfr, pKfr, pVfr, pAO2, pML2, KSPL);
    cudaEventRecord(evFA1, s1);
    cudaStreamWaitEvent(0, evFA1, 0);
    fa_combine_kernel<<<dim3(NQF, NH), DH>>>(pAO, pAO2, pML);

    // ---- epilogue ----
    convA_kernel<<<dim3(HID / 16, NQF / 128), 256>>>(pAO, nullptr, pAfr, HID);
    cudaEventRecord(evAO, 0);
    cudaStreamWaitEvent(s1, evAO, 0);
    mma_gemm_kernel<<<dim3(HID / 128, SK / 128), 128, 0, s1>>>(
        pAfr + (size_t)16 * (HID / 16) * 2048, pBwo, pZ, nullptr, nullptr, 0, nullptr, HID, HID);
    expandC_kernel<<<dim3(HID / 256, 32), 256, 0, s1>>>(pZ, ka, pE1);
    expandD_kernel<<<dim3(HID / 128, 32), DH, 0, s1>>>(pE1, kb, pIs, out);
    cudaEventRecord(evExp, s1);
    mma_gemm_kernel<<<dim3(HID / 128, TK / 128), 128>>>(pAfr, pBwo, out, pTop, nullptr, 0, nullptr, HID, HID);

    // ---- join ----
    cudaStreamWaitEvent(0, evExp, 0);
}

// round 17
// speedup vs baseline: 1.1131x; 1.0153x over previous
#include <cuda_runtime.h>
#include <cuda_bf16.h>
#include <math.h>
#include <cstdint>

// Problem constants
#define SEQ   8192
#define HID   2048
#define NH    16
#define NKV   4
#define DH    128
#define TK    2048
#define SK    640
#define NQF   (TK + SK)        // 2688
#define NQT   (NQF / 128)      // 21 q tiles
#define NKT   (NQF / 64)       // 42 key tiles
#define KSPL  21               // key tiles per split (2 splits)
#define ATT_SCALE 0.08838834764831843f   // 1/sqrt(128)

// ---------------- scratch (device globals; no allocation) ----------------
__device__ float g_T[8 * SEQ * 64];
__device__ float g_logits[SEQ];
__device__ float g_weights[SEQ];
__device__ float g_q[SEQ * NH * DH];       // normalized q
__device__ float g_k[SEQ * 512];           // normalized k (4 heads x 128)
__device__ int   g_topk[TK];
__device__ int   g_istop[SEQ];
__device__ float g_Pq[NH * 32 * 32 * DH];  // q-sketch stage-A scratch
__device__ float g_Pk[NKV * 32 * 32 * DH]; // k-sketch stage-A scratch
__device__ float g_Ph[16 * 32 * 32 * DH];  // hs-sketch stage-A scratch
__device__ float g_HSr[SK * HID];          // rest-weighted hs sketch rows
__device__ float g_Qfr[NH * NQT * 16 * 8 * 32 * 4];
__device__ float g_Kfr[NKV * NKT * 16 * 8 * 32 * 2];
__device__ float g_Vfr[NKV * NKT * 8 * 16 * 32 * 2];
__device__ float g_AO[NQF * NH * DH];      // split-0 partial, then combined AO
__device__ float g_AO2[NQF * NH * DH];     // split-1 partial
__device__ float g_ML[2 * NQF * NH * 2];
__device__ float g_E1[32 * 32 * HID];
__device__ float g_Z[SK * HID];
__device__ float g_Afr[SEQ * HID];         // A fragments (hs, later AO)
__device__ float g_Afr2[NQF * HID];        // A fragments for V GEMM (topk hs | HSr)
__device__ float g_Bfr[40 * 128 * 2048];   // wq[0:16) | wk[16:20) | wv[20:24) | wo[24:40)

// ======================= tf32 mma.sync helpers =======================
__device__ __forceinline__ float tf32f(float x) {
    uint32_t r; asm("cvt.rna.tf32.f32 %0, %1;" : "=r"(r) : "f"(x));
    return __uint_as_float(r);
}

__device__ __forceinline__ void mma_tf32(float* c, const uint32_t* a, const uint32_t* b) {
    asm volatile("mma.sync.aligned.m16n8k8.row.col.f32.tf32.tf32.f32 "
        "{%0,%1,%2,%3}, {%4,%5,%6,%7}, {%8,%9}, {%0,%1,%2,%3};"
        : "+f"(c[0]), "+f"(c[1]), "+f"(c[2]), "+f"(c[3])
        : "r"(a[0]), "r"(a[1]), "r"(a[2]), "r"(a[3]), "r"(b[0]), "r"(b[1]));
}

#define CP_ASYNC16(dst_u32, src_ptr) \
    asm volatile("cp.async.cg.shared.global [%0], [%1], 16;" :: "r"(dst_u32), "l"(src_ptr))
#define CP_COMMIT() asm volatile("cp.async.commit_group;")

__device__ __forceinline__ void store_qfrag(float* Qg, int h, int tok, int d, float v) {
    int qt = tok >> 7, m = tok & 127;
    int k8 = d >> 3, mf = m >> 4;
    int lane = ((m & 7) << 2) | (d & 3);
    int reg = 2 * ((d & 7) >= 4) + ((m & 15) >= 8);
    size_t idx = ((((size_t)(h * NQT + qt) * 16 + k8) * 8 + mf) * 32 + lane) * 4 + reg;
    Qg[idx] = tf32f(v);
}
__device__ __forceinline__ void store_kfrag(float* Kg, int kvh, int tok, int d, float v) {
    int kt = tok >> 6, key = tok & 63;
    int k8 = d >> 3, nf = key >> 3;
    int lane = ((key & 7) << 2) | (d & 3);
    int reg = ((d & 7) >= 4);
    size_t idx = ((((size_t)(kvh * NKT + kt) * 16 + k8) * 8 + nf) * 32 + lane) * 2 + reg;
    Kg[idx] = tf32f(v);
}
// V B-fragments with within-8-key permutation so PV can consume P (QK C-fragments)
// directly from registers: A k-slot s holds actual key 2*(s&3)+(s>>2), so V row for
// key7 goes to slot s = (key7>>1) | ((key7&1)<<2).
__device__ __forceinline__ void store_vfrag(float* Vg, int kvh, int tok, int d, float v) {
    int kt = tok >> 6, key = tok & 63;
    int k8 = key >> 3, nf = d >> 3;
    int key7 = key & 7;
    int s = (key7 >> 1) | ((key7 & 1) << 2);
    int lane = ((d & 7) << 2) | (s & 3);
    int reg = (s >> 2);
    size_t idx = ((((size_t)(kvh * NKT + kt) * 8 + k8) * 16 + nf) * 32 + lane) * 2 + reg;
    Vg[idx] = tf32f(v);
}

// ======================= fragment conversion pre-passes =======================
__global__ void __launch_bounds__(256) convA_kernel(const float* __restrict__ A,
                                                    const int* __restrict__ remap,
                                                    float* __restrict__ Afr, int K) {
    __shared__ float sm[2048];
    const int rt = blockIdx.y, c = blockIdx.x;
    const int tid = threadIdx.x;
#pragma unroll
    for (int i = 0; i < 2; i++) {
        int f = tid + i * 256;
        int r = f >> 2, c4 = f & 3;
        int act = remap ? __ldg(&remap[rt * 128 + r]) : (rt * 128 + r);
        float4 v = *reinterpret_cast<const float4*>(A + (size_t)act * K + c * 16 + c4 * 4);
        int mf = r >> 4, gid = r & 7, mhi = (r >> 3) & 1;
        float vv[4] = {v.x, v.y, v.z, v.w};
#pragma unroll
        for (int j = 0; j < 4; j++) {
            int k = c4 * 4 + j;
            int slot = ((k >> 3) * 8 + mf) * 128 + ((gid << 2) | (k & 3)) * 4
                     + 2 * ((k & 7) >= 4) + mhi;
            sm[slot] = tf32f(vv[j]);
        }
    }
    __syncthreads();
    float4* out = reinterpret_cast<float4*>(Afr + ((size_t)(rt * (K >> 4) + c)) * 2048);
    const float4* s4 = reinterpret_cast<const float4*>(sm);
#pragma unroll
    for (int i = 0; i < 2; i++) out[tid + i * 256] = s4[tid + i * 256];
}

__global__ void __launch_bounds__(256) convB_kernel(const float* __restrict__ B,
                                                    float* __restrict__ Bfr, int K, int N,
                                                    int ctbase) {
    __shared__ float sm[2048];
    const int ct = blockIdx.y + ctbase, c = blockIdx.x;
    const int tid = threadIdx.x;
    const float* Bb = B + ((size_t)(c * 16)) * N + blockIdx.y * 128;
#pragma unroll
    for (int i = 0; i < 2; i++) {
        int f = tid + i * 256;
        int kk = f >> 5, n4 = f & 31;
        float4 v = *reinterpret_cast<const float4*>(Bb + (size_t)kk * N + n4 * 4);
        int k8in = kk >> 3, reg = ((kk & 7) >= 4);
        float vv[4] = {v.x, v.y, v.z, v.w};
#pragma unroll
        for (int j = 0; j < 4; j++) {
            int n = n4 * 4 + j;
            int slot = (k8in * 16 + (n >> 3)) * 64 + (((n & 7) << 2) | (kk & 3)) * 2 + reg;
            sm[slot] = tf32f(vv[j]);
        }
    }
    __syncthreads();
    float4* out = reinterpret_cast<float4*>(Bfr + ((size_t)(ct * (K >> 4) + c)) * 2048);
    const float4* s4 = reinterpret_cast<const float4*>(sm);
#pragma unroll
    for (int i = 0; i < 2; i++) out[tid + i * 256] = s4[tid + i * 256];
}

// ======= tf32 GEMM: 128x128 CTA, 4 warps @ 64x64 warp tiles, cp.async 3-stage,
//         2 CTA/SM; optional rmsnorm / remap / vfrag-epilogue ===
__global__ void __launch_bounds__(128, 2) mma_gemm_kernel(
    const float* __restrict__ Afr, const float* __restrict__ Bfr,
    float* __restrict__ C, const int* __restrict__ remap,
    const float* __restrict__ normw, int normct, float* __restrict__ vfr,
    int N, int K)
{
    __shared__ float sA[3][2048];
    __shared__ float sB[3][2048];

    const int tid = threadIdx.x;
    const int lane = tid & 31, wid = tid >> 5;
    const int wm = wid >> 1, wn = wid & 1;
    const int NCH = K >> 4;

    const float4* Ag = reinterpret_cast<const float4*>(Afr) + (size_t)blockIdx.y * NCH * 512;
    const float4* Bg = reinterpret_cast<const float4*>(Bfr) + (size_t)blockIdx.x * NCH * 512;

    const uint32_t sAu = (uint32_t)__cvta_generic_to_shared(&sA[0][0]) + tid * 16;
    const uint32_t sBu = (uint32_t)__cvta_generic_to_shared(&sB[0][0]) + tid * 16;

    {
#pragma unroll
        for (int i = 0; i < 4; i++) {
            CP_ASYNC16(sAu + i * 2048, Ag + tid + i * 128);
            CP_ASYNC16(sBu + i * 2048, Bg + tid + i * 128);
        }
        CP_COMMIT();
        if (NCH > 1) {
#pragma unroll
            for (int i = 0; i < 4; i++) {
                CP_ASYNC16(sAu + 8192 + i * 2048, Ag + 512 + tid + i * 128);
                CP_ASYNC16(sBu + 8192 + i * 2048, Bg + 512 + tid + i * 128);
            }
            CP_COMMIT();
        }
    }

    float acc[4][8][4] = {};
    for (int c = 0; c < NCH; c++) {
        if (c + 1 < NCH) asm volatile("cp.async.wait_group 1;");
        else             asm volatile("cp.async.wait_group 0;");
        __syncthreads();

        const int buf = c % 3;
        const float4* A4 = reinterpret_cast<const float4*>(sA[buf]);
        const float2* B2 = reinterpret_cast<const float2*>(sB[buf]);
#pragma unroll
        for (int k8 = 0; k8 < 2; k8++) {
            float4 af[4];
            float2 bf[8];
#pragma unroll
            for (int mf = 0; mf < 4; mf++)
                af[mf] = A4[(k8 * 8 + wm * 4 + mf) * 32 + lane];
#pragma unroll
            for (int nf = 0; nf < 8; nf++)
                bf[nf] = B2[(k8 * 16 + wn * 8 + nf) * 32 + lane];
#pragma unroll
            for (int mf = 0; mf < 4; mf++)
#pragma unroll
                for (int nf = 0; nf < 8; nf++)
                    mma_tf32(acc[mf][nf],
                             reinterpret_cast<const uint32_t*>(&af[mf]),
                             reinterpret_cast<const uint32_t*>(&bf[nf]));
        }
        if (c + 2 < NCH) {
            const int st = (c + 2) % 3;
            const float4* ga = Ag + (c + 2) * 512 + tid;
            const float4* gb = Bg + (c + 2) * 512 + tid;
#pragma unroll
            for (int i = 0; i < 4; i++) {
                CP_ASYNC16(sAu + st * 8192 + i * 2048, ga + i * 128);
                CP_ASYNC16(sBu + st * 8192 + i * 2048, gb + i * 128);
            }
            CP_COMMIT();
        }
    }

    const int gid = lane >> 2, tig = lane & 3;
    const int row0 = blockIdx.y * 128;
    const int col0 = blockIdx.x * 128;

    if (vfr != nullptr) {
#pragma unroll
        for (int mf = 0; mf < 4; mf++) {
            int m = row0 + wm * 64 + mf * 16 + gid;
#pragma unroll
            for (int nf = 0; nf < 8; nf++) {
                int n = col0 + wn * 64 + nf * 8 + tig * 2;
                store_vfrag(vfr, n >> 7, m, n & 127, acc[mf][nf][0]);
                store_vfrag(vfr, (n + 1) >> 7, m, (n + 1) & 127, acc[mf][nf][1]);
                store_vfrag(vfr, n >> 7, m + 8, n & 127, acc[mf][nf][2]);
                store_vfrag(vfr, (n + 1) >> 7, m + 8, (n + 1) & 127, acc[mf][nf][3]);
            }
        }
        return;
    }

    if (normw != nullptr && blockIdx.x < normct) {
        float* ssm = &sA[0][0];
        __syncthreads();
        float ss0[4], ss1[4];
#pragma unroll
        for (int mf = 0; mf < 4; mf++) {
            float s0 = 0.f, s1 = 0.f;
#pragma unroll
            for (int nf = 0; nf < 8; nf++) {
                s0 += acc[mf][nf][0] * acc[mf][nf][0] + acc[mf][nf][1] * acc[mf][nf][1];
                s1 += acc[mf][nf][2] * acc[mf][nf][2] + acc[mf][nf][3] * acc[mf][nf][3];
            }
            s0 += __shfl_xor_sync(0xffffffffu, s0, 1);
            s0 += __shfl_xor_sync(0xffffffffu, s0, 2);
            s1 += __shfl_xor_sync(0xffffffffu, s1, 1);
            s1 += __shfl_xor_sync(0xffffffffu, s1, 2);
            ss0[mf] = s0; ss1[mf] = s1;
        }
        if (tig == 0) {
#pragma unroll
            for (int mf = 0; mf < 4; mf++) {
                int r = wm * 64 + mf * 16 + gid;
                ssm[r * 2 + wn] = ss0[mf];
                ssm[(r + 8) * 2 + wn] = ss1[mf];
            }
        }
        __syncthreads();
#pragma unroll
        for (int mf = 0; mf < 4; mf++) {
            int r = wm * 64 + mf * 16 + gid;
            float t0 = ssm[r * 2] + ssm[r * 2 + 1];
            float t1 = ssm[(r + 8) * 2] + ssm[(r + 8) * 2 + 1];
            float sc0 = rsqrtf(t0 * (1.0f / 128.0f) + 1e-6f);
            float sc1 = rsqrtf(t1 * (1.0f / 128.0f) + 1e-6f);
#pragma unroll
            for (int nf = 0; nf < 8; nf++) {
                int n = wn * 64 + nf * 8 + tig * 2;
                float w0 = __ldg(&normw[n]), w1 = __ldg(&normw[n + 1]);
                acc[mf][nf][0] *= sc0 * w0; acc[mf][nf][1] *= sc0 * w1;
                acc[mf][nf][2] *= sc1 * w0; acc[mf][nf][3] *= sc1 * w1;
            }
        }
    }

#pragma unroll
    for (int mf = 0; mf < 4; mf++) {
        int m = row0 + wm * 64 + mf * 16 + gid;
        int m1 = remap ? __ldg(&remap[m]) : m;
        int m2 = remap ? __ldg(&remap[m + 8]) : (m + 8);
#pragma unroll
        for (int nf = 0; nf < 8; nf++) {
            int n = col0 + wn * 64 + nf * 8 + tig * 2;
            *reinterpret_cast<float2*>(&C[(size_t)m1 * N + n]) =
                make_float2(acc[mf][nf][0], acc[mf][nf][1]);
            *reinterpret_cast<float2*>(&C[(size_t)m2 * N + n]) =
                make_float2(acc[mf][nf][2], acc[mf][nf][3]);
        }
    }
}

// ---------------- importance GEMM: fp32 split-K x8 ----------------
__global__ void __launch_bounds__(256) imp_gemm_kernel(
    const float* __restrict__ A, const float* __restrict__ B, float* __restrict__ Cp)
{
    __shared__ float As[16][64];
    __shared__ float Bs[16][64];
    const int tid = threadIdx.x;
    const int row0 = blockIdx.y * 64;
    const int z = blockIdx.z;
    const float* Ab = A + (size_t)row0 * HID + z * 256;
    const float* Bb = B + (size_t)z * 256 * 64;
    float acc[4][4] = {};
    const int tc = (tid & 15) * 4, tr = (tid >> 4) * 4;
    const int ar = tid >> 2, ac = (tid & 3) * 4;
    const int br = tid >> 4, bc = (tid & 15) * 4;

    for (int k0 = 0; k0 < 256; k0 += 16) {
        float4 va = *reinterpret_cast<const float4*>(Ab + (size_t)ar * HID + k0 + ac);
        As[ac + 0][ar] = va.x; As[ac + 1][ar] = va.y;
        As[ac + 2][ar] = va.z; As[ac + 3][ar] = va.w;
        float4 vb = *reinterpret_cast<const float4*>(Bb + (size_t)(k0 + br) * 64 + bc);
        *reinterpret_cast<float4*>(&Bs[br][bc]) = vb;
        __syncthreads();
#pragma unroll
        for (int k = 0; k < 16; k++) {
            float ra[4], rb[4];
#pragma unroll
            for (int m = 0; m < 4; m++) ra[m] = As[k][tr + m];
#pragma unroll
            for (int n = 0; n < 4; n++) rb[n] = Bs[k][tc + n];
#pragma unroll
            for (int m = 0; m < 4; m++)
#pragma unroll
                for (int n = 0; n < 4; n++) acc[m][n] += ra[m] * rb[n];
        }
        __syncthreads();
    }
#pragma unroll
    for (int m = 0; m < 4; m++) {
        float4 v = make_float4(acc[m][0], acc[m][1], acc[m][2], acc[m][3]);
        *reinterpret_cast<float4*>(&Cp[((size_t)z * SEQ + row0 + tr + m) * 64 + tc]) = v;
    }
}

// ---------------- importance logits epilogue ----------------
__global__ void imp_logits_kernel(const float* __restrict__ T, const float* __restrict__ b1,
                                  const float* __restrict__ w2, const float* __restrict__ b2,
                                  float* __restrict__ logits, float* __restrict__ weights) {
    const float LOG_ADJ = 2.5494451709255714f;
    int s = blockIdx.x;
    int j = threadIdx.x;
    float v1 = 0.f, v2 = 0.f;
#pragma unroll
    for (int z = 0; z < 8; z++) {
        v1 += T[((size_t)z * SEQ + s) * 64 + j];
        v2 += T[((size_t)z * SEQ + s) * 64 + j + 32];
    }
    float v = tanhf(v1 + b1[j]) * w2[j] + tanhf(v2 + b1[j + 32]) * w2[j + 32];
#pragma unroll
    for (int o = 16; o > 0; o >>= 1) v += __shfl_xor_sync(0xffffffffu, v, o);
    if (j == 0) {
        float lg = v + b2[0] - LOG_ADJ;
        logits[s] = lg;
        weights[s] = 1.0f / (1.0f + expf(-lg));
    }
}

// ---------------- top-k via single-block bitonic sort ----------------
__global__ void topk_kernel(const float* __restrict__ logits,
                            int* __restrict__ topk_list, int* __restrict__ is_topk) {
    extern __shared__ unsigned long long skeys[];
    int tid = threadIdx.x;
    for (int i = tid; i < SEQ; i += 1024) {
        unsigned u = __float_as_uint(logits[i]);
        u = (u & 0x80000000u) ? ~u : (u | 0x80000000u);
        skeys[i] = ((unsigned long long)(~u) << 32) | (unsigned)i;
        is_topk[i] = 0;
    }
    __syncthreads();
    for (int k = 2; k <= SEQ; k <<= 1) {
        for (int j = k >> 1; j > 0; j >>= 1) {
            for (int i = tid; i < SEQ; i += 1024) {
                int ixj = i ^ j;
                if (ixj > i) {
                    bool up = ((i & k) == 0);
                    unsigned long long a = skeys[i], b = skeys[ixj];
                    if ((a > b) == up) { skeys[i] = b; skeys[ixj] = a; }
                }
            }
            __syncthreads();
        }
    }
    for (int i = tid; i < TK; i += 1024) {
        int pos = (int)(skeys[i] & 0xffffffffu);
        topk_list[i] = pos;
        is_topk[pos] = 1;
    }
}

// ---------------- sketch stage A (kbo-split x2, j-unrolled x8 for MLP) ----------------
__global__ void sketchA_kernel(const float* __restrict__ X, int hstride, int hbase,
                               const float* __restrict__ weights,
                               const int* __restrict__ is_topk, int rest,
                               const float* __restrict__ kb, float* __restrict__ P) {
    int h = blockIdx.x;
    int ib = blockIdx.y;
    int z = blockIdx.z;
    int d = threadIdx.x;
    __shared__ float kbs[16 * 256];
    for (int t = d; t < 16 * 256; t += 128) kbs[t] = kb[z * 16 * 256 + t];
    __shared__ float ws[256];
    for (int j = d; j < 256; j += 128) {
        int t = ib * 256 + j;
        float w = weights[t];
        if (rest && is_topk[t]) w = 0.0f;
        ws[j] = w;
    }
    __syncthreads();
    float acc[16] = {};
    const size_t rowstride = (size_t)hstride * DH;
    const float* Xb = X + ((size_t)(ib * 256) * hstride + hbase + h) * DH + d;
    for (int j = 0; j < 256; j += 8) {
        float x0 = Xb[(size_t)(j + 0) * rowstride];
        float x1 = Xb[(size_t)(j + 1) * rowstride];
        float x2 = Xb[(size_t)(j + 2) * rowstride];
        float x3 = Xb[(size_t)(j + 3) * rowstride];
        float x4 = Xb[(size_t)(j + 4) * rowstride];
        float x5 = Xb[(size_t)(j + 5) * rowstride];
        float x6 = Xb[(size_t)(j + 6) * rowstride];
        float x7 = Xb[(size_t)(j + 7) * rowstride];
        x0 *= ws[j + 0]; x1 *= ws[j + 1]; x2 *= ws[j + 2]; x3 *= ws[j + 3];
        x4 *= ws[j + 4]; x5 *= ws[j + 5]; x6 *= ws[j + 6]; x7 *= ws[j + 7];
#pragma unroll
        for (int kbo = 0; kbo < 16; kbo++) {
            float a = acc[kbo];
            a += x0 * kbs[kbo * 256 + j + 0];
            a += x1 * kbs[kbo * 256 + j + 1];
            a += x2 * kbs[kbo * 256 + j + 2];
            a += x3 * kbs[kbo * 256 + j + 3];
            a += x4 * kbs[kbo * 256 + j + 4];
            a += x5 * kbs[kbo * 256 + j + 5];
            a += x6 * kbs[kbo * 256 + j + 6];
            a += x7 * kbs[kbo * 256 + j + 7];
            acc[kbo] = a;
        }
    }
#pragma unroll
    for (int kbo = 0; kbo < 16; kbo++)
        P[(((size_t)h * 32 + z * 16 + kbo) * 32 + ib) * DH + d] = acc[kbo];
}

// ---------------- sketch stage B (kao-split x2); mode: 0=qfrag,1=kfrag,3=dense -----
__global__ void sketchB_kernel(const float* __restrict__ P, int heads,
                               const float* __restrict__ ka,
                               const float* __restrict__ scale_p,
                               float* __restrict__ dst, int mode) {
    int h = blockIdx.x;
    int kbo = blockIdx.y;
    int zk = blockIdx.z;
    int d = threadIdx.x;
    __shared__ float kas[10 * 32];
    for (int t = d; t < 10 * 32; t += 128)
        kas[t] = ka[(zk * 10 + t / 32) * DH + (t % 32)];
    __syncthreads();
    float p[32];
#pragma unroll
    for (int i = 0; i < 32; i++) p[i] = P[(((size_t)h * 32 + kbo) * 32 + i) * DH + d];
    float scale = scale_p[0];
    if (mode == 0) scale *= ATT_SCALE;
#pragma unroll
    for (int kao = 0; kao < 10; kao++) {
        float acc = 0.f;
#pragma unroll
        for (int i = 0; i < 32; i++) acc += p[i] * kas[kao * 32 + i];
        int s = TK + kbo * 20 + zk * 10 + kao;
        float val = acc * scale;
        if (mode == 0)      store_qfrag(dst, h, s, d, val);
        else if (mode == 1) store_kfrag(dst, h, s, d, val);
        else                dst[(size_t)(s - TK) * (heads * DH) + h * DH + d] = val;
    }
}

// ---------------- gather + RoPE (q and k only) ----------------
__global__ void gather_rope_kernel(const float* __restrict__ q, const float* __restrict__ k,
                                   const float* __restrict__ cosb, const float* __restrict__ sinb,
                                   const int* __restrict__ topk_list,
                                   float* __restrict__ Qfr, float* __restrict__ Kfr) {
    int j = blockIdx.x;
    int hy = blockIdx.y;
    int d = threadIdx.x;
    int pos = topk_list[j];
    float c = cosb[(size_t)pos * DH + d];
    float s = sinb[(size_t)pos * DH + d];
    if (hy < 16) {
        const float* src = q + ((size_t)pos * NH + hy) * DH;
        float x = src[d];
        float r = (d < 64) ? -src[d + 64] : src[d - 64];
        store_qfrag(Qfr, hy, j, d, (x * c + r * s) * ATT_SCALE);
    } else {
        int h = hy - 16;
        const float* src = k + (size_t)pos * 512 + h * DH;
        float x = src[d];
        float r = (d < 64) ? -src[d + 64] : src[d - 64];
        store_kfrag(Kfr, h, j, d, x * c + r * s);
    }
}

// --------- tensor-core flash attention: register-resident P, split-KV, cp.async ------
// 8 warps x 16 q-rows each; every warp computes all 64 keys; P stays in registers
// (QK C-fragments consumed as PV A-fragments via permuted V layout).
#define FA2_SMEM ((16384 + 2*8192 + 2*8192) * 4)
__global__ void __launch_bounds__(256, 1) fa_mma_kernel(
    const float* __restrict__ Qfr, const float* __restrict__ Kfr,
    const float* __restrict__ Vfr, float* __restrict__ Op,
    float* __restrict__ ML, int kt0)
{
    extern __shared__ float fsm[];
    float* Qsm = fsm;                       // 16384
    float* Ksm = fsm + 16384;               // 2 x 8192
    float* Vsm = fsm + 32768;               // 2 x 8192

    const int qt = blockIdx.x;
    const int h  = blockIdx.y;
    const int kvh = h >> 2;
    const int tid = threadIdx.x;
    const int lane = tid & 31, w = tid >> 5;   // warp owns q rows [w*16, w*16+16)
    const int gid = lane >> 2, tig = lane & 3;

    const uint32_t ksmU = (uint32_t)__cvta_generic_to_shared(Ksm) + tid * 16;
    const uint32_t vsmU = (uint32_t)__cvta_generic_to_shared(Vsm) + tid * 16;

    {
        const float4* Kg = reinterpret_cast<const float4*>(Kfr + (size_t)(kvh * NKT + kt0) * 8192);
        const float4* Vg = reinterpret_cast<const float4*>(Vfr + (size_t)(kvh * NKT + kt0) * 8192);
#pragma unroll
        for (int i = 0; i < 8; i++) {
            CP_ASYNC16(ksmU + i * 4096, Kg + tid + i * 256);
            CP_ASYNC16(vsmU + i * 4096, Vg + tid + i * 256);
        }
        CP_COMMIT();
    }

    {
        const float4* Qg = reinterpret_cast<const float4*>(Qfr + (size_t)(h * NQT + qt) * 16384);
        float4* Qs4w = reinterpret_cast<float4*>(Qsm);
#pragma unroll
        for (int i = 0; i < 16; i++) Qs4w[tid + i * 256] = Qg[tid + i * 256];
    }

    float m_old[2] = {-1e30f, -1e30f};
    float l_run[2] = {0.f, 0.f};
    float oacc[16][4] = {};

    const float4* Qs4 = reinterpret_cast<const float4*>(Qsm);

    for (int t = 0; t < KSPL; t++) {
        const int buf = t & 1;
        if (t + 1 < KSPL) {
            const float4* Kg = reinterpret_cast<const float4*>(Kfr + (size_t)(kvh * NKT + kt0 + t + 1) * 8192);
            const float4* Vg = reinterpret_cast<const float4*>(Vfr + (size_t)(kvh * NKT + kt0 + t + 1) * 8192);
            const uint32_t kd = ksmU + (1 - buf) * 32768;
            const uint32_t vd = vsmU + (1 - buf) * 32768;
#pragma unroll
            for (int i = 0; i < 8; i++) {
                CP_ASYNC16(kd + i * 4096, Kg + tid + i * 256);
                CP_ASYNC16(vd + i * 4096, Vg + tid + i * 256);
            }
            CP_COMMIT();
            asm volatile("cp.async.wait_group 1;");
        } else {
            asm volatile("cp.async.wait_group 0;");
        }
        __syncthreads();

        const float2* Ks2 = reinterpret_cast<const float2*>(Ksm + buf * 8192);
        const float2* Vs2 = reinterpret_cast<const float2*>(Vsm + buf * 8192);

        // S = Q K^T : warp tile 16 q-rows x 64 keys (all keys in registers)
        float sacc[8][4] = {};
#pragma unroll
        for (int k8 = 0; k8 < 16; k8++) {
            float4 af = Qs4[(k8 * 8 + w) * 32 + lane];
#pragma unroll
            for (int nf = 0; nf < 8; nf++) {
                float2 bf = Ks2[(k8 * 8 + nf) * 32 + lane];
                mma_tf32(sacc[nf],
                         reinterpret_cast<const uint32_t*>(&af),
                         reinterpret_cast<const uint32_t*>(&bf));
            }
        }

        // row max (rows w*16+gid and +8) — pure quad shuffles
        float m0 = fmaxf(sacc[0][0], sacc[0][1]);
        float m1 = fmaxf(sacc[0][2], sacc[0][3]);
#pragma unroll
        for (int nf = 1; nf < 8; nf++) {
            m0 = fmaxf(m0, fmaxf(sacc[nf][0], sacc[nf][1]));
            m1 = fmaxf(m1, fmaxf(sacc[nf][2], sacc[nf][3]));
        }
        m0 = fmaxf(m0, __shfl_xor_sync(0xffffffffu, m0, 1));
        m0 = fmaxf(m0, __shfl_xor_sync(0xffffffffu, m0, 2));
        m1 = fmaxf(m1, __shfl_xor_sync(0xffffffffu, m1, 1));
        m1 = fmaxf(m1, __shfl_xor_sync(0xffffffffu, m1, 2));

        float mn0 = fmaxf(m_old[0], m0);
        float mn1 = fmaxf(m_old[1], m1);
        float corr0 = __expf(m_old[0] - mn0);
        float corr1 = __expf(m_old[1] - mn1);
        m_old[0] = mn0; m_old[1] = mn1;

        // p = exp(s - m), row sums
        float s0 = 0.f, s1 = 0.f;
#pragma unroll
        for (int nf = 0; nf < 8; nf++) {
            sacc[nf][0] = __expf(sacc[nf][0] - mn0);
            sacc[nf][1] = __expf(sacc[nf][1] - mn0);
            sacc[nf][2] = __expf(sacc[nf][2] - mn1);
            sacc[nf][3] = __expf(sacc[nf][3] - mn1);
            s0 += sacc[nf][0] + sacc[nf][1];
            s1 += sacc[nf][2] + sacc[nf][3];
        }
        s0 += __shfl_xor_sync(0xffffffffu, s0, 1);
        s0 += __shfl_xor_sync(0xffffffffu, s0, 2);
        s1 += __shfl_xor_sync(0xffffffffu, s1, 1);
        s1 += __shfl_xor_sync(0xffffffffu, s1, 2);
        l_run[0] = l_run[0] * corr0 + s0;
        l_run[1] = l_run[1] * corr1 + s1;

        // rescale O
#pragma unroll
        for (int nf = 0; nf < 16; nf++) {
            oacc[nf][0] *= corr0; oacc[nf][1] *= corr0;
            oacc[nf][2] *= corr1; oacc[nf][3] *= corr1;
        }

        // O += P V : P consumed directly from sacc registers (V pre-permuted)
#pragma unroll
        for (int kk = 0; kk < 8; kk++) {
            uint32_t a[4];
            a[0] = __float_as_uint(tf32f(sacc[kk][0]));
            a[1] = __float_as_uint(tf32f(sacc[kk][2]));
            a[2] = __float_as_uint(tf32f(sacc[kk][1]));
            a[3] = __float_as_uint(tf32f(sacc[kk][3]));
#pragma unroll
            for (int nf = 0; nf < 16; nf++) {
                float2 bf = Vs2[(kk * 16 + nf) * 32 + lane];
                mma_tf32(oacc[nf], a, reinterpret_cast<const uint32_t*>(&bf));
            }
        }
        __syncthreads();   // all reads of buf done before next prefetch overwrites it
    }

    // epilogue: UNNORMALIZED O partial + per-row (m, l)
    {
        int r0 = qt * 128 + w * 16 + gid;
        if (tig == 0) {
            size_t row0i = (size_t)r0 * NH + h;
            size_t row1i = (size_t)(r0 + 8) * NH + h;
            ML[row0i * 2] = m_old[0]; ML[row0i * 2 + 1] = l_run[0];
            ML[row1i * 2] = m_old[1]; ML[row1i * 2 + 1] = l_run[1];
        }
#pragma unroll
        for (int nf = 0; nf < 16; nf++) {
            int col = nf * 8 + tig * 2;
            *reinterpret_cast<float2*>(&Op[((size_t)r0 * NH + h) * DH + col]) =
                make_float2(oacc[nf][0], oacc[nf][1]);
            *reinterpret_cast<float2*>(&Op[((size_t)(r0 + 8) * NH + h) * DH + col]) =
                make_float2(oacc[nf][2], oacc[nf][3]);
        }
    }
}

// ---------------- fa combine ----------------
__global__ void fa_combine_kernel(float* __restrict__ O0, const float* __restrict__ O1,
                                  const float* __restrict__ ML) {
    size_t row = (size_t)blockIdx.x * NH + blockIdx.y;
    int d = threadIdx.x;
    float m0 = ML[row * 2], l0 = ML[row * 2 + 1];
    float m1 = ML[(size_t)NQF * NH * 2 + row * 2], l1 = ML[(size_t)NQF * NH * 2 + row * 2 + 1];
    float m = fmaxf(m0, m1);
    float w0 = __expf(m0 - m), w1 = __expf(m1 - m);
    float inv = 1.0f / (w0 * l0 + w1 * l1);
    O0[row * DH + d] = (O0[row * DH + d] * w0 + O1[row * DH + d] * w1) * inv;
}

// ---------------- expand stage C ----------------
__global__ void expandC_kernel(const float* __restrict__ Z, const float* __restrict__ ka,
                               float* __restrict__ E1) {
    int i = blockIdx.y;
    int hd = blockIdx.x * 256 + threadIdx.x;
    __shared__ float kav[20];
    if (threadIdx.x < 20) kav[threadIdx.x] = ka[threadIdx.x * DH + i];
    __syncthreads();
    for (int kbo = 0; kbo < 32; kbo++) {
        float acc = 0.f;
#pragma unroll
        for (int kao = 0; kao < 20; kao++)
            acc += Z[((size_t)(kbo * 20 + kao)) * HID + hd] * kav[kao];
        E1[((size_t)i * 32 + kbo) * HID + hd] = acc;
    }
}

// ---------------- expand stage D ----------------
__global__ void expandD_kernel(const float* __restrict__ E1, const float* __restrict__ kb,
                               const int* __restrict__ is_topk, float* __restrict__ OUT) {
    int i = blockIdx.y;
    int hd = blockIdx.x * 128 + threadIdx.x;
    __shared__ float kbs[32 * 256];
    for (int t = threadIdx.x; t < 32 * 256; t += 128) kbs[t] = kb[t];
    float e[32];
#pragma unroll
    for (int kbo = 0; kbo < 32; kbo++) e[kbo] = E1[((size_t)i * 32 + kbo) * HID + hd];
    __syncthreads();
    for (int j = 0; j < 256; j++) {
        int row = i * 256 + j;
        if (is_topk[row]) continue;
        float acc = 0.f;
#pragma unroll
        for (int kbo = 0; kbo < 32; kbo++) acc += e[kbo] * kbs[kbo * 256 + j];
        OUT[(size_t)row * HID + hd] = acc;
    }
}

// ---------------- host launcher ----------------
extern "C" void kernel_launch(void* const* d_in, const int* in_sizes, int n_in,
                              void* d_out, int out_size) {
    const float* hs    = (const float*)d_in[0];
    const float* cosb  = (const float*)d_in[1];
    const float* sinb  = (const float*)d_in[2];
    const float* wq    = (const float*)d_in[3];
    const float* wk    = (const float*)d_in[4];
    const float* wv    = (const float*)d_in[5];
    const float* wo    = (const float*)d_in[6];
    const float* qnw   = (const float*)d_in[7];
    const float* knw   = (const float*)d_in[8];
    const float* w1    = (const float*)d_in[9];
    const float* b1    = (const float*)d_in[10];
    const float* w2    = (const float*)d_in[11];
    const float* b2    = (const float*)d_in[12];
    const float* ka    = (const float*)d_in[13];
    const float* kb    = (const float*)d_in[14];
    const float* sscale= (const float*)d_in[15];
    float* out = (float*)d_out;

    float *pT, *pLg, *pW, *pQ, *pK, *pPq, *pPk, *pPh, *pHSr, *pQfr, *pKfr, *pVfr,
          *pAO, *pAO2, *pML, *pE1, *pZ, *pAfr, *pAfr2, *pBfr;
    int *pTop, *pIs;
    cudaGetSymbolAddress((void**)&pT, g_T);
    cudaGetSymbolAddress((void**)&pLg, g_logits);
    cudaGetSymbolAddress((void**)&pW, g_weights);
    cudaGetSymbolAddress((void**)&pQ, g_q);
    cudaGetSymbolAddress((void**)&pK, g_k);
    cudaGetSymbolAddress((void**)&pPq, g_Pq);
    cudaGetSymbolAddress((void**)&pPk, g_Pk);
    cudaGetSymbolAddress((void**)&pPh, g_Ph);
    cudaGetSymbolAddress((void**)&pHSr, g_HSr);
    cudaGetSymbolAddress((void**)&pQfr, g_Qfr);
    cudaGetSymbolAddress((void**)&pKfr, g_Kfr);
    cudaGetSymbolAddress((void**)&pVfr, g_Vfr);
    cudaGetSymbolAddress((void**)&pAO, g_AO);
    cudaGetSymbolAddress((void**)&pAO2, g_AO2);
    cudaGetSymbolAddress((void**)&pML, g_ML);
    cudaGetSymbolAddress((void**)&pE1, g_E1);
    cudaGetSymbolAddress((void**)&pZ, g_Z);
    cudaGetSymbolAddress((void**)&pAfr, g_Afr);
    cudaGetSymbolAddress((void**)&pAfr2, g_Afr2);
    cudaGetSymbolAddress((void**)&pBfr, g_Bfr);
    cudaGetSymbolAddress((void**)&pTop, g_topk);
    cudaGetSymbolAddress((void**)&pIs, g_istop);

    float* pBwk = pBfr + (size_t)16 * 128 * 2048;
    float* pBwv = pBfr + (size_t)20 * 128 * 2048;
    float* pBwo = pBfr + (size_t)24 * 128 * 2048;
    float* pML2 = pML + (size_t)NQF * NH * 2;
    float* pAfr2b = pAfr2 + (size_t)16 * (HID / 16) * 2048;

    cudaFuncSetAttribute(topk_kernel, cudaFuncAttributeMaxDynamicSharedMemorySize, SEQ * 8);
    cudaFuncSetAttribute(fa_mma_kernel, cudaFuncAttributeMaxDynamicSharedMemorySize, FA2_SMEM);

    static cudaStream_t s1 = nullptr;
    static cudaEvent_t evFork = nullptr, evImp = nullptr, evAfr = nullptr,
                       evVf = nullptr, evK = nullptr, evKf = nullptr,
                       evQg = nullptr, evFA1 = nullptr, evAO = nullptr, evExp = nullptr;
    if (s1 == nullptr) {
        cudaStreamCreateWithFlags(&s1, cudaStreamNonBlocking);
        cudaEventCreateWithFlags(&evFork, cudaEventDisableTiming);
        cudaEventCreateWithFlags(&evImp, cudaEventDisableTiming);
        cudaEventCreateWithFlags(&evAfr, cudaEventDisableTiming);
        cudaEventCreateWithFlags(&evVf, cudaEventDisableTiming);
        cudaEventCreateWithFlags(&evK, cudaEventDisableTiming);
        cudaEventCreateWithFlags(&evKf, cudaEventDisableTiming);
        cudaEventCreateWithFlags(&evQg, cudaEventDisableTiming);
        cudaEventCreateWithFlags(&evFA1, cudaEventDisableTiming);
        cudaEventCreateWithFlags(&evAO, cudaEventDisableTiming);
        cudaEventCreateWithFlags(&evExp, cudaEventDisableTiming);
    }

    // ---- fork ----
    cudaEventRecord(evFork, 0);
    cudaStreamWaitEvent(s1, evFork, 0);

    // ---- s1: importance chain ----
    imp_gemm_kernel<<<dim3(1, SEQ / 64, 8), 256, 0, s1>>>(hs, w1, pT);
    imp_logits_kernel<<<SEQ, 32, 0, s1>>>(pT, b1, w2, b2, pLg, pW);
    topk_kernel<<<1, 1024, SEQ * 8, s1>>>(pLg, pTop, pIs);
    cudaEventRecord(evImp, s1);

    // ---- s1: V path ----
    sketchA_kernel<<<dim3(16, 32, 2), DH, 0, s1>>>(hs, 16, 0, pW, pIs, 1, kb, pPh);
    sketchB_kernel<<<dim3(16, 32, 2), DH, 0, s1>>>(pPh, 16, ka, sscale, pHSr, 3);
    convA_kernel<<<dim3(HID / 16, 16), 256, 0, s1>>>(hs, pTop, pAfr2, HID);
    convA_kernel<<<dim3(HID / 16, 5), 256, 0, s1>>>(pHSr, nullptr, pAfr2b, HID);
    convB_kernel<<<dim3(HID / 16, 512 / 128), 256, 0, s1>>>(wv, pBwv, HID, 512, 0);
    mma_gemm_kernel<<<dim3(512 / 128, NQF / 128), 128, 0, s1>>>(
        pAfr2, pBwv, pVfr, nullptr, nullptr, 0, pVfr, 512, HID);
    cudaEventRecord(evVf, s1);

    // ---- default: Q projection chain ----
    convA_kernel<<<dim3(HID / 16, SEQ / 128), 256>>>(hs, nullptr, pAfr, HID);
    cudaEventRecord(evAfr, 0);
    convB_kernel<<<dim3(HID / 16, HID / 128), 256>>>(wq, pBfr, HID, HID, 0);
    mma_gemm_kernel<<<dim3(HID / 128, SEQ / 128), 128>>>(pAfr, pBfr, pQ, nullptr, qnw, 16, nullptr, HID, HID);

    // ---- s1: K projection + k-sketch ----
    convB_kernel<<<dim3(HID / 16, 512 / 128), 256, 0, s1>>>(wk, pBwk, HID, 512, 0);
    cudaStreamWaitEvent(s1, evAfr, 0);
    mma_gemm_kernel<<<dim3(512 / 128, SEQ / 128), 128, 0, s1>>>(
        pAfr, pBwk, pK, nullptr, knw, 4, nullptr, 512, HID);
    cudaEventRecord(evK, s1);
    sketchA_kernel<<<dim3(NKV, 32, 2), DH, 0, s1>>>(pK, 4, 0, pW, pIs, 1, kb, pPk);
    sketchB_kernel<<<dim3(NKV, 32, 2), DH, 0, s1>>>(pPk, NKV, ka, sscale, pKfr, 1);
    cudaEventRecord(evKf, s1);
    convB_kernel<<<dim3(HID / 16, HID / 128), 256, 0, s1>>>(wo, pBwo, HID, HID, 0);

    // ---- default: q sketch + gather ----
    cudaStreamWaitEvent(0, evImp, 0);
    sketchA_kernel<<<dim3(NH, 32, 2), DH>>>(pQ, 16, 0, pW, pIs, 0, kb, pPq);
    sketchB_kernel<<<dim3(NH, 32, 2), DH>>>(pPq, NH, ka, sscale, pQfr, 0);
    cudaStreamWaitEvent(0, evK, 0);
    gather_rope_kernel<<<dim3(TK, 20), DH>>>(pQ, pK, cosb, sinb, pTop, pQfr, pKfr);
    cudaEventRecord(evQg, 0);

    // ---- attention: split-KV x2 + combine ----
    cudaStreamWaitEvent(0, evKf, 0);
    cudaStreamWaitEvent(0, evVf, 0);
    cudaStreamWaitEvent(s1, evQg, 0);
    fa_mma_kernel<<<dim3(NQT, NH), 256, FA2_SMEM>>>(pQfr, pKfr, pVfr, pAO, pML, 0);
    fa_mma_kernel<<<dim3(NQT, NH), 256, FA2_SMEM, s1>>>(pQfr, pKfr, pVfr, pAO2, pML2, KSPL);
    cudaEventRecord(evFA1, s1);
    cudaStreamWaitEvent(0, evFA1, 0);
    fa_combine_kernel<<<dim3(NQF, NH), DH>>>(pAO, pAO2, pML);

    // ---- epilogue ----
    convA_kernel<<<dim3(HID / 16, NQF / 128), 256>>>(pAO, nullptr, pAfr, HID);
    cudaEventRecord(evAO, 0);
    cudaStreamWaitEvent(s1, evAO, 0);
    mma_gemm_kernel<<<dim3(HID / 128, SK / 128), 128, 0, s1>>>(
        pAfr + (size_t)16 * (HID / 16) * 2048, pBwo, pZ, nullptr, nullptr, 0, nullptr, HID, HID);
    expandC_kernel<<<dim3(HID / 256, 32), 256, 0, s1>>>(pZ, ka, pE1);
    expandD_kernel<<<dim3(HID / 128, 32), DH, 0, s1>>>(pE1, kb, pIs, out);
    cudaEventRecord(evExp, s1);
    mma_gemm_kernel<<<dim3(HID / 128, TK / 128), 128>>>(pAfr, pBwo, out, pTop, nullptr, 0, nullptr, HID, HID);

    // ---- join ----
    cudaStreamWaitEvent(0, evExp, 0);
}